// round 8
// baseline (speedup 1.0000x reference)
#include <cuda_runtime.h>
#include <cuda_bf16.h>
#include <cstdint>

#define NN   50000
#define NP   50048     // 391*128 padded rows
#define DEG  16
#define DIM  128
#define EDIM 32
#define HDIM 256
#define NPB  8
#define GX   391

typedef unsigned long long u64;

// ---- scratch (device globals; no allocation allowed) ----
__device__ float g_P[(size_t)NN * 512];                 // fp32 projections (edge gathers)
__device__ __nv_bfloat16 g_NAh[(size_t)NP * 256];       // cols 0-127 node_inp, 128-255 AGG
__device__ __nv_bfloat16 g_NAl[(size_t)NP * 256];
__device__ __nv_bfloat16 g_Sh[(size_t)NP * 256];        // edge-sum S
__device__ __nv_bfloat16 g_Sl[(size_t)NP * 256];
__device__ __nv_bfloat16 g_Uh[(size_t)NP * 256];        // node-MLP hidden U
__device__ __nv_bfloat16 g_Ul[(size_t)NP * 256];
__device__ __nv_bfloat16 g_Wh[196608];                  // weights, [n][K] per region
__device__ __nv_bfloat16 g_Wl[196608];

__device__ __forceinline__ float swishf(float v) {
    return __fdividef(v, 1.0f + __expf(-v));
}
__device__ __forceinline__ uint32_t smem_u32(const void* p) {
    uint32_t a;
    asm("{ .reg .u64 t; cvta.to.shared.u64 t, %1; cvt.u32.u64 %0, t; }" : "=r"(a) : "l"(p));
    return a;
}
__device__ __forceinline__ void ldsm4(uint32_t& r0, uint32_t& r1, uint32_t& r2,
                                      uint32_t& r3, uint32_t addr) {
    asm volatile("ldmatrix.sync.aligned.m8n8.x4.shared.b16 {%0,%1,%2,%3}, [%4];"
                 : "=r"(r0), "=r"(r1), "=r"(r2), "=r"(r3) : "r"(addr));
}
__device__ __forceinline__ void mma16816(float* c, const uint32_t* a, const uint32_t* b) {
    asm volatile("mma.sync.aligned.m16n8k16.row.col.f32.bf16.bf16.f32 "
                 "{%0,%1,%2,%3}, {%4,%5,%6,%7}, {%8,%9}, {%0,%1,%2,%3};"
                 : "+f"(c[0]), "+f"(c[1]), "+f"(c[2]), "+f"(c[3])
                 : "r"(a[0]), "r"(a[1]), "r"(a[2]), "r"(a[3]), "r"(b[0]), "r"(b[1]));
}
__device__ __forceinline__ void split_store(__nv_bfloat16* dh, __nv_bfloat16* dl,
                                            size_t pos, float v0, float v1) {
    __nv_bfloat16 h0 = __float2bfloat16(v0), h1 = __float2bfloat16(v1);
    __nv_bfloat162 hp; hp.x = h0; hp.y = h1;
    *reinterpret_cast<__nv_bfloat162*>(&dh[pos]) = hp;
    __nv_bfloat162 lp;
    lp.x = __float2bfloat16(v0 - __bfloat162float(h0));
    lp.y = __float2bfloat16(v1 - __bfloat162float(h1));
    *reinterpret_cast<__nv_bfloat162*>(&dl[pos]) = lp;
}

// ============================================================================
// prep kernels
// ============================================================================
__global__ void conv_node(const float* __restrict__ x) {
    int row = blockIdx.x, t = threadIdx.x;
    float2 v = *reinterpret_cast<const float2*>(&x[(size_t)row * 128 + 2 * t]);
    split_store(g_NAh, g_NAl, (size_t)row * 256 + 2 * t, v.x, v.y);
}
__global__ void wprep(const float* __restrict__ src, int ld, int rowOff, int K,
                      __nv_bfloat16* __restrict__ dh, __nv_bfloat16* __restrict__ dl,
                      int total) {
    int idx = blockIdx.x * 256 + threadIdx.x;
    if (idx >= total) return;
    int n = idx / K, k = idx % K;
    float v = src[(size_t)(rowOff + k) * ld + n];
    __nv_bfloat16 h = __float2bfloat16(v);
    dh[idx] = h;
    dl[idx] = __float2bfloat16(v - __bfloat162float(h));
}

// ============================================================================
// Split-bf16 HMMA GEMM (unchanged from round 6 — proven at 870.7us)
// ============================================================================
template<int K, int MODE>
__global__ void __launch_bounds__(256, 2) mma_gemm(
    const __nv_bfloat16* __restrict__ Ah, const __nv_bfloat16* __restrict__ Al,
    const __nv_bfloat16* __restrict__ Bh, const __nv_bfloat16* __restrict__ Bl,
    const float* __restrict__ bias, float scale,
    const float* __restrict__ gamma, const float* __restrict__ beta,
    const float* __restrict__ mask, const float* __restrict__ resid,
    float* __restrict__ outF, int ldOut,
    __nv_bfloat16* __restrict__ oBh, __nv_bfloat16* __restrict__ oBl, int oCol)
{
    extern __shared__ __align__(16) char smem[];
    __nv_bfloat16* sAh = reinterpret_cast<__nv_bfloat16*>(smem);           // [128][40]
    __nv_bfloat16* sAl = sAh + 5120;
    __nv_bfloat16* sBh = sAh + 10240;                                      // [128n][40k]
    __nv_bfloat16* sBl = sAh + 15360;
    float* Csm = reinterpret_cast<float*>(smem);                           // [128][132]

    const uint32_t sb = smem_u32(smem);
    const int t = threadIdx.x, lane = t & 31, warp = t >> 5;
    const int wm = warp & 3, wn = warp >> 2;
    const int n0 = blockIdx.x * 128, by = blockIdx.y;

    float acc[2][8][4];
    #pragma unroll
    for (int mt = 0; mt < 2; mt++)
        #pragma unroll
        for (int nt = 0; nt < 8; nt++)
            #pragma unroll
            for (int q = 0; q < 4; q++) acc[mt][nt][q] = 0.f;

    for (int kb = 0; kb < K; kb += 32) {
        #pragma unroll
        for (int s = 0; s < 2; s++) {
            int idx = t + s * 256;
            int row = idx >> 2, g = idx & 3;
            int grow = n0 + row;
            uint4 zh = make_uint4(0u, 0u, 0u, 0u), zl = zh;
            if (grow < NN) {
                size_t ap = (size_t)grow * 256 + kb + g * 8;
                zh = *reinterpret_cast<const uint4*>(&Ah[ap]);
                zl = *reinterpret_cast<const uint4*>(&Al[ap]);
            }
            int so = row * 40 + g * 8;
            *reinterpret_cast<uint4*>(&sAh[so]) = zh;
            *reinterpret_cast<uint4*>(&sAl[so]) = zl;
            size_t bp = (size_t)(by * 128 + row) * K + kb + g * 8;
            *reinterpret_cast<uint4*>(&sBh[so]) = *reinterpret_cast<const uint4*>(&Bh[bp]);
            *reinterpret_cast<uint4*>(&sBl[so]) = *reinterpret_cast<const uint4*>(&Bl[bp]);
        }
        __syncthreads();

        #pragma unroll
        for (int kt = 0; kt < 32; kt += 16) {
            uint32_t ah[2][4], al[2][4];
            {
                int ar = lane & 15, as_ = (lane >> 4) * 8;
                #pragma unroll
                for (int mt = 0; mt < 2; mt++) {
                    uint32_t off = (uint32_t)((wm * 32 + mt * 16 + ar) * 40 + kt + as_) * 2;
                    ldsm4(ah[mt][0], ah[mt][1], ah[mt][2], ah[mt][3], sb + off);
                    ldsm4(al[mt][0], al[mt][1], al[mt][2], al[mt][3], sb + 10240 + off);
                }
            }
            #pragma unroll
            for (int p = 0; p < 4; p++) {
                int sel = lane >> 3, i = lane & 7;
                uint32_t boff = (uint32_t)((wn * 64 + p * 16 + ((sel >> 1) << 3) + i) * 40
                                           + kt + ((sel & 1) << 3)) * 2;
                uint32_t bh[4], bl[4];
                ldsm4(bh[0], bh[1], bh[2], bh[3], sb + 20480 + boff);
                ldsm4(bl[0], bl[1], bl[2], bl[3], sb + 30720 + boff);
                #pragma unroll
                for (int mt = 0; mt < 2; mt++)
                    #pragma unroll
                    for (int q = 0; q < 2; q++) {
                        float* c = acc[mt][2 * p + q];
                        mma16816(c, ah[mt], &bh[2 * q]);
                        mma16816(c, ah[mt], &bl[2 * q]);
                        mma16816(c, al[mt], &bh[2 * q]);
                    }
            }
        }
        __syncthreads();
    }

    {
        int g = lane >> 2, cc = (lane & 3) * 2;
        #pragma unroll
        for (int mt = 0; mt < 2; mt++)
            #pragma unroll
            for (int nt = 0; nt < 8; nt++) {
                int r0 = wm * 32 + mt * 16 + g;
                int col = wn * 64 + nt * 8 + cc;
                *reinterpret_cast<float2*>(&Csm[r0 * 132 + col]) =
                    make_float2(acc[mt][nt][0], acc[mt][nt][1]);
                *reinterpret_cast<float2*>(&Csm[(r0 + 8) * 132 + col]) =
                    make_float2(acc[mt][nt][2], acc[mt][nt][3]);
            }
    }
    __syncthreads();

    const int r = t >> 1, hh = t & 1, ch0 = hh * 64;
    const int row = n0 + r;
    const float* crow = &Csm[r * 132 + ch0];

    if (MODE == 0) {
        if (row < NN) {
            float* o = &outF[(size_t)row * ldOut + by * 128 + ch0];
            #pragma unroll
            for (int j = 0; j < 64; j += 4)
                *reinterpret_cast<float4*>(&o[j]) = *reinterpret_cast<const float4*>(&crow[j]);
        }
        return;
    }
    if (MODE == 2) {
        if (row < NN) {
            #pragma unroll
            for (int j = 0; j < 64; j += 2) {
                int c = by * 128 + ch0 + j;
                float v0 = swishf(crow[j]     + bias[c]);
                float v1 = swishf(crow[j + 1] + bias[c + 1]);
                split_store(oBh, oBl, (size_t)row * 256 + c, v0, v1);
            }
        }
        return;
    }
    {
        float s = 0.f, s2 = 0.f;
        #pragma unroll
        for (int j = 0; j < 64; j += 4) {
            float4 c4 = *reinterpret_cast<const float4*>(&crow[j]);
            float v0 = c4.x * scale + bias[ch0 + j];
            float v1 = c4.y * scale + bias[ch0 + j + 1];
            float v2 = c4.z * scale + bias[ch0 + j + 2];
            float v3 = c4.w * scale + bias[ch0 + j + 3];
            if (MODE == 3 && row < NN) {
                float4 r4 = *reinterpret_cast<const float4*>(&resid[(size_t)row * 128 + ch0 + j]);
                v0 += r4.x; v1 += r4.y; v2 += r4.z; v3 += r4.w;
            }
            s += v0 + v1 + v2 + v3;
            s2 += v0 * v0 + v1 * v1 + v2 * v2 + v3 * v3;
        }
        s  += __shfl_xor_sync(0xffffffffu, s, 1);
        s2 += __shfl_xor_sync(0xffffffffu, s2, 1);
        float m    = s * (1.0f / 128.0f);
        float var  = s2 * (1.0f / 128.0f) - m * m;
        float rstd = rsqrtf(var + 1e-5f);
        if (row < NN) {
            float mk = mask[row];
            #pragma unroll
            for (int j = 0; j < 64; j += 2) {
                int c = ch0 + j;
                float v0 = crow[j]     * scale + bias[c];
                float v1 = crow[j + 1] * scale + bias[c + 1];
                if (MODE == 3) {
                    float2 r2 = *reinterpret_cast<const float2*>(&resid[(size_t)row * 128 + c]);
                    v0 += r2.x; v1 += r2.y;
                }
                float w0 = ((v0 - m) * rstd * gamma[c]     + beta[c])     * mk;
                float w1 = ((v1 - m) * rstd * gamma[c + 1] + beta[c + 1]) * mk;
                if (MODE == 3) {
                    *reinterpret_cast<float2*>(&outF[(size_t)row * 128 + c]) = make_float2(w0, w1);
                } else {
                    split_store(oBh, oBl, (size_t)row * 256 + oCol + c, w0, w1);
                }
            }
        }
    }
}

// ============================================================================
// Edge kernel v2: HMMA edge-feature projection + scalar swish/reduce.
//   Per block: 8 nodes = 128 edges (m-tile 16 == one node's edges).
//   B (We1 edge rows, [256 ch][32 k] n-major split bf16) -> register fragments,
//   loaded ONCE per block via the proven ldmatrix scheme.
//   A (ef [128][32]) staged split-bf16 in smem (40-elem padded rows).
//   3-term split MMA -> EFproj fragments; scalar tail adds gathered P_s (float2),
//   P_r + be1, swish, then shfl-reduces the node's 16 rows. Lanes g==0 store S.
// ============================================================================
__global__ void __launch_bounds__(256, 2) edge_kernel(
    const float* __restrict__ edge_feat, const int* __restrict__ senders,
    const float* __restrict__ We1, const float* __restrict__ be1)
{
    __shared__ __align__(16) __nv_bfloat16 sW[256 * 40];    // 20480 B (staged h then l)
    __shared__ __align__(16) __nv_bfloat16 sEh[128 * 40];   // 10240 B
    __shared__ __align__(16) __nv_bfloat16 sEl[128 * 40];   // 10240 B
    __shared__ int snd[128];

    const int t = threadIdx.x, lane = t & 31, warp = t >> 5;
    const int n0 = blockIdx.x * NPB;
    const int e0 = n0 * DEG;
    const uint32_t sWa = smem_u32(sW), sEha = smem_u32(sEh), sEla = smem_u32(sEl);

    // ---- stage Wh ([n][k], n-major, pad 40) and load fragments ----
    for (int i = t; i < 8192; i += 256) {
        int n = i >> 5, k = i & 31;
        sW[n * 40 + k] = __float2bfloat16(We1[(size_t)(HDIM + k) * HDIM + n]);
    }
    __syncthreads();
    uint32_t bwh[2][2][4], bwl[2][2][4];   // [p][kt][frag]
    {
        int sel = lane >> 3, i = lane & 7;
        #pragma unroll
        for (int p = 0; p < 2; p++)
            #pragma unroll
            for (int kt = 0; kt < 2; kt++) {
                uint32_t off = (uint32_t)((warp * 32 + p * 16 + ((sel >> 1) << 3) + i) * 40
                                          + kt * 16 + ((sel & 1) << 3)) * 2;
                ldsm4(bwh[p][kt][0], bwh[p][kt][1], bwh[p][kt][2], bwh[p][kt][3], sWa + off);
            }
    }
    __syncthreads();
    // ---- stage Wl and load fragments ----
    for (int i = t; i < 8192; i += 256) {
        int n = i >> 5, k = i & 31;
        float v = We1[(size_t)(HDIM + k) * HDIM + n];
        __nv_bfloat16 h = __float2bfloat16(v);
        sW[n * 40 + k] = __float2bfloat16(v - __bfloat162float(h));
    }
    __syncthreads();
    {
        int sel = lane >> 3, i = lane & 7;
        #pragma unroll
        for (int p = 0; p < 2; p++)
            #pragma unroll
            for (int kt = 0; kt < 2; kt++) {
                uint32_t off = (uint32_t)((warp * 32 + p * 16 + ((sel >> 1) << 3) + i) * 40
                                          + kt * 16 + ((sel & 1) << 3)) * 2;
                ldsm4(bwl[p][kt][0], bwl[p][kt][1], bwl[p][kt][2], bwl[p][kt][3], sWa + off);
            }
    }

    // be1 pairs per (p, q) for this lane's channel pair
    float2 beq[2][2];
    #pragma unroll
    for (int p = 0; p < 2; p++)
        #pragma unroll
        for (int q = 0; q < 2; q++) {
            int ch = warp * 32 + p * 16 + q * 8 + (lane & 3) * 2;
            beq[p][q] = *reinterpret_cast<const float2*>(&be1[ch]);
        }

    // ---- stage ef tile (128 edges x 32), split bf16 ----
    #pragma unroll
    for (int s = 0; s < 4; s++) {
        int j4 = t + s * 256;                 // float4 index within 1024
        int row = j4 >> 3, k4 = (j4 & 7) * 4;
        float4 v = *reinterpret_cast<const float4*>(&edge_feat[(size_t)e0 * EDIM + j4 * 4]);
        float vv[4] = {v.x, v.y, v.z, v.w};
        #pragma unroll
        for (int c = 0; c < 4; c++) {
            __nv_bfloat16 h = __float2bfloat16(vv[c]);
            sEh[row * 40 + k4 + c] = h;
            sEl[row * 40 + k4 + c] = __float2bfloat16(vv[c] - __bfloat162float(h));
        }
    }
    if (t < 128) snd[t] = senders[e0 + t];
    __syncthreads();

    // ---- per-node: MMA projection + scalar swish/reduce ----
    const int g = lane >> 2;
    for (int ni = 0; ni < NPB; ni++) {
        const int n = n0 + ni;

        uint32_t ah[2][4], al[2][4];          // [kt][frag]
        {
            int ar = lane & 15, as_ = (lane >> 4) * 8;
            #pragma unroll
            for (int kt = 0; kt < 2; kt++) {
                uint32_t off = (uint32_t)((ni * 16 + ar) * 40 + kt * 16 + as_) * 2;
                ldsm4(ah[kt][0], ah[kt][1], ah[kt][2], ah[kt][3], sEha + off);
                ldsm4(al[kt][0], al[kt][1], al[kt][2], al[kt][3], sEla + off);
            }
        }
        float acc[2][2][4];
        #pragma unroll
        for (int p = 0; p < 2; p++)
            #pragma unroll
            for (int q = 0; q < 2; q++)
                #pragma unroll
                for (int x = 0; x < 4; x++) acc[p][q][x] = 0.f;

        #pragma unroll
        for (int p = 0; p < 2; p++)
            #pragma unroll
            for (int kt = 0; kt < 2; kt++)
                #pragma unroll
                for (int q = 0; q < 2; q++) {
                    float* c = acc[p][q];
                    mma16816(c, ah[kt], &bwh[p][kt][2 * q]);
                    mma16816(c, ah[kt], &bwl[p][kt][2 * q]);
                    mma16816(c, al[kt], &bwh[p][kt][2 * q]);
                }

        const int s0 = snd[ni * 16 + g], s1 = snd[ni * 16 + 8 + g];
        #pragma unroll
        for (int p = 0; p < 2; p++)
            #pragma unroll
            for (int q = 0; q < 2; q++) {
                int ch = warp * 32 + p * 16 + q * 8 + (lane & 3) * 2;
                float2 ps0 = *reinterpret_cast<const float2*>(&g_P[(size_t)s0 * 512 + ch]);
                float2 ps1 = *reinterpret_cast<const float2*>(&g_P[(size_t)s1 * 512 + ch]);
                float2 pr  = *reinterpret_cast<const float2*>(&g_P[(size_t)n * 512 + 256 + ch]);
                float b0 = pr.x + beq[p][q].x, b1 = pr.y + beq[p][q].y;
                float r0 = swishf(acc[p][q][0] + ps0.x + b0)
                         + swishf(acc[p][q][2] + ps1.x + b0);
                float r1 = swishf(acc[p][q][1] + ps0.y + b1)
                         + swishf(acc[p][q][3] + ps1.y + b1);
                r0 += __shfl_xor_sync(0xffffffffu, r0, 4);
                r1 += __shfl_xor_sync(0xffffffffu, r1, 4);
                r0 += __shfl_xor_sync(0xffffffffu, r0, 8);
                r1 += __shfl_xor_sync(0xffffffffu, r1, 8);
                r0 += __shfl_xor_sync(0xffffffffu, r0, 16);
                r1 += __shfl_xor_sync(0xffffffffu, r1, 16);
                if (g == 0)
                    split_store(g_Sh, g_Sl, (size_t)n * 256 + ch, r0, r1);
            }
    }
}

// ============================================================================
extern "C" void kernel_launch(void* const* d_in, const int* in_sizes, int n_in,
                              void* d_out, int out_size)
{
    const float* node_inp  = (const float*)d_in[0];
    const float* edge_feat = (const float*)d_in[1];
    const float* node_mask = (const float*)d_in[2];
    const float* We1       = (const float*)d_in[3];
    const float* be1       = (const float*)d_in[4];
    const float* We2       = (const float*)d_in[5];
    const float* be2       = (const float*)d_in[6];
    const float* g_msg     = (const float*)d_in[7];
    const float* b_msg     = (const float*)d_in[8];
    const float* Wn1       = (const float*)d_in[9];
    const float* bn1       = (const float*)d_in[10];
    const float* Wn2       = (const float*)d_in[11];
    const float* bn2       = (const float*)d_in[12];
    const float* g_node    = (const float*)d_in[13];
    const float* b_node    = (const float*)d_in[14];
    const int*   senders   = (const int*)d_in[15];
    float* out = (float*)d_out;

    float* Pp;
    __nv_bfloat16 *NAh, *NAl, *Sh, *Sl, *Uh, *Ul, *Wh, *Wl;
    cudaGetSymbolAddress((void**)&Pp,  g_P);
    cudaGetSymbolAddress((void**)&NAh, g_NAh);
    cudaGetSymbolAddress((void**)&NAl, g_NAl);
    cudaGetSymbolAddress((void**)&Sh,  g_Sh);
    cudaGetSymbolAddress((void**)&Sl,  g_Sl);
    cudaGetSymbolAddress((void**)&Uh,  g_Uh);
    cudaGetSymbolAddress((void**)&Ul,  g_Ul);
    cudaGetSymbolAddress((void**)&Wh,  g_Wh);
    cudaGetSymbolAddress((void**)&Wl,  g_Wl);

    const int SMEMT = 67584;
    cudaFuncSetAttribute(mma_gemm<128,0>, cudaFuncAttributeMaxDynamicSharedMemorySize, SMEMT);
    cudaFuncSetAttribute(mma_gemm<256,1>, cudaFuncAttributeMaxDynamicSharedMemorySize, SMEMT);
    cudaFuncSetAttribute(mma_gemm<256,2>, cudaFuncAttributeMaxDynamicSharedMemorySize, SMEMT);
    cudaFuncSetAttribute(mma_gemm<256,3>, cudaFuncAttributeMaxDynamicSharedMemorySize, SMEMT);

    // ---- weight prep: regions [NCtot][K] ----
    wprep<<<128, 256>>>(We1, 256,   0, 128, Wh,          Wl,          32768);
    wprep<<<128, 256>>>(We1, 256, 128, 128, Wh + 32768,  Wl + 32768,  32768);
    wprep<<<128, 256>>>(We2, 128,   0, 256, Wh + 65536,  Wl + 65536,  32768);
    wprep<<<256, 256>>>(Wn1, 256,   0, 256, Wh + 98304,  Wl + 98304,  65536);
    wprep<<<128, 256>>>(Wn2, 128,   0, 256, Wh + 163840, Wl + 163840, 32768);

    conv_node<<<NN, 64>>>(node_inp);

    // 1) P = node_inp @ [We1_s | We1_r] -> g_P fp32 [N,512]
    mma_gemm<128,0><<<dim3(GX, 4), 256, SMEMT>>>(
        NAh, NAl, Wh, Wl,
        nullptr, 1.0f, nullptr, nullptr, nullptr, nullptr, Pp, 512, nullptr, nullptr, 0);

    // 2) per-edge HMMA projection + swish + segment sum -> S (split bf16)
    edge_kernel<<<NN / NPB, 256>>>(edge_feat, senders, We1, be1);

    // 3) agg = LN(S @ We2 /16 + be2; g_msg,b_msg)*mask -> g_NA cols 128..255
    mma_gemm<256,1><<<dim3(GX, 1), 256, SMEMT>>>(
        Sh, Sl, Wh + 65536, Wl + 65536,
        be2, 1.0f / 16.0f, g_msg, b_msg, node_mask, nullptr, nullptr, 0, NAh, NAl, 128);

    // 4) U = swish(NA @ Wn1 + bn1) -> g_U (split bf16)
    mma_gemm<256,2><<<dim3(GX, 2), 256, SMEMT>>>(
        NAh, NAl, Wh + 98304, Wl + 98304,
        bn1, 1.0f, nullptr, nullptr, nullptr, nullptr, nullptr, 0, Uh, Ul, 0);

    // 5) out = LN(node_inp + U @ Wn2 + bn2; g_node,b_node)*mask -> fp32 out
    mma_gemm<256,3><<<dim3(GX, 1), 256, SMEMT>>>(
        Uh, Ul, Wh + 163840, Wl + 163840,
        bn2, 1.0f, g_node, b_node, node_mask, node_inp, out, 128, nullptr, nullptr, 0);
}

// round 9
// speedup vs baseline: 1.1906x; 1.1906x over previous
#include <cuda_runtime.h>
#include <cuda_bf16.h>
#include <cstdint>

#define NN   50000
#define NP   50048     // 391*128 padded rows
#define DEG  16
#define DIM  128
#define EDIM 32
#define HDIM 256
#define NPB  8
#define GX   391

typedef unsigned long long u64;

// ---- scratch (device globals; no allocation allowed) ----
// g_P: [0 .. NN*256)       = Ps (sender projections, gathered; L2-friendly dense)
//      [NN*256 .. NN*512)  = Pr (receiver projections, sequential reads)
__device__ float g_P[(size_t)NN * 512];
__device__ __nv_bfloat16 g_NAh[(size_t)NP * 256];       // cols 0-127 node_inp, 128-255 AGG
__device__ __nv_bfloat16 g_NAl[(size_t)NP * 256];
__device__ __nv_bfloat16 g_Sh[(size_t)NP * 256];        // edge-sum S
__device__ __nv_bfloat16 g_Sl[(size_t)NP * 256];
__device__ __nv_bfloat16 g_Uh[(size_t)NP * 256];        // node-MLP hidden U
__device__ __nv_bfloat16 g_Ul[(size_t)NP * 256];
__device__ __nv_bfloat16 g_Wh[196608];                  // weights, [n][K] per region
__device__ __nv_bfloat16 g_Wl[196608];

// single-MUFU swish: v * sigmoid(v) = 0.5*v*(1 + tanh(0.5*v))
__device__ __forceinline__ float swishf(float v) {
    float th;
    asm("tanh.approx.f32 %0, %1;" : "=f"(th) : "f"(0.5f * v));
    return 0.5f * v * (1.0f + th);
}
__device__ __forceinline__ uint32_t smem_u32(const void* p) {
    uint32_t a;
    asm("{ .reg .u64 t; cvta.to.shared.u64 t, %1; cvt.u32.u64 %0, t; }" : "=r"(a) : "l"(p));
    return a;
}
__device__ __forceinline__ void ldsm4(uint32_t& r0, uint32_t& r1, uint32_t& r2,
                                      uint32_t& r3, uint32_t addr) {
    asm volatile("ldmatrix.sync.aligned.m8n8.x4.shared.b16 {%0,%1,%2,%3}, [%4];"
                 : "=r"(r0), "=r"(r1), "=r"(r2), "=r"(r3) : "r"(addr));
}
__device__ __forceinline__ void mma16816(float* c, const uint32_t* a, const uint32_t* b) {
    asm volatile("mma.sync.aligned.m16n8k16.row.col.f32.bf16.bf16.f32 "
                 "{%0,%1,%2,%3}, {%4,%5,%6,%7}, {%8,%9}, {%0,%1,%2,%3};"
                 : "+f"(c[0]), "+f"(c[1]), "+f"(c[2]), "+f"(c[3])
                 : "r"(a[0]), "r"(a[1]), "r"(a[2]), "r"(a[3]), "r"(b[0]), "r"(b[1]));
}
__device__ __forceinline__ void split_store(__nv_bfloat16* dh, __nv_bfloat16* dl,
                                            size_t pos, float v0, float v1) {
    __nv_bfloat16 h0 = __float2bfloat16(v0), h1 = __float2bfloat16(v1);
    __nv_bfloat162 hp; hp.x = h0; hp.y = h1;
    *reinterpret_cast<__nv_bfloat162*>(&dh[pos]) = hp;
    __nv_bfloat162 lp;
    lp.x = __float2bfloat16(v0 - __bfloat162float(h0));
    lp.y = __float2bfloat16(v1 - __bfloat162float(h1));
    *reinterpret_cast<__nv_bfloat162*>(&dl[pos]) = lp;
}

typedef unsigned long long ull;
__device__ __forceinline__ void ffma2(u64& d, u64 a, u64 b) {
    asm("fma.rn.f32x2 %0, %1, %2, %3;" : "=l"(d) : "l"(a), "l"(b), "l"(d));
}
__device__ __forceinline__ u64 packf2(float lo, float hi) {
    u64 r; asm("mov.b64 %0, {%1, %2};" : "=l"(r) : "f"(lo), "f"(hi)); return r;
}
__device__ __forceinline__ u64 dupf2(float v) {
    u64 r; asm("mov.b64 %0, {%1, %1};" : "=l"(r) : "f"(v)); return r;
}
__device__ __forceinline__ float2 unpackf2(u64 v) {
    float2 r; asm("mov.b64 {%0, %1}, %2;" : "=f"(r.x), "=f"(r.y) : "l"(v)); return r;
}
__device__ __forceinline__ u64 addf2(u64 a, u64 b) {
    u64 r; asm("add.rn.f32x2 %0, %1, %2;" : "=l"(r) : "l"(a), "l"(b)); return r;
}

// ============================================================================
// prep kernels
// ============================================================================
// node_inp -> g_NA cols 0-127 (split bf16). grid=NN/4, block=256 (4 rows/block).
__global__ void conv_node(const float* __restrict__ x) {
    int t = threadIdx.x;
    int row = blockIdx.x * 4 + (t >> 6);
    int c = (t & 63) * 2;
    float2 v = *reinterpret_cast<const float2*>(&x[(size_t)row * 128 + c]);
    split_store(g_NAh, g_NAl, (size_t)row * 256 + c, v.x, v.y);
}
__global__ void wprep(const float* __restrict__ src, int ld, int rowOff, int K,
                      __nv_bfloat16* __restrict__ dh, __nv_bfloat16* __restrict__ dl,
                      int total) {
    int idx = blockIdx.x * 256 + threadIdx.x;
    if (idx >= total) return;
    int n = idx / K, k = idx % K;
    float v = src[(size_t)(rowOff + k) * ld + n];
    __nv_bfloat16 h = __float2bfloat16(v);
    dh[idx] = h;
    dl[idx] = __float2bfloat16(v - __bfloat162float(h));
}

// ============================================================================
// Split-bf16 HMMA GEMM (round-6 proven structure).
//   MODE 0: P store -> split Ps/Pr layout (by 0,1 -> Ps; by 2,3 -> Pr)
//   MODE 1: v=acc*scale+bias; LN*mask -> split bf16 g_NA cols 128..255
//   MODE 2: v=swish(acc+bias)        -> split bf16 oB cols by*128..
//   MODE 3: v=acc+bias+resid; LN*mask -> fp32 out
// ============================================================================
template<int K, int MODE>
__global__ void __launch_bounds__(256, 2) mma_gemm(
    const __nv_bfloat16* __restrict__ Ah, const __nv_bfloat16* __restrict__ Al,
    const __nv_bfloat16* __restrict__ Bh, const __nv_bfloat16* __restrict__ Bl,
    const float* __restrict__ bias, float scale,
    const float* __restrict__ gamma, const float* __restrict__ beta,
    const float* __restrict__ mask, const float* __restrict__ resid,
    float* __restrict__ outF, int ldOut,
    __nv_bfloat16* __restrict__ oBh, __nv_bfloat16* __restrict__ oBl, int oCol)
{
    extern __shared__ __align__(16) char smem[];
    __nv_bfloat16* sAh = reinterpret_cast<__nv_bfloat16*>(smem);           // [128][40]
    __nv_bfloat16* sAl = sAh + 5120;
    __nv_bfloat16* sBh = sAh + 10240;                                      // [128n][40k]
    __nv_bfloat16* sBl = sAh + 15360;
    float* Csm = reinterpret_cast<float*>(smem);                           // [128][132]

    const uint32_t sb = smem_u32(smem);
    const int t = threadIdx.x, lane = t & 31, warp = t >> 5;
    const int wm = warp & 3, wn = warp >> 2;
    const int n0 = blockIdx.x * 128, by = blockIdx.y;

    float acc[2][8][4];
    #pragma unroll
    for (int mt = 0; mt < 2; mt++)
        #pragma unroll
        for (int nt = 0; nt < 8; nt++)
            #pragma unroll
            for (int q = 0; q < 4; q++) acc[mt][nt][q] = 0.f;

    for (int kb = 0; kb < K; kb += 32) {
        #pragma unroll
        for (int s = 0; s < 2; s++) {
            int idx = t + s * 256;
            int row = idx >> 2, g = idx & 3;
            int grow = n0 + row;
            uint4 zh = make_uint4(0u, 0u, 0u, 0u), zl = zh;
            if (grow < NN) {
                size_t ap = (size_t)grow * 256 + kb + g * 8;
                zh = *reinterpret_cast<const uint4*>(&Ah[ap]);
                zl = *reinterpret_cast<const uint4*>(&Al[ap]);
            }
            int so = row * 40 + g * 8;
            *reinterpret_cast<uint4*>(&sAh[so]) = zh;
            *reinterpret_cast<uint4*>(&sAl[so]) = zl;
            size_t bp = (size_t)(by * 128 + row) * K + kb + g * 8;
            *reinterpret_cast<uint4*>(&sBh[so]) = *reinterpret_cast<const uint4*>(&Bh[bp]);
            *reinterpret_cast<uint4*>(&sBl[so]) = *reinterpret_cast<const uint4*>(&Bl[bp]);
        }
        __syncthreads();

        #pragma unroll
        for (int kt = 0; kt < 32; kt += 16) {
            uint32_t ah[2][4], al[2][4];
            {
                int ar = lane & 15, as_ = (lane >> 4) * 8;
                #pragma unroll
                for (int mt = 0; mt < 2; mt++) {
                    uint32_t off = (uint32_t)((wm * 32 + mt * 16 + ar) * 40 + kt + as_) * 2;
                    ldsm4(ah[mt][0], ah[mt][1], ah[mt][2], ah[mt][3], sb + off);
                    ldsm4(al[mt][0], al[mt][1], al[mt][2], al[mt][3], sb + 10240 + off);
                }
            }
            #pragma unroll
            for (int p = 0; p < 4; p++) {
                int sel = lane >> 3, i = lane & 7;
                uint32_t boff = (uint32_t)((wn * 64 + p * 16 + ((sel >> 1) << 3) + i) * 40
                                           + kt + ((sel & 1) << 3)) * 2;
                uint32_t bh[4], bl[4];
                ldsm4(bh[0], bh[1], bh[2], bh[3], sb + 20480 + boff);
                ldsm4(bl[0], bl[1], bl[2], bl[3], sb + 30720 + boff);
                #pragma unroll
                for (int mt = 0; mt < 2; mt++)
                    #pragma unroll
                    for (int q = 0; q < 2; q++) {
                        float* c = acc[mt][2 * p + q];
                        mma16816(c, ah[mt], &bh[2 * q]);
                        mma16816(c, ah[mt], &bl[2 * q]);
                        mma16816(c, al[mt], &bh[2 * q]);
                    }
            }
        }
        __syncthreads();
    }

    {
        int g = lane >> 2, cc = (lane & 3) * 2;
        #pragma unroll
        for (int mt = 0; mt < 2; mt++)
            #pragma unroll
            for (int nt = 0; nt < 8; nt++) {
                int r0 = wm * 32 + mt * 16 + g;
                int col = wn * 64 + nt * 8 + cc;
                *reinterpret_cast<float2*>(&Csm[r0 * 132 + col]) =
                    make_float2(acc[mt][nt][0], acc[mt][nt][1]);
                *reinterpret_cast<float2*>(&Csm[(r0 + 8) * 132 + col]) =
                    make_float2(acc[mt][nt][2], acc[mt][nt][3]);
            }
    }
    __syncthreads();

    const int r = t >> 1, hh = t & 1, ch0 = hh * 64;
    const int row = n0 + r;
    const float* crow = &Csm[r * 132 + ch0];

    if (MODE == 0) {
        // split Ps/Pr layout: by 0,1 -> Ps[row*256 + by*128 + ...]; by 2,3 -> Pr
        if (row < NN) {
            size_t obase = (by >= 2 ? (size_t)NN * 256 : 0)
                         + (size_t)row * 256 + (size_t)(by & 1) * 128 + ch0;
            float* o = &outF[obase];
            #pragma unroll
            for (int j = 0; j < 64; j += 4)
                *reinterpret_cast<float4*>(&o[j]) = *reinterpret_cast<const float4*>(&crow[j]);
        }
        return;
    }
    if (MODE == 2) {
        if (row < NN) {
            #pragma unroll
            for (int j = 0; j < 64; j += 2) {
                int c = by * 128 + ch0 + j;
                float v0 = swishf(crow[j]     + bias[c]);
                float v1 = swishf(crow[j + 1] + bias[c + 1]);
                split_store(oBh, oBl, (size_t)row * 256 + c, v0, v1);
            }
        }
        return;
    }
    {
        float s = 0.f, s2 = 0.f;
        #pragma unroll
        for (int j = 0; j < 64; j += 4) {
            float4 c4 = *reinterpret_cast<const float4*>(&crow[j]);
            float v0 = c4.x * scale + bias[ch0 + j];
            float v1 = c4.y * scale + bias[ch0 + j + 1];
            float v2 = c4.z * scale + bias[ch0 + j + 2];
            float v3 = c4.w * scale + bias[ch0 + j + 3];
            if (MODE == 3 && row < NN) {
                float4 r4 = *reinterpret_cast<const float4*>(&resid[(size_t)row * 128 + ch0 + j]);
                v0 += r4.x; v1 += r4.y; v2 += r4.z; v3 += r4.w;
            }
            s += v0 + v1 + v2 + v3;
            s2 += v0 * v0 + v1 * v1 + v2 * v2 + v3 * v3;
        }
        s  += __shfl_xor_sync(0xffffffffu, s, 1);
        s2 += __shfl_xor_sync(0xffffffffu, s2, 1);
        float m    = s * (1.0f / 128.0f);
        float var  = s2 * (1.0f / 128.0f) - m * m;
        float rstd = rsqrtf(var + 1e-5f);
        if (row < NN) {
            float mk = mask[row];
            #pragma unroll
            for (int j = 0; j < 64; j += 2) {
                int c = ch0 + j;
                float v0 = crow[j]     * scale + bias[c];
                float v1 = crow[j + 1] * scale + bias[c + 1];
                if (MODE == 3) {
                    float2 r2 = *reinterpret_cast<const float2*>(&resid[(size_t)row * 128 + c]);
                    v0 += r2.x; v1 += r2.y;
                }
                float w0 = ((v0 - m) * rstd * gamma[c]     + beta[c])     * mk;
                float w1 = ((v1 - m) * rstd * gamma[c + 1] + beta[c + 1]) * mk;
                if (MODE == 3) {
                    *reinterpret_cast<float2*>(&outF[(size_t)row * 128 + c]) = make_float2(w0, w1);
                } else {
                    split_store(oBh, oBl, (size_t)row * 256 + oCol + c, w0, w1);
                }
            }
        }
    }
}

// ============================================================================
// Edge kernel (round-5 proven FFMA2 body; Ps/Pr split; tanh swish):
//   h_e = swish(Ps[senders[e]] + Pr[n] + ef[e]@We1[256:288] + be1)
//   S[n] = sum_e h_e  (split bf16 out)
// ============================================================================
__global__ void __launch_bounds__(256, 2) edge_kernel(
    const float* __restrict__ edge_feat, const int* __restrict__ senders,
    const float* __restrict__ We1, const float* __restrict__ be1)
{
    __shared__ __align__(16) u64 efp[NPB * (DEG / 2) * EDIM];
    __shared__ int snd[NPB * DEG];

    const int t  = threadIdx.x;
    const int n0 = blockIdx.x * NPB;
    const int e0 = n0 * DEG;
    const float* __restrict__ Ps = g_P;
    const float* __restrict__ Pr = g_P + (size_t)NN * 256;

    {
        float* efs = reinterpret_cast<float*>(efp);
        for (int j = t; j < NPB * DEG * EDIM; j += 256) {
            int el = j / EDIM, k = j % EDIM;
            int pg = el >> 1, half = el & 1;
            efs[(pg * EDIM + k) * 2 + half] = edge_feat[(size_t)e0 * EDIM + j];
        }
        if (t < NPB * DEG) snd[t] = senders[e0 + t];
    }

    u64 w2[EDIM];
    #pragma unroll
    for (int k = 0; k < EDIM; k++)
        w2[k] = dupf2(We1[(size_t)(HDIM + k) * HDIM + t]);
    const float b1 = be1[t];
    __syncthreads();

    for (int ni = 0; ni < NPB; ni++) {
        const int n = n0 + ni;
        const float pr = Pr[(size_t)n * 256 + t] + b1;
        const u64 prd = dupf2(pr);

        float fv[DEG];
        #pragma unroll
        for (int e = 0; e < DEG; e++)
            fv[e] = Ps[(size_t)snd[ni * DEG + e] * 256 + t];

        float sacc = 0.0f;
        #pragma unroll
        for (int p = 0; p < DEG / 2; p++) {
            u64 v2 = addf2(prd, packf2(fv[2 * p], fv[2 * p + 1]));
            const ulonglong2* ep =
                reinterpret_cast<const ulonglong2*>(&efp[(ni * (DEG / 2) + p) * EDIM]);
            #pragma unroll
            for (int q = 0; q < EDIM / 2; q++) {
                ulonglong2 e2 = ep[q];
                ffma2(v2, e2.x, w2[2 * q]);
                ffma2(v2, e2.y, w2[2 * q + 1]);
            }
            float2 v = unpackf2(v2);
            sacc += swishf(v.x) + swishf(v.y);
        }
        __nv_bfloat16 h = __float2bfloat16(sacc);
        g_Sh[(size_t)n * 256 + t] = h;
        g_Sl[(size_t)n * 256 + t] = __float2bfloat16(sacc - __bfloat162float(h));
    }
}

// ============================================================================
extern "C" void kernel_launch(void* const* d_in, const int* in_sizes, int n_in,
                              void* d_out, int out_size)
{
    const float* node_inp  = (const float*)d_in[0];
    const float* edge_feat = (const float*)d_in[1];
    const float* node_mask = (const float*)d_in[2];
    const float* We1       = (const float*)d_in[3];
    const float* be1       = (const float*)d_in[4];
    const float* We2       = (const float*)d_in[5];
    const float* be2       = (const float*)d_in[6];
    const float* g_msg     = (const float*)d_in[7];
    const float* b_msg     = (const float*)d_in[8];
    const float* Wn1       = (const float*)d_in[9];
    const float* bn1       = (const float*)d_in[10];
    const float* Wn2       = (const float*)d_in[11];
    const float* bn2       = (const float*)d_in[12];
    const float* g_node    = (const float*)d_in[13];
    const float* b_node    = (const float*)d_in[14];
    const int*   senders   = (const int*)d_in[15];
    float* out = (float*)d_out;

    float* Pp;
    __nv_bfloat16 *NAh, *NAl, *Sh, *Sl, *Uh, *Ul, *Wh, *Wl;
    cudaGetSymbolAddress((void**)&Pp,  g_P);
    cudaGetSymbolAddress((void**)&NAh, g_NAh);
    cudaGetSymbolAddress((void**)&NAl, g_NAl);
    cudaGetSymbolAddress((void**)&Sh,  g_Sh);
    cudaGetSymbolAddress((void**)&Sl,  g_Sl);
    cudaGetSymbolAddress((void**)&Uh,  g_Uh);
    cudaGetSymbolAddress((void**)&Ul,  g_Ul);
    cudaGetSymbolAddress((void**)&Wh,  g_Wh);
    cudaGetSymbolAddress((void**)&Wl,  g_Wl);

    const int SMEMT = 67584;
    cudaFuncSetAttribute(mma_gemm<128,0>, cudaFuncAttributeMaxDynamicSharedMemorySize, SMEMT);
    cudaFuncSetAttribute(mma_gemm<256,1>, cudaFuncAttributeMaxDynamicSharedMemorySize, SMEMT);
    cudaFuncSetAttribute(mma_gemm<256,2>, cudaFuncAttributeMaxDynamicSharedMemorySize, SMEMT);
    cudaFuncSetAttribute(mma_gemm<256,3>, cudaFuncAttributeMaxDynamicSharedMemorySize, SMEMT);

    // ---- weight prep: regions [NCtot][K] ----
    wprep<<<128, 256>>>(We1, 256,   0, 128, Wh,          Wl,          32768);
    wprep<<<128, 256>>>(We1, 256, 128, 128, Wh + 32768,  Wl + 32768,  32768);
    wprep<<<128, 256>>>(We2, 128,   0, 256, Wh + 65536,  Wl + 65536,  32768);
    wprep<<<256, 256>>>(Wn1, 256,   0, 256, Wh + 98304,  Wl + 98304,  65536);
    wprep<<<128, 256>>>(Wn2, 128,   0, 256, Wh + 163840, Wl + 163840, 32768);

    conv_node<<<NN / 4, 256>>>(node_inp);

    // 1) P = node_inp @ [We1_s | We1_r] -> Ps/Pr split fp32
    mma_gemm<128,0><<<dim3(GX, 4), 256, SMEMT>>>(
        NAh, NAl, Wh, Wl,
        nullptr, 1.0f, nullptr, nullptr, nullptr, nullptr, Pp, 0, nullptr, nullptr, 0);

    // 2) per-edge swish + segment sum -> S (split bf16)
    edge_kernel<<<NN / NPB, 256>>>(edge_feat, senders, We1, be1);

    // 3) agg = LN(S @ We2 /16 + be2; g_msg,b_msg)*mask -> g_NA cols 128..255
    mma_gemm<256,1><<<dim3(GX, 1), 256, SMEMT>>>(
        Sh, Sl, Wh + 65536, Wl + 65536,
        be2, 1.0f / 16.0f, g_msg, b_msg, node_mask, nullptr, nullptr, 0, NAh, NAl, 128);

    // 4) U = swish(NA @ Wn1 + bn1) -> g_U (split bf16)
    mma_gemm<256,2><<<dim3(GX, 2), 256, SMEMT>>>(
        NAh, NAl, Wh + 98304, Wl + 98304,
        bn1, 1.0f, nullptr, nullptr, nullptr, nullptr, nullptr, 0, Uh, Ul, 0);

    // 5) out = LN(node_inp + U @ Wn2 + bn2; g_node,b_node)*mask -> fp32 out
    mma_gemm<256,3><<<dim3(GX, 1), 256, SMEMT>>>(
        Uh, Ul, Wh + 163840, Wl + 163840,
        bn2, 1.0f, g_node, b_node, node_mask, node_inp, out, 128, nullptr, nullptr, 0);
}

// round 10
// speedup vs baseline: 1.2586x; 1.0571x over previous
#include <cuda_runtime.h>
#include <cuda_fp16.h>
#include <cstdint>

#define NN   50000
#define NP   50048     // 391*128 padded rows
#define DEG  16
#define DIM  128
#define EDIM 32
#define HDIM 256
#define NPB  8
#define GX   391

typedef unsigned long long u64;

// ---- scratch (device globals; no allocation allowed) ----
__device__ float g_P[(size_t)NN * 512];          // fp32 projections (edge gathers)
__device__ __half g_NAh[(size_t)NP * 256];       // cols 0-127 node_inp, 128-255 AGG (hi)
__device__ __half g_NAl[(size_t)NP * 256];       // (activation residual)
__device__ __half g_Sh[(size_t)NP * 256];        // edge-sum S
__device__ __half g_Sl[(size_t)NP * 256];
__device__ __half g_Uh[(size_t)NP * 256];        // node-MLP hidden U
__device__ __half g_Ul[(size_t)NP * 256];
__device__ __half g_Wh[196608];                  // weights, [n][K] per region (1-term fp16)

__device__ __forceinline__ float swishf(float v) {
    return __fdividef(v, 1.0f + __expf(-v));
}
__device__ __forceinline__ uint32_t smem_u32(const void* p) {
    uint32_t a;
    asm("{ .reg .u64 t; cvta.to.shared.u64 t, %1; cvt.u32.u64 %0, t; }" : "=r"(a) : "l"(p));
    return a;
}
__device__ __forceinline__ void ldsm4(uint32_t& r0, uint32_t& r1, uint32_t& r2,
                                      uint32_t& r3, uint32_t addr) {
    asm volatile("ldmatrix.sync.aligned.m8n8.x4.shared.b16 {%0,%1,%2,%3}, [%4];"
                 : "=r"(r0), "=r"(r1), "=r"(r2), "=r"(r3) : "r"(addr));
}
__device__ __forceinline__ void mma16816(float* c, const uint32_t* a, const uint32_t* b) {
    asm volatile("mma.sync.aligned.m16n8k16.row.col.f32.f16.f16.f32 "
                 "{%0,%1,%2,%3}, {%4,%5,%6,%7}, {%8,%9}, {%0,%1,%2,%3};"
                 : "+f"(c[0]), "+f"(c[1]), "+f"(c[2]), "+f"(c[3])
                 : "r"(a[0]), "r"(a[1]), "r"(a[2]), "r"(a[3]), "r"(b[0]), "r"(b[1]));
}
__device__ __forceinline__ void split_store(__half* dh, __half* dl,
                                            size_t pos, float v0, float v1) {
    __half h0 = __float2half_rn(v0), h1 = __float2half_rn(v1);
    __half2 hp; hp.x = h0; hp.y = h1;
    *reinterpret_cast<__half2*>(&dh[pos]) = hp;
    __half2 lp;
    lp.x = __float2half_rn(v0 - __half2float(h0));
    lp.y = __float2half_rn(v1 - __half2float(h1));
    *reinterpret_cast<__half2*>(&dl[pos]) = lp;
}

typedef unsigned long long ull;
__device__ __forceinline__ void ffma2(u64& d, u64 a, u64 b) {
    asm("fma.rn.f32x2 %0, %1, %2, %3;" : "=l"(d) : "l"(a), "l"(b), "l"(d));
}
__device__ __forceinline__ u64 packf2(float lo, float hi) {
    u64 r; asm("mov.b64 %0, {%1, %2};" : "=l"(r) : "f"(lo), "f"(hi)); return r;
}
__device__ __forceinline__ u64 dupf2(float v) {
    u64 r; asm("mov.b64 %0, {%1, %1};" : "=l"(r) : "f"(v)); return r;
}
__device__ __forceinline__ float2 unpackf2(u64 v) {
    float2 r; asm("mov.b64 {%0, %1}, %2;" : "=f"(r.x), "=f"(r.y) : "l"(v)); return r;
}
__device__ __forceinline__ u64 addf2(u64 a, u64 b) {
    u64 r; asm("add.rn.f32x2 %0, %1, %2;" : "=l"(r) : "l"(a), "l"(b)); return r;
}

// ============================================================================
// prep kernels
// ============================================================================
__global__ void conv_node(const float* __restrict__ x) {
    int row = blockIdx.x, t = threadIdx.x;
    float2 v = *reinterpret_cast<const float2*>(&x[(size_t)row * 128 + 2 * t]);
    split_store(g_NAh, g_NAl, (size_t)row * 256 + 2 * t, v.x, v.y);
}
__global__ void wprep(const float* __restrict__ src, int ld, int rowOff, int K,
                      __half* __restrict__ dh, int total) {
    int idx = blockIdx.x * 256 + threadIdx.x;
    if (idx >= total) return;
    int n = idx / K, k = idx % K;
    dh[idx] = __float2half_rn(src[(size_t)(rowOff + k) * ld + n]);
}

// ============================================================================
// 2-term fp16 HMMA GEMM: C = (Ah+Al) @ Bh.  M-tile 128, N-tile 128, BK=32.
//   A exact via 2-term fp16 split; only weight rounding (A@Bl) dropped.
//   MODE 0: fp32 store (ldOut, col by*128)
//   MODE 1: v=acc*scale+bias; LN*mask -> split fp16 g_NA cols 128..255
//   MODE 2: v=swish(acc+bias)        -> split fp16 oB cols by*128..
//   MODE 3: v=acc+bias+resid; LN*mask -> fp32 out
// ============================================================================
template<int K, int MODE>
__global__ void __launch_bounds__(256, 2) mma_gemm(
    const __half* __restrict__ Ah, const __half* __restrict__ Al,
    const __half* __restrict__ Bh,
    const float* __restrict__ bias, float scale,
    const float* __restrict__ gamma, const float* __restrict__ beta,
    const float* __restrict__ mask, const float* __restrict__ resid,
    float* __restrict__ outF, int ldOut,
    __half* __restrict__ oBh, __half* __restrict__ oBl, int oCol)
{
    extern __shared__ __align__(16) char smem[];
    __half* sAh = reinterpret_cast<__half*>(smem);           // [128][40]  bytes 0..10239
    __half* sAl = sAh + 5120;                                //            bytes 10240..20479
    __half* sBh = sAh + 10240;                               // [128n][40k] bytes 20480..30719
    float* Csm = reinterpret_cast<float*>(smem);             // [128][132]

    const uint32_t sb = smem_u32(smem);
    const int t = threadIdx.x, lane = t & 31, warp = t >> 5;
    const int wm = warp & 3, wn = warp >> 2;
    const int n0 = blockIdx.x * 128, by = blockIdx.y;

    float acc[2][8][4];
    #pragma unroll
    for (int mt = 0; mt < 2; mt++)
        #pragma unroll
        for (int nt = 0; nt < 8; nt++)
            #pragma unroll
            for (int q = 0; q < 4; q++) acc[mt][nt][q] = 0.f;

    for (int kb = 0; kb < K; kb += 32) {
        // ---- stage 3 tiles: 512 uint4 each, 2 per thread ----
        #pragma unroll
        for (int s = 0; s < 2; s++) {
            int idx = t + s * 256;
            int row = idx >> 2, g = idx & 3;
            int grow = n0 + row;
            uint4 zh = make_uint4(0u, 0u, 0u, 0u), zl = zh;
            if (grow < NN) {
                size_t ap = (size_t)grow * 256 + kb + g * 8;
                zh = *reinterpret_cast<const uint4*>(&Ah[ap]);
                zl = *reinterpret_cast<const uint4*>(&Al[ap]);
            }
            int so = row * 40 + g * 8;
            *reinterpret_cast<uint4*>(&sAh[so]) = zh;
            *reinterpret_cast<uint4*>(&sAl[so]) = zl;
            size_t bp = (size_t)(by * 128 + row) * K + kb + g * 8;
            *reinterpret_cast<uint4*>(&sBh[so]) = *reinterpret_cast<const uint4*>(&Bh[bp]);
        }
        __syncthreads();

        #pragma unroll
        for (int kt = 0; kt < 32; kt += 16) {
            uint32_t ah[2][4], al[2][4];
            {
                int ar = lane & 15, as_ = (lane >> 4) * 8;
                #pragma unroll
                for (int mt = 0; mt < 2; mt++) {
                    uint32_t off = (uint32_t)((wm * 32 + mt * 16 + ar) * 40 + kt + as_) * 2;
                    ldsm4(ah[mt][0], ah[mt][1], ah[mt][2], ah[mt][3], sb + off);
                    ldsm4(al[mt][0], al[mt][1], al[mt][2], al[mt][3], sb + 10240 + off);
                }
            }
            #pragma unroll
            for (int p = 0; p < 4; p++) {
                int sel = lane >> 3, i = lane & 7;
                uint32_t boff = (uint32_t)((wn * 64 + p * 16 + ((sel >> 1) << 3) + i) * 40
                                           + kt + ((sel & 1) << 3)) * 2;
                uint32_t bh[4];
                ldsm4(bh[0], bh[1], bh[2], bh[3], sb + 20480 + boff);
                #pragma unroll
                for (int mt = 0; mt < 2; mt++)
                    #pragma unroll
                    for (int q = 0; q < 2; q++) {
                        float* c = acc[mt][2 * p + q];
                        mma16816(c, ah[mt], &bh[2 * q]);
                        mma16816(c, al[mt], &bh[2 * q]);
                    }
            }
        }
        __syncthreads();
    }

    {
        int g = lane >> 2, cc = (lane & 3) * 2;
        #pragma unroll
        for (int mt = 0; mt < 2; mt++)
            #pragma unroll
            for (int nt = 0; nt < 8; nt++) {
                int r0 = wm * 32 + mt * 16 + g;
                int col = wn * 64 + nt * 8 + cc;
                *reinterpret_cast<float2*>(&Csm[r0 * 132 + col]) =
                    make_float2(acc[mt][nt][0], acc[mt][nt][1]);
                *reinterpret_cast<float2*>(&Csm[(r0 + 8) * 132 + col]) =
                    make_float2(acc[mt][nt][2], acc[mt][nt][3]);
            }
    }
    __syncthreads();

    const int r = t >> 1, hh = t & 1, ch0 = hh * 64;
    const int row = n0 + r;
    const float* crow = &Csm[r * 132 + ch0];

    if (MODE == 0) {
        if (row < NN) {
            float* o = &outF[(size_t)row * ldOut + by * 128 + ch0];
            #pragma unroll
            for (int j = 0; j < 64; j += 4)
                *reinterpret_cast<float4*>(&o[j]) = *reinterpret_cast<const float4*>(&crow[j]);
        }
        return;
    }
    if (MODE == 2) {
        if (row < NN) {
            #pragma unroll
            for (int j = 0; j < 64; j += 2) {
                int c = by * 128 + ch0 + j;
                float v0 = swishf(crow[j]     + bias[c]);
                float v1 = swishf(crow[j + 1] + bias[c + 1]);
                split_store(oBh, oBl, (size_t)row * 256 + c, v0, v1);
            }
        }
        return;
    }
    {
        float s = 0.f, s2 = 0.f;
        #pragma unroll
        for (int j = 0; j < 64; j += 4) {
            float4 c4 = *reinterpret_cast<const float4*>(&crow[j]);
            float v0 = c4.x * scale + bias[ch0 + j];
            float v1 = c4.y * scale + bias[ch0 + j + 1];
            float v2 = c4.z * scale + bias[ch0 + j + 2];
            float v3 = c4.w * scale + bias[ch0 + j + 3];
            if (MODE == 3 && row < NN) {
                float4 r4 = *reinterpret_cast<const float4*>(&resid[(size_t)row * 128 + ch0 + j]);
                v0 += r4.x; v1 += r4.y; v2 += r4.z; v3 += r4.w;
            }
            s += v0 + v1 + v2 + v3;
            s2 += v0 * v0 + v1 * v1 + v2 * v2 + v3 * v3;
        }
        s  += __shfl_xor_sync(0xffffffffu, s, 1);
        s2 += __shfl_xor_sync(0xffffffffu, s2, 1);
        float m    = s * (1.0f / 128.0f);
        float var  = s2 * (1.0f / 128.0f) - m * m;
        float rstd = rsqrtf(var + 1e-5f);
        if (row < NN) {
            float mk = mask[row];
            #pragma unroll
            for (int j = 0; j < 64; j += 2) {
                int c = ch0 + j;
                float v0 = crow[j]     * scale + bias[c];
                float v1 = crow[j + 1] * scale + bias[c + 1];
                if (MODE == 3) {
                    float2 r2 = *reinterpret_cast<const float2*>(&resid[(size_t)row * 128 + c]);
                    v0 += r2.x; v1 += r2.y;
                }
                float w0 = ((v0 - m) * rstd * gamma[c]     + beta[c])     * mk;
                float w1 = ((v1 - m) * rstd * gamma[c + 1] + beta[c + 1]) * mk;
                if (MODE == 3) {
                    *reinterpret_cast<float2*>(&outF[(size_t)row * 128 + c]) = make_float2(w0, w1);
                } else {
                    split_store(oBh, oBl, (size_t)row * 256 + oCol + c, w0, w1);
                }
            }
        }
    }
}

// ============================================================================
// Edge kernel (round-6 proven body; S out split fp16):
//   h_e = swish(P_s[senders[e]] + P_r[n] + ef[e]@We1[256:288] + be1)
//   S[n] = sum_e h_e
// ============================================================================
__global__ void __launch_bounds__(256, 2) edge_kernel(
    const float* __restrict__ edge_feat, const int* __restrict__ senders,
    const float* __restrict__ We1, const float* __restrict__ be1)
{
    __shared__ __align__(16) u64 efp[NPB * (DEG / 2) * EDIM];
    __shared__ int snd[NPB * DEG];

    const int t  = threadIdx.x;
    const int n0 = blockIdx.x * NPB;
    const int e0 = n0 * DEG;

    {
        float* efs = reinterpret_cast<float*>(efp);
        for (int j = t; j < NPB * DEG * EDIM; j += 256) {
            int el = j / EDIM, k = j % EDIM;
            int pg = el >> 1, half = el & 1;
            efs[(pg * EDIM + k) * 2 + half] = edge_feat[(size_t)e0 * EDIM + j];
        }
        if (t < NPB * DEG) snd[t] = senders[e0 + t];
    }

    u64 w2[EDIM];
    #pragma unroll
    for (int k = 0; k < EDIM; k++)
        w2[k] = dupf2(We1[(size_t)(HDIM + k) * HDIM + t]);
    const float b1 = be1[t];
    __syncthreads();

    for (int ni = 0; ni < NPB; ni++) {
        const int n = n0 + ni;
        const float pr = g_P[(size_t)n * 512 + 256 + t] + b1;
        const u64 prd = dupf2(pr);

        float fv[DEG];
        #pragma unroll
        for (int e = 0; e < DEG; e++)
            fv[e] = g_P[(size_t)snd[ni * DEG + e] * 512 + t];

        float sacc = 0.0f;
        #pragma unroll
        for (int p = 0; p < DEG / 2; p++) {
            u64 v2 = addf2(prd, packf2(fv[2 * p], fv[2 * p + 1]));
            const ulonglong2* ep =
                reinterpret_cast<const ulonglong2*>(&efp[(ni * (DEG / 2) + p) * EDIM]);
            #pragma unroll
            for (int q = 0; q < EDIM / 2; q++) {
                ulonglong2 e2 = ep[q];
                ffma2(v2, e2.x, w2[2 * q]);
                ffma2(v2, e2.y, w2[2 * q + 1]);
            }
            float2 v = unpackf2(v2);
            sacc += swishf(v.x) + swishf(v.y);
        }
        __half h = __float2half_rn(sacc);
        g_Sh[(size_t)n * 256 + t] = h;
        g_Sl[(size_t)n * 256 + t] = __float2half_rn(sacc - __half2float(h));
    }
}

// ============================================================================
extern "C" void kernel_launch(void* const* d_in, const int* in_sizes, int n_in,
                              void* d_out, int out_size)
{
    const float* node_inp  = (const float*)d_in[0];
    const float* edge_feat = (const float*)d_in[1];
    const float* node_mask = (const float*)d_in[2];
    const float* We1       = (const float*)d_in[3];
    const float* be1       = (const float*)d_in[4];
    const float* We2       = (const float*)d_in[5];
    const float* be2       = (const float*)d_in[6];
    const float* g_msg     = (const float*)d_in[7];
    const float* b_msg     = (const float*)d_in[8];
    const float* Wn1       = (const float*)d_in[9];
    const float* bn1       = (const float*)d_in[10];
    const float* Wn2       = (const float*)d_in[11];
    const float* bn2       = (const float*)d_in[12];
    const float* g_node    = (const float*)d_in[13];
    const float* b_node    = (const float*)d_in[14];
    const int*   senders   = (const int*)d_in[15];
    float* out = (float*)d_out;

    float* Pp;
    __half *NAh, *NAl, *Sh, *Sl, *Uh, *Ul, *Wh;
    cudaGetSymbolAddress((void**)&Pp,  g_P);
    cudaGetSymbolAddress((void**)&NAh, g_NAh);
    cudaGetSymbolAddress((void**)&NAl, g_NAl);
    cudaGetSymbolAddress((void**)&Sh,  g_Sh);
    cudaGetSymbolAddress((void**)&Sl,  g_Sl);
    cudaGetSymbolAddress((void**)&Uh,  g_Uh);
    cudaGetSymbolAddress((void**)&Ul,  g_Ul);
    cudaGetSymbolAddress((void**)&Wh,  g_Wh);

    const int SMEMT = 67584;
    cudaFuncSetAttribute(mma_gemm<128,0>, cudaFuncAttributeMaxDynamicSharedMemorySize, SMEMT);
    cudaFuncSetAttribute(mma_gemm<256,1>, cudaFuncAttributeMaxDynamicSharedMemorySize, SMEMT);
    cudaFuncSetAttribute(mma_gemm<256,2>, cudaFuncAttributeMaxDynamicSharedMemorySize, SMEMT);
    cudaFuncSetAttribute(mma_gemm<256,3>, cudaFuncAttributeMaxDynamicSharedMemorySize, SMEMT);

    // ---- weight prep: regions [NCtot][K], 1-term fp16 ----
    wprep<<<128, 256>>>(We1, 256,   0, 128, Wh,          32768);
    wprep<<<128, 256>>>(We1, 256, 128, 128, Wh + 32768,  32768);
    wprep<<<128, 256>>>(We2, 128,   0, 256, Wh + 65536,  32768);
    wprep<<<256, 256>>>(Wn1, 256,   0, 256, Wh + 98304,  65536);
    wprep<<<128, 256>>>(Wn2, 128,   0, 256, Wh + 163840, 32768);

    conv_node<<<NN, 64>>>(node_inp);

    // 1) P = node_inp @ [We1_s | We1_r] -> g_P fp32 [N,512]
    mma_gemm<128,0><<<dim3(GX, 4), 256, SMEMT>>>(
        NAh, NAl, Wh,
        nullptr, 1.0f, nullptr, nullptr, nullptr, nullptr, Pp, 512, nullptr, nullptr, 0);

    // 2) per-edge swish + segment sum -> S (split fp16)
    edge_kernel<<<NN / NPB, 256>>>(edge_feat, senders, We1, be1);

    // 3) agg = LN(S @ We2 /16 + be2; g_msg,b_msg)*mask -> g_NA cols 128..255
    mma_gemm<256,1><<<dim3(GX, 1), 256, SMEMT>>>(
        Sh, Sl, Wh + 65536,
        be2, 1.0f / 16.0f, g_msg, b_msg, node_mask, nullptr, nullptr, 0, NAh, NAl, 128);

    // 4) U = swish(NA @ Wn1 + bn1) -> g_U (split fp16)
    mma_gemm<256,2><<<dim3(GX, 2), 256, SMEMT>>>(
        NAh, NAl, Wh + 98304,
        bn1, 1.0f, nullptr, nullptr, nullptr, nullptr, nullptr, 0, Uh, Ul, 0);

    // 5) out = LN(node_inp + U @ Wn2 + bn2; g_node,b_node)*mask -> fp32 out
    mma_gemm<256,3><<<dim3(GX, 1), 256, SMEMT>>>(
        Uh, Ul, Wh + 163840,
        bn2, 1.0f, g_node, b_node, node_mask, node_inp, out, 128, nullptr, nullptr, 0);
}

// round 11
// speedup vs baseline: 1.3180x; 1.0472x over previous
#include <cuda_runtime.h>
#include <cuda_fp16.h>
#include <cstdint>

#define NN   50000
#define NP   50048     // 391*128 padded rows
#define DEG  16
#define DIM  128
#define EDIM 32
#define HDIM 256
#define NPB  8
#define GX   391

typedef unsigned long long u64;

// ---- scratch (device globals; no allocation allowed) ----
__device__ float g_P[(size_t)NN * 512];          // fp32 projections (edge gathers)
__device__ __half g_NAh[(size_t)NP * 256];       // cols 0-127 node_inp, 128-255 AGG (hi)
__device__ __half g_NAl[(size_t)NP * 256];       // (activation residual)
__device__ __half g_Sh[(size_t)NP * 256];        // edge-sum S
__device__ __half g_Sl[(size_t)NP * 256];
__device__ __half g_Uh[(size_t)NP * 256];        // node-MLP hidden U
__device__ __half g_Ul[(size_t)NP * 256];
__device__ __half g_Wh[196608];                  // weights, [n][K] per region (1-term fp16)

__device__ __forceinline__ float swishf(float v) {
    return __fdividef(v, 1.0f + __expf(-v));
}
__device__ __forceinline__ uint32_t smem_u32(const void* p) {
    uint32_t a;
    asm("{ .reg .u64 t; cvta.to.shared.u64 t, %1; cvt.u32.u64 %0, t; }" : "=r"(a) : "l"(p));
    return a;
}
__device__ __forceinline__ void ldsm4(uint32_t& r0, uint32_t& r1, uint32_t& r2,
                                      uint32_t& r3, uint32_t addr) {
    asm volatile("ldmatrix.sync.aligned.m8n8.x4.shared.b16 {%0,%1,%2,%3}, [%4];"
                 : "=r"(r0), "=r"(r1), "=r"(r2), "=r"(r3) : "r"(addr));
}
__device__ __forceinline__ void mma16816(float* c, const uint32_t* a, const uint32_t* b) {
    asm volatile("mma.sync.aligned.m16n8k16.row.col.f32.f16.f16.f32 "
                 "{%0,%1,%2,%3}, {%4,%5,%6,%7}, {%8,%9}, {%0,%1,%2,%3};"
                 : "+f"(c[0]), "+f"(c[1]), "+f"(c[2]), "+f"(c[3])
                 : "r"(a[0]), "r"(a[1]), "r"(a[2]), "r"(a[3]), "r"(b[0]), "r"(b[1]));
}
__device__ __forceinline__ void cp_async16(uint32_t dst, const void* src, int src_bytes) {
    asm volatile("cp.async.cg.shared.global [%0], [%1], 16, %2;"
                 :: "r"(dst), "l"(src), "r"(src_bytes) : "memory");
}
__device__ __forceinline__ void cp_commit() {
    asm volatile("cp.async.commit_group;" ::: "memory");
}
__device__ __forceinline__ void split_store(__half* dh, __half* dl,
                                            size_t pos, float v0, float v1) {
    __half h0 = __float2half_rn(v0), h1 = __float2half_rn(v1);
    __half2 hp; hp.x = h0; hp.y = h1;
    *reinterpret_cast<__half2*>(&dh[pos]) = hp;
    __half2 lp;
    lp.x = __float2half_rn(v0 - __half2float(h0));
    lp.y = __float2half_rn(v1 - __half2float(h1));
    *reinterpret_cast<__half2*>(&dl[pos]) = lp;
}

__device__ __forceinline__ void ffma2(u64& d, u64 a, u64 b) {
    asm("fma.rn.f32x2 %0, %1, %2, %3;" : "=l"(d) : "l"(a), "l"(b), "l"(d));
}
__device__ __forceinline__ u64 packf2(float lo, float hi) {
    u64 r; asm("mov.b64 %0, {%1, %2};" : "=l"(r) : "f"(lo), "f"(hi)); return r;
}
__device__ __forceinline__ u64 dupf2(float v) {
    u64 r; asm("mov.b64 %0, {%1, %1};" : "=l"(r) : "f"(v)); return r;
}
__device__ __forceinline__ float2 unpackf2(u64 v) {
    float2 r; asm("mov.b64 {%0, %1}, %2;" : "=f"(r.x), "=f"(r.y) : "l"(v)); return r;
}
__device__ __forceinline__ u64 addf2(u64 a, u64 b) {
    u64 r; asm("add.rn.f32x2 %0, %1, %2;" : "=l"(r) : "l"(a), "l"(b)); return r;
}

// ============================================================================
// prep kernels
// ============================================================================
__global__ void conv_node(const float* __restrict__ x) {
    int t = threadIdx.x;
    int row = blockIdx.x * 4 + (t >> 6);
    int c = (t & 63) * 2;
    float2 v = *reinterpret_cast<const float2*>(&x[(size_t)row * 128 + c]);
    split_store(g_NAh, g_NAl, (size_t)row * 256 + c, v.x, v.y);
}
__global__ void wprep(const float* __restrict__ src, int ld, int rowOff, int K,
                      __half* __restrict__ dh, int total) {
    int idx = blockIdx.x * 256 + threadIdx.x;
    if (idx >= total) return;
    int n = idx / K, k = idx % K;
    dh[idx] = __float2half_rn(src[(size_t)(rowOff + k) * ld + n]);
}

// ============================================================================
// 2-term fp16 HMMA GEMM, cp.async double-buffered staging.
//   C = (Ah+Al) @ Bh.  M-tile 128, N-tile 128, BK=32.
//   MODE 0: fp32 store (ldOut, col by*128)
//   MODE 1: v=acc*scale+bias; LN*mask -> split fp16 g_NA cols 128..255
//   MODE 2: v=swish(acc+bias)        -> split fp16 oB cols by*128..
//   MODE 3: v=acc+bias+resid; LN*mask -> fp32 out
// Smem: buf[2] x (sAh 10240B | sAl 10240B | sBh 10240B) = 61440B; Csm overlays.
// ============================================================================
template<int K, int MODE>
__global__ void __launch_bounds__(256, 2) mma_gemm(
    const __half* __restrict__ Ah, const __half* __restrict__ Al,
    const __half* __restrict__ Bh,
    const float* __restrict__ bias, float scale,
    const float* __restrict__ gamma, const float* __restrict__ beta,
    const float* __restrict__ mask, const float* __restrict__ resid,
    float* __restrict__ outF, int ldOut,
    __half* __restrict__ oBh, __half* __restrict__ oBl, int oCol)
{
    extern __shared__ __align__(16) char smem[];
    float* Csm = reinterpret_cast<float*>(smem);             // [128][132] (post-loop)

    const uint32_t sb = smem_u32(smem);
    const int t = threadIdx.x, lane = t & 31, warp = t >> 5;
    const int wm = warp & 3, wn = warp >> 2;
    const int n0 = blockIdx.x * 128, by = blockIdx.y;
    constexpr int NCH = K / 32;
    constexpr uint32_t BUFB = 30720;

    float acc[2][8][4];
    #pragma unroll
    for (int mt = 0; mt < 2; mt++)
        #pragma unroll
        for (int nt = 0; nt < 8; nt++)
            #pragma unroll
            for (int q = 0; q < 4; q++) acc[mt][nt][q] = 0.f;

    // per-thread staging coords (2 stages of 256 threads cover 512 rows-of-8)
    const int r0s = t >> 2, g0 = t & 3;

    // ---- async stage of chunk c into buffer b ----
    auto stage = [&](int c, int b) {
        uint32_t base = sb + (uint32_t)b * BUFB;
        #pragma unroll
        for (int s = 0; s < 2; s++) {
            int row = r0s + s * 64;
            int grow = n0 + row;
            int ga = grow < NN ? grow : NN - 1;
            int ok = grow < NN ? 16 : 0;
            uint32_t so = (uint32_t)(row * 40 + g0 * 8) * 2;
            cp_async16(base + so,         &Ah[(size_t)ga * 256 + c * 32 + g0 * 8], ok);
            cp_async16(base + 10240 + so, &Al[(size_t)ga * 256 + c * 32 + g0 * 8], ok);
            cp_async16(base + 20480 + so,
                       &Bh[(size_t)(by * 128 + row) * K + c * 32 + g0 * 8], 16);
        }
        cp_commit();
    };

    stage(0, 0);

    for (int c = 0; c < NCH; c++) {
        const int b = c & 1;
        if (c + 1 < NCH) {
            stage(c + 1, (c + 1) & 1);
            asm volatile("cp.async.wait_group 1;" ::: "memory");
        } else {
            asm volatile("cp.async.wait_group 0;" ::: "memory");
        }
        __syncthreads();

        const uint32_t base = sb + (uint32_t)b * BUFB;
        #pragma unroll
        for (int kt = 0; kt < 32; kt += 16) {
            uint32_t ah[2][4], al[2][4];
            {
                int ar = lane & 15, as_ = (lane >> 4) * 8;
                #pragma unroll
                for (int mt = 0; mt < 2; mt++) {
                    uint32_t off = (uint32_t)((wm * 32 + mt * 16 + ar) * 40 + kt + as_) * 2;
                    ldsm4(ah[mt][0], ah[mt][1], ah[mt][2], ah[mt][3], base + off);
                    ldsm4(al[mt][0], al[mt][1], al[mt][2], al[mt][3], base + 10240 + off);
                }
            }
            #pragma unroll
            for (int p = 0; p < 4; p++) {
                int sel = lane >> 3, i = lane & 7;
                uint32_t boff = (uint32_t)((wn * 64 + p * 16 + ((sel >> 1) << 3) + i) * 40
                                           + kt + ((sel & 1) << 3)) * 2;
                uint32_t bh[4];
                ldsm4(bh[0], bh[1], bh[2], bh[3], base + 20480 + boff);
                #pragma unroll
                for (int mt = 0; mt < 2; mt++)
                    #pragma unroll
                    for (int q = 0; q < 2; q++) {
                        float* cc = acc[mt][2 * p + q];
                        mma16816(cc, ah[mt], &bh[2 * q]);
                        mma16816(cc, al[mt], &bh[2 * q]);
                    }
            }
        }
        __syncthreads();
    }

    // ---- fragments -> Csm ----
    {
        int g = lane >> 2, cc = (lane & 3) * 2;
        #pragma unroll
        for (int mt = 0; mt < 2; mt++)
            #pragma unroll
            for (int nt = 0; nt < 8; nt++) {
                int r0 = wm * 32 + mt * 16 + g;
                int col = wn * 64 + nt * 8 + cc;
                *reinterpret_cast<float2*>(&Csm[r0 * 132 + col]) =
                    make_float2(acc[mt][nt][0], acc[mt][nt][1]);
                *reinterpret_cast<float2*>(&Csm[(r0 + 8) * 132 + col]) =
                    make_float2(acc[mt][nt][2], acc[mt][nt][3]);
            }
    }
    __syncthreads();

    const int r = t >> 1, hh = t & 1, ch0 = hh * 64;
    const int row = n0 + r;
    const float* crow = &Csm[r * 132 + ch0];

    if (MODE == 0) {
        if (row < NN) {
            float* o = &outF[(size_t)row * ldOut + by * 128 + ch0];
            #pragma unroll
            for (int j = 0; j < 64; j += 4)
                *reinterpret_cast<float4*>(&o[j]) = *reinterpret_cast<const float4*>(&crow[j]);
        }
        return;
    }
    if (MODE == 2) {
        if (row < NN) {
            #pragma unroll
            for (int j = 0; j < 64; j += 2) {
                int c = by * 128 + ch0 + j;
                float v0 = swishf(crow[j]     + bias[c]);
                float v1 = swishf(crow[j + 1] + bias[c + 1]);
                split_store(oBh, oBl, (size_t)row * 256 + c, v0, v1);
            }
        }
        return;
    }
    {
        float s = 0.f, s2 = 0.f;
        #pragma unroll
        for (int j = 0; j < 64; j += 4) {
            float4 c4 = *reinterpret_cast<const float4*>(&crow[j]);
            float v0 = c4.x * scale + bias[ch0 + j];
            float v1 = c4.y * scale + bias[ch0 + j + 1];
            float v2 = c4.z * scale + bias[ch0 + j + 2];
            float v3 = c4.w * scale + bias[ch0 + j + 3];
            if (MODE == 3 && row < NN) {
                float4 r4 = *reinterpret_cast<const float4*>(&resid[(size_t)row * 128 + ch0 + j]);
                v0 += r4.x; v1 += r4.y; v2 += r4.z; v3 += r4.w;
            }
            s += v0 + v1 + v2 + v3;
            s2 += v0 * v0 + v1 * v1 + v2 * v2 + v3 * v3;
        }
        s  += __shfl_xor_sync(0xffffffffu, s, 1);
        s2 += __shfl_xor_sync(0xffffffffu, s2, 1);
        float m    = s * (1.0f / 128.0f);
        float var  = s2 * (1.0f / 128.0f) - m * m;
        float rstd = rsqrtf(var + 1e-5f);
        if (row < NN) {
            float mk = mask[row];
            #pragma unroll
            for (int j = 0; j < 64; j += 2) {
                int c = ch0 + j;
                float v0 = crow[j]     * scale + bias[c];
                float v1 = crow[j + 1] * scale + bias[c + 1];
                if (MODE == 3) {
                    float2 r2 = *reinterpret_cast<const float2*>(&resid[(size_t)row * 128 + c]);
                    v0 += r2.x; v1 += r2.y;
                }
                float w0 = ((v0 - m) * rstd * gamma[c]     + beta[c])     * mk;
                float w1 = ((v1 - m) * rstd * gamma[c + 1] + beta[c + 1]) * mk;
                if (MODE == 3) {
                    *reinterpret_cast<float2*>(&outF[(size_t)row * 128 + c]) = make_float2(w0, w1);
                } else {
                    split_store(oBh, oBl, (size_t)row * 256 + oCol + c, w0, w1);
                }
            }
        }
    }
}

// ============================================================================
// Edge kernel (round-6 proven body; S out split fp16):
//   h_e = swish(P_s[senders[e]] + P_r[n] + ef[e]@We1[256:288] + be1)
//   S[n] = sum_e h_e
// ============================================================================
__global__ void __launch_bounds__(256, 2) edge_kernel(
    const float* __restrict__ edge_feat, const int* __restrict__ senders,
    const float* __restrict__ We1, const float* __restrict__ be1)
{
    __shared__ __align__(16) u64 efp[NPB * (DEG / 2) * EDIM];
    __shared__ int snd[NPB * DEG];

    const int t  = threadIdx.x;
    const int n0 = blockIdx.x * NPB;
    const int e0 = n0 * DEG;

    {
        float* efs = reinterpret_cast<float*>(efp);
        for (int j = t; j < NPB * DEG * EDIM; j += 256) {
            int el = j / EDIM, k = j % EDIM;
            int pg = el >> 1, half = el & 1;
            efs[(pg * EDIM + k) * 2 + half] = edge_feat[(size_t)e0 * EDIM + j];
        }
        if (t < NPB * DEG) snd[t] = senders[e0 + t];
    }

    u64 w2[EDIM];
    #pragma unroll
    for (int k = 0; k < EDIM; k++)
        w2[k] = dupf2(We1[(size_t)(HDIM + k) * HDIM + t]);
    const float b1 = be1[t];
    __syncthreads();

    for (int ni = 0; ni < NPB; ni++) {
        const int n = n0 + ni;
        const float pr = g_P[(size_t)n * 512 + 256 + t] + b1;
        const u64 prd = dupf2(pr);

        float fv[DEG];
        #pragma unroll
        for (int e = 0; e < DEG; e++)
            fv[e] = g_P[(size_t)snd[ni * DEG + e] * 512 + t];

        float sacc = 0.0f;
        #pragma unroll
        for (int p = 0; p < DEG / 2; p++) {
            u64 v2 = addf2(prd, packf2(fv[2 * p], fv[2 * p + 1]));
            const ulonglong2* ep =
                reinterpret_cast<const ulonglong2*>(&efp[(ni * (DEG / 2) + p) * EDIM]);
            #pragma unroll
            for (int q = 0; q < EDIM / 2; q++) {
                ulonglong2 e2 = ep[q];
                ffma2(v2, e2.x, w2[2 * q]);
                ffma2(v2, e2.y, w2[2 * q + 1]);
            }
            float2 v = unpackf2(v2);
            sacc += swishf(v.x) + swishf(v.y);
        }
        __half h = __float2half_rn(sacc);
        g_Sh[(size_t)n * 256 + t] = h;
        g_Sl[(size_t)n * 256 + t] = __float2half_rn(sacc - __half2float(h));
    }
}

// ============================================================================
extern "C" void kernel_launch(void* const* d_in, const int* in_sizes, int n_in,
                              void* d_out, int out_size)
{
    const float* node_inp  = (const float*)d_in[0];
    const float* edge_feat = (const float*)d_in[1];
    const float* node_mask = (const float*)d_in[2];
    const float* We1       = (const float*)d_in[3];
    const float* be1       = (const float*)d_in[4];
    const float* We2       = (const float*)d_in[5];
    const float* be2       = (const float*)d_in[6];
    const float* g_msg     = (const float*)d_in[7];
    const float* b_msg     = (const float*)d_in[8];
    const float* Wn1       = (const float*)d_in[9];
    const float* bn1       = (const float*)d_in[10];
    const float* Wn2       = (const float*)d_in[11];
    const float* bn2       = (const float*)d_in[12];
    const float* g_node    = (const float*)d_in[13];
    const float* b_node    = (const float*)d_in[14];
    const int*   senders   = (const int*)d_in[15];
    float* out = (float*)d_out;

    float* Pp;
    __half *NAh, *NAl, *Sh, *Sl, *Uh, *Ul, *Wh;
    cudaGetSymbolAddress((void**)&Pp,  g_P);
    cudaGetSymbolAddress((void**)&NAh, g_NAh);
    cudaGetSymbolAddress((void**)&NAl, g_NAl);
    cudaGetSymbolAddress((void**)&Sh,  g_Sh);
    cudaGetSymbolAddress((void**)&Sl,  g_Sl);
    cudaGetSymbolAddress((void**)&Uh,  g_Uh);
    cudaGetSymbolAddress((void**)&Ul,  g_Ul);
    cudaGetSymbolAddress((void**)&Wh,  g_Wh);

    const int SMEMT = 67584;
    cudaFuncSetAttribute(mma_gemm<128,0>, cudaFuncAttributeMaxDynamicSharedMemorySize, SMEMT);
    cudaFuncSetAttribute(mma_gemm<256,1>, cudaFuncAttributeMaxDynamicSharedMemorySize, SMEMT);
    cudaFuncSetAttribute(mma_gemm<256,2>, cudaFuncAttributeMaxDynamicSharedMemorySize, SMEMT);
    cudaFuncSetAttribute(mma_gemm<256,3>, cudaFuncAttributeMaxDynamicSharedMemorySize, SMEMT);

    // ---- weight prep: regions [NCtot][K], 1-term fp16 ----
    wprep<<<128, 256>>>(We1, 256,   0, 128, Wh,          32768);
    wprep<<<128, 256>>>(We1, 256, 128, 128, Wh + 32768,  32768);
    wprep<<<128, 256>>>(We2, 128,   0, 256, Wh + 65536,  32768);
    wprep<<<256, 256>>>(Wn1, 256,   0, 256, Wh + 98304,  65536);
    wprep<<<128, 256>>>(Wn2, 128,   0, 256, Wh + 163840, 32768);

    conv_node<<<NN / 4, 256>>>(node_inp);

    // 1) P = node_inp @ [We1_s | We1_r] -> g_P fp32 [N,512]
    mma_gemm<128,0><<<dim3(GX, 4), 256, SMEMT>>>(
        NAh, NAl, Wh,
        nullptr, 1.0f, nullptr, nullptr, nullptr, nullptr, Pp, 512, nullptr, nullptr, 0);

    // 2) per-edge swish + segment sum -> S (split fp16)
    edge_kernel<<<NN / NPB, 256>>>(edge_feat, senders, We1, be1);

    // 3) agg = LN(S @ We2 /16 + be2; g_msg,b_msg)*mask -> g_NA cols 128..255
    mma_gemm<256,1><<<dim3(GX, 1), 256, SMEMT>>>(
        Sh, Sl, Wh + 65536,
        be2, 1.0f / 16.0f, g_msg, b_msg, node_mask, nullptr, nullptr, 0, NAh, NAl, 128);

    // 4) U = swish(NA @ Wn1 + bn1) -> g_U (split fp16)
    mma_gemm<256,2><<<dim3(GX, 2), 256, SMEMT>>>(
        NAh, NAl, Wh + 98304,
        bn1, 1.0f, nullptr, nullptr, nullptr, nullptr, nullptr, 0, Uh, Ul, 0);

    // 5) out = LN(node_inp + U @ Wn2 + bn2; g_node,b_node)*mask -> fp32 out
    mma_gemm<256,3><<<dim3(GX, 1), 256, SMEMT>>>(
        Uh, Ul, Wh + 163840,
        bn2, 1.0f, g_node, b_node, node_mask, node_inp, out, 128, nullptr, nullptr, 0);
}

// round 12
// speedup vs baseline: 2.0418x; 1.5491x over previous
#include <cuda_runtime.h>
#include <cuda_fp16.h>
#include <cstdint>

#define NN   50000
#define NP   50048     // 391*128 padded rows
#define DEG  16
#define DIM  128
#define EDIM 32
#define HDIM 256
#define NPB  8
#define GX   391

typedef unsigned long long u64;

// ---- scratch (device globals; no allocation allowed) ----
__device__ float g_P[(size_t)NN * 512];          // fp32 projections (edge gathers)
__device__ __half g_NAh[(size_t)NP * 256];       // cols 0-127 node_inp, 128-255 AGG (hi)
__device__ __half g_NAl[(size_t)NP * 256];       // (activation residual)
__device__ __half g_Sh[(size_t)NP * 256];        // edge-sum S
__device__ __half g_Sl[(size_t)NP * 256];
__device__ __half g_Uh[(size_t)NP * 256];        // node-MLP hidden U
__device__ __half g_Ul[(size_t)NP * 256];
__device__ __half g_Wh[196608];                  // GEMM weights, [n][K] per region
__device__ __half g_We[8192];                    // edge-proj weights [256 ch][32 k] fp16

__device__ __forceinline__ float swishf(float v) {
    return __fdividef(v, 1.0f + __expf(-v));
}
__device__ __forceinline__ uint32_t smem_u32(const void* p) {
    uint32_t a;
    asm("{ .reg .u64 t; cvta.to.shared.u64 t, %1; cvt.u32.u64 %0, t; }" : "=r"(a) : "l"(p));
    return a;
}
__device__ __forceinline__ void ldsm4(uint32_t& r0, uint32_t& r1, uint32_t& r2,
                                      uint32_t& r3, uint32_t addr) {
    asm volatile("ldmatrix.sync.aligned.m8n8.x4.shared.b16 {%0,%1,%2,%3}, [%4];"
                 : "=r"(r0), "=r"(r1), "=r"(r2), "=r"(r3) : "r"(addr));
}
__device__ __forceinline__ void mma16816(float* c, const uint32_t* a, const uint32_t* b) {
    asm volatile("mma.sync.aligned.m16n8k16.row.col.f32.f16.f16.f32 "
                 "{%0,%1,%2,%3}, {%4,%5,%6,%7}, {%8,%9}, {%0,%1,%2,%3};"
                 : "+f"(c[0]), "+f"(c[1]), "+f"(c[2]), "+f"(c[3])
                 : "r"(a[0]), "r"(a[1]), "r"(a[2]), "r"(a[3]), "r"(b[0]), "r"(b[1]));
}
__device__ __forceinline__ void cp_async16(uint32_t dst, const void* src, int src_bytes) {
    asm volatile("cp.async.cg.shared.global [%0], [%1], 16, %2;"
                 :: "r"(dst), "l"(src), "r"(src_bytes) : "memory");
}
__device__ __forceinline__ void cp_commit() {
    asm volatile("cp.async.commit_group;" ::: "memory");
}
__device__ __forceinline__ void split_store(__half* dh, __half* dl,
                                            size_t pos, float v0, float v1) {
    __half h0 = __float2half_rn(v0), h1 = __float2half_rn(v1);
    __half2 hp; hp.x = h0; hp.y = h1;
    *reinterpret_cast<__half2*>(&dh[pos]) = hp;
    __half2 lp;
    lp.x = __float2half_rn(v0 - __half2float(h0));
    lp.y = __float2half_rn(v1 - __half2float(h1));
    *reinterpret_cast<__half2*>(&dl[pos]) = lp;
}

// ============================================================================
// prep kernels (3 launches so edge_kernel is launch index 5 for ncu -s 5)
// ============================================================================
__global__ void conv_node(const float* __restrict__ x) {
    int t = threadIdx.x;
    int row = blockIdx.x * 4 + (t >> 6);
    int c = (t & 63) * 2;
    float2 v = *reinterpret_cast<const float2*>(&x[(size_t)row * 128 + c]);
    split_store(g_NAh, g_NAl, (size_t)row * 256 + c, v.x, v.y);
}
__global__ void wprepA(const float* __restrict__ We1) {      // 65536 elems
    int idx = blockIdx.x * 256 + threadIdx.x;
    int local = idx & 32767, region = idx >> 15;
    int n = local >> 7, k = local & 127;
    g_Wh[idx] = __float2half_rn(We1[(size_t)(region * 128 + k) * 256 + n]);
}
__global__ void wprepB(const float* __restrict__ We2, const float* __restrict__ Wn1) {
    int idx = blockIdx.x * 256 + threadIdx.x;                // 98304 elems
    if (idx < 32768) {
        int n = idx >> 8, k = idx & 255;
        g_Wh[65536 + idx] = __float2half_rn(We2[(size_t)k * 128 + n]);
    } else {
        int j = idx - 32768, n = j >> 8, k = j & 255;
        g_Wh[98304 + j] = __float2half_rn(Wn1[(size_t)k * 256 + n]);
    }
}
__global__ void wprepC(const float* __restrict__ Wn2, const float* __restrict__ We1) {
    int idx = blockIdx.x * 256 + threadIdx.x;                // 40960 elems
    if (idx < 32768) {
        int n = idx >> 8, k = idx & 255;
        g_Wh[163840 + idx] = __float2half_rn(Wn2[(size_t)k * 128 + n]);
    } else {
        int j = idx - 32768, n = j >> 5, k = j & 31;
        g_We[j] = __float2half_rn(We1[(size_t)(256 + k) * 256 + n]);
    }
}

// ============================================================================
// 2-term fp16 HMMA GEMM, cp.async double-buffered (round-11 proven, 856.6us).
// ============================================================================
template<int K, int MODE>
__global__ void __launch_bounds__(256, 2) mma_gemm(
    const __half* __restrict__ Ah, const __half* __restrict__ Al,
    const __half* __restrict__ Bh,
    const float* __restrict__ bias, float scale,
    const float* __restrict__ gamma, const float* __restrict__ beta,
    const float* __restrict__ mask, const float* __restrict__ resid,
    float* __restrict__ outF, int ldOut,
    __half* __restrict__ oBh, __half* __restrict__ oBl, int oCol)
{
    extern __shared__ __align__(16) char smem[];
    float* Csm = reinterpret_cast<float*>(smem);             // [128][132] (post-loop)

    const uint32_t sb = smem_u32(smem);
    const int t = threadIdx.x, lane = t & 31, warp = t >> 5;
    const int wm = warp & 3, wn = warp >> 2;
    const int n0 = blockIdx.x * 128, by = blockIdx.y;
    constexpr int NCH = K / 32;
    constexpr uint32_t BUFB = 30720;

    float acc[2][8][4];
    #pragma unroll
    for (int mt = 0; mt < 2; mt++)
        #pragma unroll
        for (int nt = 0; nt < 8; nt++)
            #pragma unroll
            for (int q = 0; q < 4; q++) acc[mt][nt][q] = 0.f;

    const int r0s = t >> 2, g0 = t & 3;

    auto stage = [&](int c, int b) {
        uint32_t base = sb + (uint32_t)b * BUFB;
        #pragma unroll
        for (int s = 0; s < 2; s++) {
            int row = r0s + s * 64;
            int grow = n0 + row;
            int ga = grow < NN ? grow : NN - 1;
            int ok = grow < NN ? 16 : 0;
            uint32_t so = (uint32_t)(row * 40 + g0 * 8) * 2;
            cp_async16(base + so,         &Ah[(size_t)ga * 256 + c * 32 + g0 * 8], ok);
            cp_async16(base + 10240 + so, &Al[(size_t)ga * 256 + c * 32 + g0 * 8], ok);
            cp_async16(base + 20480 + so,
                       &Bh[(size_t)(by * 128 + row) * K + c * 32 + g0 * 8], 16);
        }
        cp_commit();
    };

    stage(0, 0);

    for (int c = 0; c < NCH; c++) {
        const int b = c & 1;
        if (c + 1 < NCH) {
            stage(c + 1, (c + 1) & 1);
            asm volatile("cp.async.wait_group 1;" ::: "memory");
        } else {
            asm volatile("cp.async.wait_group 0;" ::: "memory");
        }
        __syncthreads();

        const uint32_t base = sb + (uint32_t)b * BUFB;
        #pragma unroll
        for (int kt = 0; kt < 32; kt += 16) {
            uint32_t ah[2][4], al[2][4];
            {
                int ar = lane & 15, as_ = (lane >> 4) * 8;
                #pragma unroll
                for (int mt = 0; mt < 2; mt++) {
                    uint32_t off = (uint32_t)((wm * 32 + mt * 16 + ar) * 40 + kt + as_) * 2;
                    ldsm4(ah[mt][0], ah[mt][1], ah[mt][2], ah[mt][3], base + off);
                    ldsm4(al[mt][0], al[mt][1], al[mt][2], al[mt][3], base + 10240 + off);
                }
            }
            #pragma unroll
            for (int p = 0; p < 4; p++) {
                int sel = lane >> 3, i = lane & 7;
                uint32_t boff = (uint32_t)((wn * 64 + p * 16 + ((sel >> 1) << 3) + i) * 40
                                           + kt + ((sel & 1) << 3)) * 2;
                uint32_t bh[4];
                ldsm4(bh[0], bh[1], bh[2], bh[3], base + 20480 + boff);
                #pragma unroll
                for (int mt = 0; mt < 2; mt++)
                    #pragma unroll
                    for (int q = 0; q < 2; q++) {
                        float* cc = acc[mt][2 * p + q];
                        mma16816(cc, ah[mt], &bh[2 * q]);
                        mma16816(cc, al[mt], &bh[2 * q]);
                    }
            }
        }
        __syncthreads();
    }

    {
        int g = lane >> 2, cc = (lane & 3) * 2;
        #pragma unroll
        for (int mt = 0; mt < 2; mt++)
            #pragma unroll
            for (int nt = 0; nt < 8; nt++) {
                int r0 = wm * 32 + mt * 16 + g;
                int col = wn * 64 + nt * 8 + cc;
                *reinterpret_cast<float2*>(&Csm[r0 * 132 + col]) =
                    make_float2(acc[mt][nt][0], acc[mt][nt][1]);
                *reinterpret_cast<float2*>(&Csm[(r0 + 8) * 132 + col]) =
                    make_float2(acc[mt][nt][2], acc[mt][nt][3]);
            }
    }
    __syncthreads();

    const int r = t >> 1, hh = t & 1, ch0 = hh * 64;
    const int row = n0 + r;
    const float* crow = &Csm[r * 132 + ch0];

    if (MODE == 0) {
        if (row < NN) {
            float* o = &outF[(size_t)row * ldOut + by * 128 + ch0];
            #pragma unroll
            for (int j = 0; j < 64; j += 4)
                *reinterpret_cast<float4*>(&o[j]) = *reinterpret_cast<const float4*>(&crow[j]);
        }
        return;
    }
    if (MODE == 2) {
        if (row < NN) {
            #pragma unroll
            for (int j = 0; j < 64; j += 2) {
                int c = by * 128 + ch0 + j;
                float v0 = swishf(crow[j]     + bias[c]);
                float v1 = swishf(crow[j + 1] + bias[c + 1]);
                split_store(oBh, oBl, (size_t)row * 256 + c, v0, v1);
            }
        }
        return;
    }
    {
        float s = 0.f, s2 = 0.f;
        #pragma unroll
        for (int j = 0; j < 64; j += 4) {
            float4 c4 = *reinterpret_cast<const float4*>(&crow[j]);
            float v0 = c4.x * scale + bias[ch0 + j];
            float v1 = c4.y * scale + bias[ch0 + j + 1];
            float v2 = c4.z * scale + bias[ch0 + j + 2];
            float v3 = c4.w * scale + bias[ch0 + j + 3];
            if (MODE == 3 && row < NN) {
                float4 r4 = *reinterpret_cast<const float4*>(&resid[(size_t)row * 128 + ch0 + j]);
                v0 += r4.x; v1 += r4.y; v2 += r4.z; v3 += r4.w;
            }
            s += v0 + v1 + v2 + v3;
            s2 += v0 * v0 + v1 * v1 + v2 * v2 + v3 * v3;
        }
        s  += __shfl_xor_sync(0xffffffffu, s, 1);
        s2 += __shfl_xor_sync(0xffffffffu, s2, 1);
        float m    = s * (1.0f / 128.0f);
        float var  = s2 * (1.0f / 128.0f) - m * m;
        float rstd = rsqrtf(var + 1e-5f);
        if (row < NN) {
            float mk = mask[row];
            #pragma unroll
            for (int j = 0; j < 64; j += 2) {
                int c = ch0 + j;
                float v0 = crow[j]     * scale + bias[c];
                float v1 = crow[j + 1] * scale + bias[c + 1];
                if (MODE == 3) {
                    float2 r2 = *reinterpret_cast<const float2*>(&resid[(size_t)row * 128 + c]);
                    v0 += r2.x; v1 += r2.y;
                }
                float w0 = ((v0 - m) * rstd * gamma[c]     + beta[c])     * mk;
                float w1 = ((v1 - m) * rstd * gamma[c + 1] + beta[c + 1]) * mk;
                if (MODE == 3) {
                    *reinterpret_cast<float2*>(&outF[(size_t)row * 128 + c]) = make_float2(w0, w1);
                } else {
                    split_store(oBh, oBl, (size_t)row * 256 + oCol + c, w0, w1);
                }
            }
        }
    }
}

// ============================================================================
// Edge kernel v3: phase-separated HMMA projection + proven scalar tail.
//   Phase A: EP[128 edge][256 ch] = ef @ We1_edge  (fp16 1-term MMA -> smem)
//   Phase B: S[n] = sum_e swish(Ps[snd]+Pr[n]+EP[e]+be1)  (identical to r6 tail)
// Smem: sW [256][40] fp16 | sE [128][40] fp16 | EP [128][260] fp16 | snd[128]
// ============================================================================
__global__ void __launch_bounds__(256, 2) edge_kernel(
    const float* __restrict__ edge_feat, const int* __restrict__ senders,
    const __half* __restrict__ gWe, const float* __restrict__ be1)
{
    extern __shared__ __align__(16) char esm[];
    __half* sW = reinterpret_cast<__half*>(esm);             // 20480 B
    __half* sE = reinterpret_cast<__half*>(esm + 20480);     // 10240 B
    __half* EP = reinterpret_cast<__half*>(esm + 30720);     // 66560 B
    int* snd   = reinterpret_cast<int*>(esm + 97280);        // 512 B

    const int t = threadIdx.x, lane = t & 31, warp = t >> 5;
    const int n0 = blockIdx.x * NPB;
    const int e0 = n0 * DEG;
    const uint32_t sWa = smem_u32(sW), sEa = smem_u32(sE);

    // stage W (pre-converted fp16 global, contiguous uint4 copy)
    {
        const uint4* src = reinterpret_cast<const uint4*>(gWe);
        #pragma unroll
        for (int s = 0; s < 4; s++) {
            int i = t + s * 256;
            int n = i >> 2, kq = i & 3;
            *reinterpret_cast<uint4*>(sW + n * 40 + kq * 8) = src[i];
        }
    }
    // stage ef fp16
    #pragma unroll
    for (int s = 0; s < 4; s++) {
        int j4 = t + s * 256;
        int row = j4 >> 3, k4 = (j4 & 7) * 4;
        float4 v = *reinterpret_cast<const float4*>(&edge_feat[(size_t)e0 * EDIM + j4 * 4]);
        *reinterpret_cast<__half2*>(sE + row * 40 + k4)     = __floats2half2_rn(v.x, v.y);
        *reinterpret_cast<__half2*>(sE + row * 40 + k4 + 2) = __floats2half2_rn(v.z, v.w);
    }
    if (t < 128) snd[t] = senders[e0 + t];
    __syncthreads();

    // ---- phase A: MMA projection -> EP ----
    {
        uint32_t af[2][4];
        int ar = lane & 15, as_ = (lane >> 4) * 8;
        #pragma unroll
        for (int kt = 0; kt < 2; kt++) {
            uint32_t off = (uint32_t)((warp * 16 + ar) * 40 + kt * 16 + as_) * 2;
            ldsm4(af[kt][0], af[kt][1], af[kt][2], af[kt][3], sEa + off);
        }
        int sel = lane >> 3, ii = lane & 7;
        int g = lane >> 2, cq = (lane & 3) * 2;
        int ebase = warp * 16 + g;
        #pragma unroll
        for (int p = 0; p < 16; p++) {
            uint32_t bh0[4], bh1[4];
            uint32_t brow = (uint32_t)(p * 16 + ((sel >> 1) << 3) + ii) * 40 + ((sel & 1) << 3);
            ldsm4(bh0[0], bh0[1], bh0[2], bh0[3], sWa + brow * 2);
            ldsm4(bh1[0], bh1[1], bh1[2], bh1[3], sWa + (brow + 16) * 2);
            #pragma unroll
            for (int q = 0; q < 2; q++) {
                float c4[4] = {0.f, 0.f, 0.f, 0.f};
                mma16816(c4, af[0], &bh0[2 * q]);
                mma16816(c4, af[1], &bh1[2 * q]);
                int ch = p * 16 + q * 8 + cq;
                *reinterpret_cast<__half2*>(EP + ebase * 260 + ch) =
                    __floats2half2_rn(c4[0], c4[1]);
                *reinterpret_cast<__half2*>(EP + (ebase + 8) * 260 + ch) =
                    __floats2half2_rn(c4[2], c4[3]);
            }
        }
    }
    __syncthreads();

    // ---- phase B: proven scalar tail ----
    const float b1 = be1[t];
    for (int ni = 0; ni < NPB; ni++) {
        const int n = n0 + ni;
        const float pr = g_P[(size_t)n * 512 + 256 + t] + b1;

        float fv[DEG];
        #pragma unroll
        for (int e = 0; e < DEG; e++)
            fv[e] = g_P[(size_t)snd[ni * DEG + e] * 512 + t];

        float sacc = 0.f;
        #pragma unroll
        for (int e = 0; e < DEG; e++) {
            float ep = __half2float(EP[(ni * 16 + e) * 260 + t]);
            sacc += swishf(pr + fv[e] + ep);
        }
        __half h = __float2half_rn(sacc);
        g_Sh[(size_t)n * 256 + t] = h;
        g_Sl[(size_t)n * 256 + t] = __float2half_rn(sacc - __half2float(h));
    }
}

// ============================================================================
extern "C" void kernel_launch(void* const* d_in, const int* in_sizes, int n_in,
                              void* d_out, int out_size)
{
    const float* node_inp  = (const float*)d_in[0];
    const float* edge_feat = (const float*)d_in[1];
    const float* node_mask = (const float*)d_in[2];
    const float* We1       = (const float*)d_in[3];
    const float* be1       = (const float*)d_in[4];
    const float* We2       = (const float*)d_in[5];
    const float* be2       = (const float*)d_in[6];
    const float* g_msg     = (const float*)d_in[7];
    const float* b_msg     = (const float*)d_in[8];
    const float* Wn1       = (const float*)d_in[9];
    const float* bn1       = (const float*)d_in[10];
    const float* Wn2       = (const float*)d_in[11];
    const float* bn2       = (const float*)d_in[12];
    const float* g_node    = (const float*)d_in[13];
    const float* b_node    = (const float*)d_in[14];
    const int*   senders   = (const int*)d_in[15];
    float* out = (float*)d_out;

    float* Pp;
    __half *NAh, *NAl, *Sh, *Sl, *Uh, *Ul, *Wep;
    cudaGetSymbolAddress((void**)&Pp,  g_P);
    cudaGetSymbolAddress((void**)&NAh, g_NAh);
    cudaGetSymbolAddress((void**)&NAl, g_NAl);
    cudaGetSymbolAddress((void**)&Sh,  g_Sh);
    cudaGetSymbolAddress((void**)&Sl,  g_Sl);
    cudaGetSymbolAddress((void**)&Uh,  g_Uh);
    cudaGetSymbolAddress((void**)&Ul,  g_Ul);
    cudaGetSymbolAddress((void**)&Wep, g_We);

    const int SMEMT = 67584;
    const int SMEME = 97792;
    cudaFuncSetAttribute(mma_gemm<128,0>, cudaFuncAttributeMaxDynamicSharedMemorySize, SMEMT);
    cudaFuncSetAttribute(mma_gemm<256,1>, cudaFuncAttributeMaxDynamicSharedMemorySize, SMEMT);
    cudaFuncSetAttribute(mma_gemm<256,2>, cudaFuncAttributeMaxDynamicSharedMemorySize, SMEMT);
    cudaFuncSetAttribute(mma_gemm<256,3>, cudaFuncAttributeMaxDynamicSharedMemorySize, SMEMT);
    cudaFuncSetAttribute(edge_kernel,     cudaFuncAttributeMaxDynamicSharedMemorySize, SMEME);

    __half* Whp;
    cudaGetSymbolAddress((void**)&Whp, g_Wh);

    // launches 0..2: weight prep (3 kernels so edge_kernel is launch index 5)
    wprepA<<<256, 256>>>(We1);
    wprepB<<<384, 256>>>(We2, Wn1);
    wprepC<<<160, 256>>>(Wn2, We1);
    // launch 3
    conv_node<<<NN / 4, 256>>>(node_inp);

    // launch 4: P = node_inp @ [We1_s | We1_r] -> g_P fp32 [N,512]
    mma_gemm<128,0><<<dim3(GX, 4), 256, SMEMT>>>(
        NAh, NAl, Whp,
        nullptr, 1.0f, nullptr, nullptr, nullptr, nullptr, Pp, 512, nullptr, nullptr, 0);

    // launch 5: edge kernel (HMMA projection + swish segment sum)
    edge_kernel<<<NN / NPB, 256, SMEME>>>(edge_feat, senders, Wep, be1);

    // launch 6: agg = LN(S @ We2 /16 + be2)*mask -> g_NA cols 128..255
    mma_gemm<256,1><<<dim3(GX, 1), 256, SMEMT>>>(
        Sh, Sl, Whp + 65536,
        be2, 1.0f / 16.0f, g_msg, b_msg, node_mask, nullptr, nullptr, 0, NAh, NAl, 128);

    // launch 7: U = swish(NA @ Wn1 + bn1) -> g_U
    mma_gemm<256,2><<<dim3(GX, 2), 256, SMEMT>>>(
        NAh, NAl, Whp + 98304,
        bn1, 1.0f, nullptr, nullptr, nullptr, nullptr, nullptr, 0, Uh, Ul, 0);

    // launch 8: out = LN(node_inp + U @ Wn2 + bn2)*mask -> fp32 out
    mma_gemm<256,3><<<dim3(GX, 1), 256, SMEMT>>>(
        Uh, Ul, Whp + 163840,
        bn2, 1.0f, g_node, b_node, node_mask, node_inp, out, 128, nullptr, nullptr, 0);
}

// round 13
// speedup vs baseline: 2.0785x; 1.0180x over previous
#include <cuda_runtime.h>
#include <cuda_fp16.h>
#include <cstdint>

#define NN   50000
#define NP   50048     // 391*128 padded rows
#define DEG  16
#define DIM  128
#define EDIM 32
#define HDIM 256
#define NPB  8
#define GX   391

typedef unsigned long long u64;

// ---- scratch (device globals; no allocation allowed) ----
__device__ __half g_Psh[(size_t)NN * 256];       // sender projections, fp16 (L2-resident gathers)
__device__ float  g_Pr[(size_t)NN * 256];        // receiver projections, fp32 (sequential)
__device__ __half g_NAh[(size_t)NP * 256];       // cols 0-127 node_inp, 128-255 AGG (hi)
__device__ __half g_NAl[(size_t)NP * 256];       // (activation residual)
__device__ __half g_Sh[(size_t)NP * 256];        // edge-sum S
__device__ __half g_Sl[(size_t)NP * 256];
__device__ __half g_Uh[(size_t)NP * 256];        // node-MLP hidden U
__device__ __half g_Ul[(size_t)NP * 256];
__device__ __half g_Wh[196608];                  // GEMM weights, [n][K] per region
__device__ __half g_We[8192];                    // edge-proj weights [256 ch][32 k] fp16

// single-MUFU swish: v*sigmoid(v) = 0.5*v*(1+tanh(0.5*v))  (r9-validated accuracy)
__device__ __forceinline__ float swishf(float v) {
    float th;
    asm("tanh.approx.f32 %0, %1;" : "=f"(th) : "f"(0.5f * v));
    return 0.5f * v * (1.0f + th);
}
__device__ __forceinline__ uint32_t smem_u32(const void* p) {
    uint32_t a;
    asm("{ .reg .u64 t; cvta.to.shared.u64 t, %1; cvt.u32.u64 %0, t; }" : "=r"(a) : "l"(p));
    return a;
}
__device__ __forceinline__ void ldsm4(uint32_t& r0, uint32_t& r1, uint32_t& r2,
                                      uint32_t& r3, uint32_t addr) {
    asm volatile("ldmatrix.sync.aligned.m8n8.x4.shared.b16 {%0,%1,%2,%3}, [%4];"
                 : "=r"(r0), "=r"(r1), "=r"(r2), "=r"(r3) : "r"(addr));
}
__device__ __forceinline__ void mma16816(float* c, const uint32_t* a, const uint32_t* b) {
    asm volatile("mma.sync.aligned.m16n8k16.row.col.f32.f16.f16.f32 "
                 "{%0,%1,%2,%3}, {%4,%5,%6,%7}, {%8,%9}, {%0,%1,%2,%3};"
                 : "+f"(c[0]), "+f"(c[1]), "+f"(c[2]), "+f"(c[3])
                 : "r"(a[0]), "r"(a[1]), "r"(a[2]), "r"(a[3]), "r"(b[0]), "r"(b[1]));
}
__device__ __forceinline__ void cp_async16(uint32_t dst, const void* src, int src_bytes) {
    asm volatile("cp.async.cg.shared.global [%0], [%1], 16, %2;"
                 :: "r"(dst), "l"(src), "r"(src_bytes) : "memory");
}
__device__ __forceinline__ void cp_commit() {
    asm volatile("cp.async.commit_group;" ::: "memory");
}
__device__ __forceinline__ void split_store(__half* dh, __half* dl,
                                            size_t pos, float v0, float v1) {
    __half h0 = __float2half_rn(v0), h1 = __float2half_rn(v1);
    __half2 hp; hp.x = h0; hp.y = h1;
    *reinterpret_cast<__half2*>(&dh[pos]) = hp;
    __half2 lp;
    lp.x = __float2half_rn(v0 - __half2float(h0));
    lp.y = __float2half_rn(v1 - __half2float(h1));
    *reinterpret_cast<__half2*>(&dl[pos]) = lp;
}

// ============================================================================
// prep kernels
// ============================================================================
__global__ void conv_node(const float* __restrict__ x) {
    int t = threadIdx.x;
    int row = blockIdx.x * 4 + (t >> 6);
    int c = (t & 63) * 2;
    float2 v = *reinterpret_cast<const float2*>(&x[(size_t)row * 128 + c]);
    split_store(g_NAh, g_NAl, (size_t)row * 256 + c, v.x, v.y);
}
__global__ void wprepA(const float* __restrict__ We1) {      // 65536 elems
    int idx = blockIdx.x * 256 + threadIdx.x;
    int local = idx & 32767, region = idx >> 15;
    int n = local >> 7, k = local & 127;
    g_Wh[idx] = __float2half_rn(We1[(size_t)(region * 128 + k) * 256 + n]);
}
__global__ void wprepB(const float* __restrict__ We2, const float* __restrict__ Wn1) {
    int idx = blockIdx.x * 256 + threadIdx.x;                // 98304 elems
    if (idx < 32768) {
        int n = idx >> 8, k = idx & 255;
        g_Wh[65536 + idx] = __float2half_rn(We2[(size_t)k * 128 + n]);
    } else {
        int j = idx - 32768, n = j >> 8, k = j & 255;
        g_Wh[98304 + j] = __float2half_rn(Wn1[(size_t)k * 256 + n]);
    }
}
__global__ void wprepC(const float* __restrict__ Wn2, const float* __restrict__ We1) {
    int idx = blockIdx.x * 256 + threadIdx.x;                // 40960 elems
    if (idx < 32768) {
        int n = idx >> 8, k = idx & 255;
        g_Wh[163840 + idx] = __float2half_rn(Wn2[(size_t)k * 128 + n]);
    } else {
        int j = idx - 32768, n = j >> 5, k = j & 31;
        g_We[j] = __float2half_rn(We1[(size_t)(256 + k) * 256 + n]);
    }
}

// ============================================================================
// 2-term fp16 HMMA GEMM, cp.async double-buffered (proven structure).
//   MODE 0: P store -> by 0,1: Ps fp16 (oBh); by 2,3: Pr fp32 (outF)
//   MODE 1: v=acc*scale+bias; LN*mask -> split fp16 g_NA cols 128..255
//   MODE 2: v=swish(acc+bias)        -> split fp16 oB cols by*128..
//   MODE 3: v=acc+bias+resid; LN*mask -> fp32 out
// ============================================================================
template<int K, int MODE>
__global__ void __launch_bounds__(256, 2) mma_gemm(
    const __half* __restrict__ Ah, const __half* __restrict__ Al,
    const __half* __restrict__ Bh,
    const float* __restrict__ bias, float scale,
    const float* __restrict__ gamma, const float* __restrict__ beta,
    const float* __restrict__ mask, const float* __restrict__ resid,
    float* __restrict__ outF, int ldOut,
    __half* __restrict__ oBh, __half* __restrict__ oBl, int oCol)
{
    extern __shared__ __align__(16) char smem[];
    float* Csm = reinterpret_cast<float*>(smem);             // [128][132] (post-loop)

    const uint32_t sb = smem_u32(smem);
    const int t = threadIdx.x, lane = t & 31, warp = t >> 5;
    const int wm = warp & 3, wn = warp >> 2;
    const int n0 = blockIdx.x * 128, by = blockIdx.y;
    constexpr int NCH = K / 32;
    constexpr uint32_t BUFB = 30720;

    float acc[2][8][4];
    #pragma unroll
    for (int mt = 0; mt < 2; mt++)
        #pragma unroll
        for (int nt = 0; nt < 8; nt++)
            #pragma unroll
            for (int q = 0; q < 4; q++) acc[mt][nt][q] = 0.f;

    const int r0s = t >> 2, g0 = t & 3;

    auto stage = [&](int c, int b) {
        uint32_t base = sb + (uint32_t)b * BUFB;
        #pragma unroll
        for (int s = 0; s < 2; s++) {
            int row = r0s + s * 64;
            int grow = n0 + row;
            int ga = grow < NN ? grow : NN - 1;
            int ok = grow < NN ? 16 : 0;
            uint32_t so = (uint32_t)(row * 40 + g0 * 8) * 2;
            cp_async16(base + so,         &Ah[(size_t)ga * 256 + c * 32 + g0 * 8], ok);
            cp_async16(base + 10240 + so, &Al[(size_t)ga * 256 + c * 32 + g0 * 8], ok);
            cp_async16(base + 20480 + so,
                       &Bh[(size_t)(by * 128 + row) * K + c * 32 + g0 * 8], 16);
        }
        cp_commit();
    };

    stage(0, 0);

    for (int c = 0; c < NCH; c++) {
        const int b = c & 1;
        if (c + 1 < NCH) {
            stage(c + 1, (c + 1) & 1);
            asm volatile("cp.async.wait_group 1;" ::: "memory");
        } else {
            asm volatile("cp.async.wait_group 0;" ::: "memory");
        }
        __syncthreads();

        const uint32_t base = sb + (uint32_t)b * BUFB;
        #pragma unroll
        for (int kt = 0; kt < 32; kt += 16) {
            uint32_t ah[2][4], al[2][4];
            {
                int ar = lane & 15, as_ = (lane >> 4) * 8;
                #pragma unroll
                for (int mt = 0; mt < 2; mt++) {
                    uint32_t off = (uint32_t)((wm * 32 + mt * 16 + ar) * 40 + kt + as_) * 2;
                    ldsm4(ah[mt][0], ah[mt][1], ah[mt][2], ah[mt][3], base + off);
                    ldsm4(al[mt][0], al[mt][1], al[mt][2], al[mt][3], base + 10240 + off);
                }
            }
            #pragma unroll
            for (int p = 0; p < 4; p++) {
                int sel = lane >> 3, i = lane & 7;
                uint32_t boff = (uint32_t)((wn * 64 + p * 16 + ((sel >> 1) << 3) + i) * 40
                                           + kt + ((sel & 1) << 3)) * 2;
                uint32_t bh[4];
                ldsm4(bh[0], bh[1], bh[2], bh[3], base + 20480 + boff);
                #pragma unroll
                for (int mt = 0; mt < 2; mt++)
                    #pragma unroll
                    for (int q = 0; q < 2; q++) {
                        float* cc = acc[mt][2 * p + q];
                        mma16816(cc, ah[mt], &bh[2 * q]);
                        mma16816(cc, al[mt], &bh[2 * q]);
                    }
            }
        }
        __syncthreads();
    }

    {
        int g = lane >> 2, cc = (lane & 3) * 2;
        #pragma unroll
        for (int mt = 0; mt < 2; mt++)
            #pragma unroll
            for (int nt = 0; nt < 8; nt++) {
                int r0 = wm * 32 + mt * 16 + g;
                int col = wn * 64 + nt * 8 + cc;
                *reinterpret_cast<float2*>(&Csm[r0 * 132 + col]) =
                    make_float2(acc[mt][nt][0], acc[mt][nt][1]);
                *reinterpret_cast<float2*>(&Csm[(r0 + 8) * 132 + col]) =
                    make_float2(acc[mt][nt][2], acc[mt][nt][3]);
            }
    }
    __syncthreads();

    const int r = t >> 1, hh = t & 1, ch0 = hh * 64;
    const int row = n0 + r;
    const float* crow = &Csm[r * 132 + ch0];

    if (MODE == 0) {
        if (row < NN) {
            if (by < 2) {
                __half* o = &oBh[(size_t)row * 256 + by * 128 + ch0];
                #pragma unroll
                for (int j = 0; j < 64; j += 2)
                    *reinterpret_cast<__half2*>(&o[j]) =
                        __floats2half2_rn(crow[j], crow[j + 1]);
            } else {
                float* o = &outF[(size_t)row * 256 + (by - 2) * 128 + ch0];
                #pragma unroll
                for (int j = 0; j < 64; j += 4)
                    *reinterpret_cast<float4*>(&o[j]) =
                        *reinterpret_cast<const float4*>(&crow[j]);
            }
        }
        return;
    }
    if (MODE == 2) {
        if (row < NN) {
            #pragma unroll
            for (int j = 0; j < 64; j += 2) {
                int c = by * 128 + ch0 + j;
                float v0 = swishf(crow[j]     + bias[c]);
                float v1 = swishf(crow[j + 1] + bias[c + 1]);
                split_store(oBh, oBl, (size_t)row * 256 + c, v0, v1);
            }
        }
        return;
    }
    {
        float s = 0.f, s2 = 0.f;
        #pragma unroll
        for (int j = 0; j < 64; j += 4) {
            float4 c4 = *reinterpret_cast<const float4*>(&crow[j]);
            float v0 = c4.x * scale + bias[ch0 + j];
            float v1 = c4.y * scale + bias[ch0 + j + 1];
            float v2 = c4.z * scale + bias[ch0 + j + 2];
            float v3 = c4.w * scale + bias[ch0 + j + 3];
            if (MODE == 3 && row < NN) {
                float4 r4 = *reinterpret_cast<const float4*>(&resid[(size_t)row * 128 + ch0 + j]);
                v0 += r4.x; v1 += r4.y; v2 += r4.z; v3 += r4.w;
            }
            s += v0 + v1 + v2 + v3;
            s2 += v0 * v0 + v1 * v1 + v2 * v2 + v3 * v3;
        }
        s  += __shfl_xor_sync(0xffffffffu, s, 1);
        s2 += __shfl_xor_sync(0xffffffffu, s2, 1);
        float m    = s * (1.0f / 128.0f);
        float var  = s2 * (1.0f / 128.0f) - m * m;
        float rstd = rsqrtf(var + 1e-5f);
        if (row < NN) {
            float mk = mask[row];
            #pragma unroll
            for (int j = 0; j < 64; j += 2) {
                int c = ch0 + j;
                float v0 = crow[j]     * scale + bias[c];
                float v1 = crow[j + 1] * scale + bias[c + 1];
                if (MODE == 3) {
                    float2 r2 = *reinterpret_cast<const float2*>(&resid[(size_t)row * 128 + c]);
                    v0 += r2.x; v1 += r2.y;
                }
                float w0 = ((v0 - m) * rstd * gamma[c]     + beta[c])     * mk;
                float w1 = ((v1 - m) * rstd * gamma[c + 1] + beta[c + 1]) * mk;
                if (MODE == 3) {
                    *reinterpret_cast<float2*>(&outF[(size_t)row * 128 + c]) = make_float2(w0, w1);
                } else {
                    split_store(oBh, oBl, (size_t)row * 256 + oCol + c, w0, w1);
                }
            }
        }
    }
}

// ============================================================================
// Edge kernel (r12 proven structure; fp16 Ps gathers + 1-MUFU swish):
//   Phase A: EP[128 edge][256 ch] = ef @ We1_edge  (fp16 MMA -> smem)
//   Phase B: S[n] = sum_e swish(Ps[snd]+Pr[n]+EP[e]+be1)
// ============================================================================
__global__ void __launch_bounds__(256, 2) edge_kernel(
    const float* __restrict__ edge_feat, const int* __restrict__ senders,
    const __half* __restrict__ gWe, const float* __restrict__ be1)
{
    extern __shared__ __align__(16) char esm[];
    __half* sW = reinterpret_cast<__half*>(esm);             // 20480 B
    __half* sE = reinterpret_cast<__half*>(esm + 20480);     // 10240 B
    __half* EP = reinterpret_cast<__half*>(esm + 30720);     // 66560 B
    int* snd   = reinterpret_cast<int*>(esm + 97280);        // 512 B

    const int t = threadIdx.x, lane = t & 31, warp = t >> 5;
    const int n0 = blockIdx.x * NPB;
    const int e0 = n0 * DEG;
    const uint32_t sWa = smem_u32(sW), sEa = smem_u32(sE);

    {
        const uint4* src = reinterpret_cast<const uint4*>(gWe);
        #pragma unroll
        for (int s = 0; s < 4; s++) {
            int i = t + s * 256;
            int n = i >> 2, kq = i & 3;
            *reinterpret_cast<uint4*>(sW + n * 40 + kq * 8) = src[i];
        }
    }
    #pragma unroll
    for (int s = 0; s < 4; s++) {
        int j4 = t + s * 256;
        int row = j4 >> 3, k4 = (j4 & 7) * 4;
        float4 v = *reinterpret_cast<const float4*>(&edge_feat[(size_t)e0 * EDIM + j4 * 4]);
        *reinterpret_cast<__half2*>(sE + row * 40 + k4)     = __floats2half2_rn(v.x, v.y);
        *reinterpret_cast<__half2*>(sE + row * 40 + k4 + 2) = __floats2half2_rn(v.z, v.w);
    }
    if (t < 128) snd[t] = senders[e0 + t];
    __syncthreads();

    // ---- phase A: MMA projection -> EP ----
    {
        uint32_t af[2][4];
        int ar = lane & 15, as_ = (lane >> 4) * 8;
        #pragma unroll
        for (int kt = 0; kt < 2; kt++) {
            uint32_t off = (uint32_t)((warp * 16 + ar) * 40 + kt * 16 + as_) * 2;
            ldsm4(af[kt][0], af[kt][1], af[kt][2], af[kt][3], sEa + off);
        }
        int sel = lane >> 3, ii = lane & 7;
        int g = lane >> 2, cq = (lane & 3) * 2;
        int ebase = warp * 16 + g;
        #pragma unroll
        for (int p = 0; p < 16; p++) {
            uint32_t bh0[4], bh1[4];
            uint32_t brow = (uint32_t)(p * 16 + ((sel >> 1) << 3) + ii) * 40 + ((sel & 1) << 3);
            ldsm4(bh0[0], bh0[1], bh0[2], bh0[3], sWa + brow * 2);
            ldsm4(bh1[0], bh1[1], bh1[2], bh1[3], sWa + (brow + 16) * 2);
            #pragma unroll
            for (int q = 0; q < 2; q++) {
                float c4[4] = {0.f, 0.f, 0.f, 0.f};
                mma16816(c4, af[0], &bh0[2 * q]);
                mma16816(c4, af[1], &bh1[2 * q]);
                int ch = p * 16 + q * 8 + cq;
                *reinterpret_cast<__half2*>(EP + ebase * 260 + ch) =
                    __floats2half2_rn(c4[0], c4[1]);
                *reinterpret_cast<__half2*>(EP + (ebase + 8) * 260 + ch) =
                    __floats2half2_rn(c4[2], c4[3]);
            }
        }
    }
    __syncthreads();

    // ---- phase B: scalar tail (fp16 Ps gathers, 1-MUFU swish) ----
    const float b1 = be1[t];
    for (int ni = 0; ni < NPB; ni++) {
        const int n = n0 + ni;
        const float pr = g_Pr[(size_t)n * 256 + t] + b1;

        float fv[DEG];
        #pragma unroll
        for (int e = 0; e < DEG; e++)
            fv[e] = __half2float(g_Psh[(size_t)snd[ni * DEG + e] * 256 + t]);

        float sacc = 0.f;
        #pragma unroll
        for (int e = 0; e < DEG; e++) {
            float ep = __half2float(EP[(ni * 16 + e) * 260 + t]);
            sacc += swishf(pr + fv[e] + ep);
        }
        __half h = __float2half_rn(sacc);
        g_Sh[(size_t)n * 256 + t] = h;
        g_Sl[(size_t)n * 256 + t] = __float2half_rn(sacc - __half2float(h));
    }
}

// ============================================================================
extern "C" void kernel_launch(void* const* d_in, const int* in_sizes, int n_in,
                              void* d_out, int out_size)
{
    const float* node_inp  = (const float*)d_in[0];
    const float* edge_feat = (const float*)d_in[1];
    const float* node_mask = (const float*)d_in[2];
    const float* We1       = (const float*)d_in[3];
    const float* be1       = (const float*)d_in[4];
    const float* We2       = (const float*)d_in[5];
    const float* be2       = (const float*)d_in[6];
    const float* g_msg     = (const float*)d_in[7];
    const float* b_msg     = (const float*)d_in[8];
    const float* Wn1       = (const float*)d_in[9];
    const float* bn1       = (const float*)d_in[10];
    const float* Wn2       = (const float*)d_in[11];
    const float* bn2       = (const float*)d_in[12];
    const float* g_node    = (const float*)d_in[13];
    const float* b_node    = (const float*)d_in[14];
    const int*   senders   = (const int*)d_in[15];
    float* out = (float*)d_out;

    float* Prp;
    __half *Pshp, *NAh, *NAl, *Sh, *Sl, *Uh, *Ul, *Wep, *Whp;
    cudaGetSymbolAddress((void**)&Prp,  g_Pr);
    cudaGetSymbolAddress((void**)&Pshp, g_Psh);
    cudaGetSymbolAddress((void**)&NAh,  g_NAh);
    cudaGetSymbolAddress((void**)&NAl,  g_NAl);
    cudaGetSymbolAddress((void**)&Sh,   g_Sh);
    cudaGetSymbolAddress((void**)&Sl,   g_Sl);
    cudaGetSymbolAddress((void**)&Uh,   g_Uh);
    cudaGetSymbolAddress((void**)&Ul,   g_Ul);
    cudaGetSymbolAddress((void**)&Wep,  g_We);
    cudaGetSymbolAddress((void**)&Whp,  g_Wh);

    const int SMEMT = 67584;
    const int SMEME = 97792;
    cudaFuncSetAttribute(mma_gemm<128,0>, cudaFuncAttributeMaxDynamicSharedMemorySize, SMEMT);
    cudaFuncSetAttribute(mma_gemm<256,1>, cudaFuncAttributeMaxDynamicSharedMemorySize, SMEMT);
    cudaFuncSetAttribute(mma_gemm<256,2>, cudaFuncAttributeMaxDynamicSharedMemorySize, SMEMT);
    cudaFuncSetAttribute(mma_gemm<256,3>, cudaFuncAttributeMaxDynamicSharedMemorySize, SMEMT);
    cudaFuncSetAttribute(edge_kernel,     cudaFuncAttributeMaxDynamicSharedMemorySize, SMEME);

    wprepA<<<256, 256>>>(We1);
    wprepB<<<384, 256>>>(We2, Wn1);
    wprepC<<<160, 256>>>(Wn2, We1);
    conv_node<<<NN / 4, 256>>>(node_inp);

    // P: by 0,1 -> Ps fp16; by 2,3 -> Pr fp32
    mma_gemm<128,0><<<dim3(GX, 4), 256, SMEMT>>>(
        NAh, NAl, Whp,
        nullptr, 1.0f, nullptr, nullptr, nullptr, nullptr, Prp, 0, Pshp, nullptr, 0);

    edge_kernel<<<NN / NPB, 256, SMEME>>>(edge_feat, senders, Wep, be1);

    mma_gemm<256,1><<<dim3(GX, 1), 256, SMEMT>>>(
        Sh, Sl, Whp + 65536,
        be2, 1.0f / 16.0f, g_msg, b_msg, node_mask, nullptr, nullptr, 0, NAh, NAl, 128);

    mma_gemm<256,2><<<dim3(GX, 2), 256, SMEMT>>>(
        NAh, NAl, Whp + 98304,
        bn1, 1.0f, nullptr, nullptr, nullptr, nullptr, nullptr, 0, Uh, Ul, 0);

    mma_gemm<256,3><<<dim3(GX, 1), 256, SMEMT>>>(
        Uh, Ul, Whp + 163840,
        bn2, 1.0f, g_node, b_node, node_mask, node_inp, out, 128, nullptr, nullptr, 0);
}

// round 14
// speedup vs baseline: 2.5402x; 1.2222x over previous
#include <cuda_runtime.h>
#include <cuda_fp16.h>
#include <cstdint>

#define NN   50000
#define NP   50048     // 391*128 padded rows
#define DEG  16
#define DIM  128
#define EDIM 32
#define HDIM 256
#define NPB  8
#define GX   391

typedef unsigned long long u64;

// ---- scratch (device globals; no allocation allowed) ----
__device__ __half g_Psh[(size_t)NN * 256];       // sender projections, fp16 (L2-resident gathers)
__device__ float  g_Pr[(size_t)NN * 256];        // receiver projections, fp32 (sequential)
__device__ __half g_NA[(size_t)NP * 256];        // cols 0-127 node_inp, 128-255 AGG (fp16)
__device__ __half g_S[(size_t)NP * 256];         // edge-sum S (fp16)
__device__ __half g_U[(size_t)NP * 256];         // node-MLP hidden U (fp16)
__device__ __half g_Wh[196608];                  // GEMM weights, [n][K] per region
__device__ __half g_We[8192];                    // edge-proj weights [256 ch][32 k] fp16

// single-MUFU swish: v*sigmoid(v) = 0.5*v*(1+tanh(0.5*v))  (r9/r13-validated accuracy)
__device__ __forceinline__ float swishf(float v) {
    float th;
    asm("tanh.approx.f32 %0, %1;" : "=f"(th) : "f"(0.5f * v));
    return 0.5f * v * (1.0f + th);
}
__device__ __forceinline__ uint32_t smem_u32(const void* p) {
    uint32_t a;
    asm("{ .reg .u64 t; cvta.to.shared.u64 t, %1; cvt.u32.u64 %0, t; }" : "=r"(a) : "l"(p));
    return a;
}
__device__ __forceinline__ void ldsm4(uint32_t& r0, uint32_t& r1, uint32_t& r2,
                                      uint32_t& r3, uint32_t addr) {
    asm volatile("ldmatrix.sync.aligned.m8n8.x4.shared.b16 {%0,%1,%2,%3}, [%4];"
                 : "=r"(r0), "=r"(r1), "=r"(r2), "=r"(r3) : "r"(addr));
}
__device__ __forceinline__ void mma16816(float* c, const uint32_t* a, const uint32_t* b) {
    asm volatile("mma.sync.aligned.m16n8k16.row.col.f32.f16.f16.f32 "
                 "{%0,%1,%2,%3}, {%4,%5,%6,%7}, {%8,%9}, {%0,%1,%2,%3};"
                 : "+f"(c[0]), "+f"(c[1]), "+f"(c[2]), "+f"(c[3])
                 : "r"(a[0]), "r"(a[1]), "r"(a[2]), "r"(a[3]), "r"(b[0]), "r"(b[1]));
}
__device__ __forceinline__ void cp_async16(uint32_t dst, const void* src, int src_bytes) {
    asm volatile("cp.async.cg.shared.global [%0], [%1], 16, %2;"
                 :: "r"(dst), "l"(src), "r"(src_bytes) : "memory");
}
__device__ __forceinline__ void cp_commit() {
    asm volatile("cp.async.commit_group;" ::: "memory");
}

// ============================================================================
// prep kernels
// ============================================================================
__global__ void conv_node(const float* __restrict__ x) {
    int t = threadIdx.x;
    int row = blockIdx.x * 4 + (t >> 6);
    int c = (t & 63) * 2;
    float2 v = *reinterpret_cast<const float2*>(&x[(size_t)row * 128 + c]);
    *reinterpret_cast<__half2*>(&g_NA[(size_t)row * 256 + c]) = __floats2half2_rn(v.x, v.y);
}
__global__ void wprepA(const float* __restrict__ We1) {      // 65536 elems
    int idx = blockIdx.x * 256 + threadIdx.x;
    int local = idx & 32767, region = idx >> 15;
    int n = local >> 7, k = local & 127;
    g_Wh[idx] = __float2half_rn(We1[(size_t)(region * 128 + k) * 256 + n]);
}
__global__ void wprepB(const float* __restrict__ We2, const float* __restrict__ Wn1) {
    int idx = blockIdx.x * 256 + threadIdx.x;                // 98304 elems
    if (idx < 32768) {
        int n = idx >> 8, k = idx & 255;
        g_Wh[65536 + idx] = __float2half_rn(We2[(size_t)k * 128 + n]);
    } else {
        int j = idx - 32768, n = j >> 8, k = j & 255;
        g_Wh[98304 + j] = __float2half_rn(Wn1[(size_t)k * 256 + n]);
    }
}
__global__ void wprepC(const float* __restrict__ Wn2, const float* __restrict__ We1) {
    int idx = blockIdx.x * 256 + threadIdx.x;                // 40960 elems
    if (idx < 32768) {
        int n = idx >> 8, k = idx & 255;
        g_Wh[163840 + idx] = __float2half_rn(Wn2[(size_t)k * 128 + n]);
    } else {
        int j = idx - 32768, n = j >> 5, k = j & 31;
        g_We[j] = __float2half_rn(We1[(size_t)(256 + k) * 256 + n]);
    }
}

// ============================================================================
// 1-term fp16 HMMA GEMM, cp.async double-buffered.
//   C = A @ B.  M-tile 128, N-tile 128, BK=32.
//   MODE 0: P store -> by 0,1: Ps fp16 (oB); by 2,3: Pr fp32 (outF)
//   MODE 1: v=acc*scale+bias; LN*mask -> fp16 g_NA cols 128..255
//   MODE 2: v=swish(acc+bias)        -> fp16 oB cols by*128..
//   MODE 3: v=acc+bias+resid; LN*mask -> fp32 out
// Smem: buf[2] x (sA 10240B | sB 10240B) = 40960B; Csm [128][132] overlays.
// ============================================================================
template<int K, int MODE>
__global__ void __launch_bounds__(256, 2) mma_gemm(
    const __half* __restrict__ A, const __half* __restrict__ B,
    const float* __restrict__ bias, float scale,
    const float* __restrict__ gamma, const float* __restrict__ beta,
    const float* __restrict__ mask, const float* __restrict__ resid,
    float* __restrict__ outF,
    __half* __restrict__ oB, int oCol)
{
    extern __shared__ __align__(16) char smem[];
    float* Csm = reinterpret_cast<float*>(smem);             // [128][132] (post-loop)

    const uint32_t sb = smem_u32(smem);
    const int t = threadIdx.x, lane = t & 31, warp = t >> 5;
    const int wm = warp & 3, wn = warp >> 2;
    const int n0 = blockIdx.x * 128, by = blockIdx.y;
    constexpr int NCH = K / 32;
    constexpr uint32_t BUFB = 20480;

    float acc[2][8][4];
    #pragma unroll
    for (int mt = 0; mt < 2; mt++)
        #pragma unroll
        for (int nt = 0; nt < 8; nt++)
            #pragma unroll
            for (int q = 0; q < 4; q++) acc[mt][nt][q] = 0.f;

    const int r0s = t >> 2, g0 = t & 3;

    auto stage = [&](int c, int b) {
        uint32_t base = sb + (uint32_t)b * BUFB;
        #pragma unroll
        for (int s = 0; s < 2; s++) {
            int row = r0s + s * 64;
            int grow = n0 + row;
            int ga = grow < NN ? grow : NN - 1;
            int ok = grow < NN ? 16 : 0;
            uint32_t so = (uint32_t)(row * 40 + g0 * 8) * 2;
            cp_async16(base + so,         &A[(size_t)ga * 256 + c * 32 + g0 * 8], ok);
            cp_async16(base + 10240 + so,
                       &B[(size_t)(by * 128 + row) * K + c * 32 + g0 * 8], 16);
        }
        cp_commit();
    };

    stage(0, 0);

    for (int c = 0; c < NCH; c++) {
        const int b = c & 1;
        if (c + 1 < NCH) {
            stage(c + 1, (c + 1) & 1);
            asm volatile("cp.async.wait_group 1;" ::: "memory");
        } else {
            asm volatile("cp.async.wait_group 0;" ::: "memory");
        }
        __syncthreads();

        const uint32_t base = sb + (uint32_t)b * BUFB;
        #pragma unroll
        for (int kt = 0; kt < 32; kt += 16) {
            uint32_t ah[2][4];
            {
                int ar = lane & 15, as_ = (lane >> 4) * 8;
                #pragma unroll
                for (int mt = 0; mt < 2; mt++) {
                    uint32_t off = (uint32_t)((wm * 32 + mt * 16 + ar) * 40 + kt + as_) * 2;
                    ldsm4(ah[mt][0], ah[mt][1], ah[mt][2], ah[mt][3], base + off);
                }
            }
            #pragma unroll
            for (int p = 0; p < 4; p++) {
                int sel = lane >> 3, i = lane & 7;
                uint32_t boff = (uint32_t)((wn * 64 + p * 16 + ((sel >> 1) << 3) + i) * 40
                                           + kt + ((sel & 1) << 3)) * 2;
                uint32_t bh[4];
                ldsm4(bh[0], bh[1], bh[2], bh[3], base + 10240 + boff);
                #pragma unroll
                for (int mt = 0; mt < 2; mt++)
                    #pragma unroll
                    for (int q = 0; q < 2; q++)
                        mma16816(acc[mt][2 * p + q], ah[mt], &bh[2 * q]);
            }
        }
        __syncthreads();
    }

    {
        int g = lane >> 2, cc = (lane & 3) * 2;
        #pragma unroll
        for (int mt = 0; mt < 2; mt++)
            #pragma unroll
            for (int nt = 0; nt < 8; nt++) {
                int r0 = wm * 32 + mt * 16 + g;
                int col = wn * 64 + nt * 8 + cc;
                *reinterpret_cast<float2*>(&Csm[r0 * 132 + col]) =
                    make_float2(acc[mt][nt][0], acc[mt][nt][1]);
                *reinterpret_cast<float2*>(&Csm[(r0 + 8) * 132 + col]) =
                    make_float2(acc[mt][nt][2], acc[mt][nt][3]);
            }
    }
    __syncthreads();

    const int r = t >> 1, hh = t & 1, ch0 = hh * 64;
    const int row = n0 + r;
    const float* crow = &Csm[r * 132 + ch0];

    if (MODE == 0) {
        if (row < NN) {
            if (by < 2) {
                __half* o = &oB[(size_t)row * 256 + by * 128 + ch0];
                #pragma unroll
                for (int j = 0; j < 64; j += 2)
                    *reinterpret_cast<__half2*>(&o[j]) =
                        __floats2half2_rn(crow[j], crow[j + 1]);
            } else {
                float* o = &outF[(size_t)row * 256 + (by - 2) * 128 + ch0];
                #pragma unroll
                for (int j = 0; j < 64; j += 4)
                    *reinterpret_cast<float4*>(&o[j]) =
                        *reinterpret_cast<const float4*>(&crow[j]);
            }
        }
        return;
    }
    if (MODE == 2) {
        if (row < NN) {
            __half* o = &oB[(size_t)row * 256 + by * 128 + ch0];
            #pragma unroll
            for (int j = 0; j < 64; j += 2) {
                int c = by * 128 + ch0 + j;
                float v0 = swishf(crow[j]     + bias[c]);
                float v1 = swishf(crow[j + 1] + bias[c + 1]);
                *reinterpret_cast<__half2*>(&o[j]) = __floats2half2_rn(v0, v1);
            }
        }
        return;
    }
    {
        float s = 0.f, s2 = 0.f;
        #pragma unroll
        for (int j = 0; j < 64; j += 4) {
            float4 c4 = *reinterpret_cast<const float4*>(&crow[j]);
            float v0 = c4.x * scale + bias[ch0 + j];
            float v1 = c4.y * scale + bias[ch0 + j + 1];
            float v2 = c4.z * scale + bias[ch0 + j + 2];
            float v3 = c4.w * scale + bias[ch0 + j + 3];
            if (MODE == 3 && row < NN) {
                float4 r4 = *reinterpret_cast<const float4*>(&resid[(size_t)row * 128 + ch0 + j]);
                v0 += r4.x; v1 += r4.y; v2 += r4.z; v3 += r4.w;
            }
            s += v0 + v1 + v2 + v3;
            s2 += v0 * v0 + v1 * v1 + v2 * v2 + v3 * v3;
        }
        s  += __shfl_xor_sync(0xffffffffu, s, 1);
        s2 += __shfl_xor_sync(0xffffffffu, s2, 1);
        float m    = s * (1.0f / 128.0f);
        float var  = s2 * (1.0f / 128.0f) - m * m;
        float rstd = rsqrtf(var + 1e-5f);
        if (row < NN) {
            float mk = mask[row];
            #pragma unroll
            for (int j = 0; j < 64; j += 2) {
                int c = ch0 + j;
                float v0 = crow[j]     * scale + bias[c];
                float v1 = crow[j + 1] * scale + bias[c + 1];
                if (MODE == 3) {
                    float2 r2 = *reinterpret_cast<const float2*>(&resid[(size_t)row * 128 + c]);
                    v0 += r2.x; v1 += r2.y;
                }
                float w0 = ((v0 - m) * rstd * gamma[c]     + beta[c])     * mk;
                float w1 = ((v1 - m) * rstd * gamma[c + 1] + beta[c + 1]) * mk;
                if (MODE == 3) {
                    *reinterpret_cast<float2*>(&outF[(size_t)row * 128 + c]) = make_float2(w0, w1);
                } else {
                    *reinterpret_cast<__half2*>(&oB[(size_t)row * 256 + oCol + c]) =
                        __floats2half2_rn(w0, w1);
                }
            }
        }
    }
}

// ============================================================================
// Edge kernel (r12/r13 proven structure; S out fp16):
//   Phase A: EP[128 edge][256 ch] = ef @ We1_edge  (fp16 MMA -> smem)
//   Phase B: S[n] = sum_e swish(Ps[snd]+Pr[n]+EP[e]+be1)
// ============================================================================
__global__ void __launch_bounds__(256, 2) edge_kernel(
    const float* __restrict__ edge_feat, const int* __restrict__ senders,
    const __half* __restrict__ gWe, const float* __restrict__ be1)
{
    extern __shared__ __align__(16) char esm[];
    __half* sW = reinterpret_cast<__half*>(esm);             // 20480 B
    __half* sE = reinterpret_cast<__half*>(esm + 20480);     // 10240 B
    __half* EP = reinterpret_cast<__half*>(esm + 30720);     // 66560 B
    int* snd   = reinterpret_cast<int*>(esm + 97280);        // 512 B

    const int t = threadIdx.x, lane = t & 31, warp = t >> 5;
    const int n0 = blockIdx.x * NPB;
    const int e0 = n0 * DEG;
    const uint32_t sWa = smem_u32(sW), sEa = smem_u32(sE);

    {
        const uint4* src = reinterpret_cast<const uint4*>(gWe);
        #pragma unroll
        for (int s = 0; s < 4; s++) {
            int i = t + s * 256;
            int n = i >> 2, kq = i & 3;
            *reinterpret_cast<uint4*>(sW + n * 40 + kq * 8) = src[i];
        }
    }
    #pragma unroll
    for (int s = 0; s < 4; s++) {
        int j4 = t + s * 256;
        int row = j4 >> 3, k4 = (j4 & 7) * 4;
        float4 v = *reinterpret_cast<const float4*>(&edge_feat[(size_t)e0 * EDIM + j4 * 4]);
        *reinterpret_cast<__half2*>(sE + row * 40 + k4)     = __floats2half2_rn(v.x, v.y);
        *reinterpret_cast<__half2*>(sE + row * 40 + k4 + 2) = __floats2half2_rn(v.z, v.w);
    }
    if (t < 128) snd[t] = senders[e0 + t];
    __syncthreads();

    // ---- phase A: MMA projection -> EP ----
    {
        uint32_t af[2][4];
        int ar = lane & 15, as_ = (lane >> 4) * 8;
        #pragma unroll
        for (int kt = 0; kt < 2; kt++) {
            uint32_t off = (uint32_t)((warp * 16 + ar) * 40 + kt * 16 + as_) * 2;
            ldsm4(af[kt][0], af[kt][1], af[kt][2], af[kt][3], sEa + off);
        }
        int sel = lane >> 3, ii = lane & 7;
        int g = lane >> 2, cq = (lane & 3) * 2;
        int ebase = warp * 16 + g;
        #pragma unroll
        for (int p = 0; p < 16; p++) {
            uint32_t bh0[4], bh1[4];
            uint32_t brow = (uint32_t)(p * 16 + ((sel >> 1) << 3) + ii) * 40 + ((sel & 1) << 3);
            ldsm4(bh0[0], bh0[1], bh0[2], bh0[3], sWa + brow * 2);
            ldsm4(bh1[0], bh1[1], bh1[2], bh1[3], sWa + (brow + 16) * 2);
            #pragma unroll
            for (int q = 0; q < 2; q++) {
                float c4[4] = {0.f, 0.f, 0.f, 0.f};
                mma16816(c4, af[0], &bh0[2 * q]);
                mma16816(c4, af[1], &bh1[2 * q]);
                int ch = p * 16 + q * 8 + cq;
                *reinterpret_cast<__half2*>(EP + ebase * 260 + ch) =
                    __floats2half2_rn(c4[0], c4[1]);
                *reinterpret_cast<__half2*>(EP + (ebase + 8) * 260 + ch) =
                    __floats2half2_rn(c4[2], c4[3]);
            }
        }
    }
    __syncthreads();

    // ---- phase B: scalar tail (fp16 Ps gathers, 1-MUFU swish) ----
    const float b1 = be1[t];
    for (int ni = 0; ni < NPB; ni++) {
        const int n = n0 + ni;
        const float pr = g_Pr[(size_t)n * 256 + t] + b1;

        float fv[DEG];
        #pragma unroll
        for (int e = 0; e < DEG; e++)
            fv[e] = __half2float(g_Psh[(size_t)snd[ni * DEG + e] * 256 + t]);

        float sacc = 0.f;
        #pragma unroll
        for (int e = 0; e < DEG; e++) {
            float ep = __half2float(EP[(ni * 16 + e) * 260 + t]);
            sacc += swishf(pr + fv[e] + ep);
        }
        g_S[(size_t)n * 256 + t] = __float2half_rn(sacc);
    }
}

// ============================================================================
extern "C" void kernel_launch(void* const* d_in, const int* in_sizes, int n_in,
                              void* d_out, int out_size)
{
    const float* node_inp  = (const float*)d_in[0];
    const float* edge_feat = (const float*)d_in[1];
    const float* node_mask = (const float*)d_in[2];
    const float* We1       = (const float*)d_in[3];
    const float* be1       = (const float*)d_in[4];
    const float* We2       = (const float*)d_in[5];
    const float* be2       = (const float*)d_in[6];
    const float* g_msg     = (const float*)d_in[7];
    const float* b_msg     = (const float*)d_in[8];
    const float* Wn1       = (const float*)d_in[9];
    const float* bn1       = (const float*)d_in[10];
    const float* Wn2       = (const float*)d_in[11];
    const float* bn2       = (const float*)d_in[12];
    const float* g_node    = (const float*)d_in[13];
    const float* b_node    = (const float*)d_in[14];
    const int*   senders   = (const int*)d_in[15];
    float* out = (float*)d_out;

    float* Prp;
    __half *Pshp, *NAp, *Sp, *Up, *Wep, *Whp;
    cudaGetSymbolAddress((void**)&Prp,  g_Pr);
    cudaGetSymbolAddress((void**)&Pshp, g_Psh);
    cudaGetSymbolAddress((void**)&NAp,  g_NA);
    cudaGetSymbolAddress((void**)&Sp,   g_S);
    cudaGetSymbolAddress((void**)&Up,   g_U);
    cudaGetSymbolAddress((void**)&Wep,  g_We);
    cudaGetSymbolAddress((void**)&Whp,  g_Wh);

    const int SMEMT = 67584;
    const int SMEME = 97792;
    cudaFuncSetAttribute(mma_gemm<128,0>, cudaFuncAttributeMaxDynamicSharedMemorySize, SMEMT);
    cudaFuncSetAttribute(mma_gemm<256,1>, cudaFuncAttributeMaxDynamicSharedMemorySize, SMEMT);
    cudaFuncSetAttribute(mma_gemm<256,2>, cudaFuncAttributeMaxDynamicSharedMemorySize, SMEMT);
    cudaFuncSetAttribute(mma_gemm<256,3>, cudaFuncAttributeMaxDynamicSharedMemorySize, SMEMT);
    cudaFuncSetAttribute(edge_kernel,     cudaFuncAttributeMaxDynamicSharedMemorySize, SMEME);

    wprepA<<<256, 256>>>(We1);
    wprepB<<<384, 256>>>(We2, Wn1);
    wprepC<<<160, 256>>>(Wn2, We1);
    conv_node<<<NN / 4, 256>>>(node_inp);

    // P: by 0,1 -> Ps fp16; by 2,3 -> Pr fp32
    mma_gemm<128,0><<<dim3(GX, 4), 256, SMEMT>>>(
        NAp, Whp,
        nullptr, 1.0f, nullptr, nullptr, nullptr, nullptr, Prp, Pshp, 0);

    edge_kernel<<<NN / NPB, 256, SMEME>>>(edge_feat, senders, Wep, be1);

    // agg = LN(S @ We2 /16 + be2)*mask -> g_NA cols 128..255
    mma_gemm<256,1><<<dim3(GX, 1), 256, SMEMT>>>(
        Sp, Whp + 65536,
        be2, 1.0f / 16.0f, g_msg, b_msg, node_mask, nullptr, nullptr, NAp, 128);

    // U = swish(NA @ Wn1 + bn1) -> g_U
    mma_gemm<256,2><<<dim3(GX, 2), 256, SMEMT>>>(
        NAp, Whp + 98304,
        bn1, 1.0f, nullptr, nullptr, nullptr, nullptr, nullptr, Up, 0);

    // out = LN(node_inp + U @ Wn2 + bn2)*mask -> fp32 out
    mma_gemm<256,3><<<dim3(GX, 1), 256, SMEMT>>>(
        Up, Whp + 163840,
        bn2, 1.0f, g_node, b_node, node_mask, node_inp, out, nullptr, 0);
}

// round 16
// speedup vs baseline: 2.7739x; 1.0920x over previous
#include <cuda_runtime.h>
#include <cuda_fp16.h>
#include <cstdint>

#define NN   50000
#define NP   50048     // 391*128 padded rows
#define DEG  16
#define DIM  128
#define EDIM 32
#define HDIM 256
#define NPB  8
#define GX   391

typedef unsigned long long u64;

// ---- scratch (device globals; no allocation allowed) ----
__device__ __half g_Psh[(size_t)NN * 256];       // sender projections, fp16 (L2-resident gathers)
__device__ float  g_Pr[(size_t)NN * 256];        // receiver projections, fp32 (sequential)
__device__ __half g_NA[(size_t)NP * 256];        // cols 0-127 node_inp, 128-255 AGG (fp16)
__device__ __half g_S[(size_t)NP * 256];         // edge-sum S (fp16)
__device__ __half g_Wh[196608];                  // GEMM weights, [n][K] per region
__device__ __half g_We[8192];                    // edge-proj weights [256 ch][32 k] fp16

// single-MUFU swish: v*sigmoid(v) = 0.5*v*(1+tanh(0.5*v))
__device__ __forceinline__ float swishf(float v) {
    float th;
    asm("tanh.approx.f32 %0, %1;" : "=f"(th) : "f"(0.5f * v));
    return 0.5f * v * (1.0f + th);
}
__device__ __forceinline__ uint32_t smem_u32(const void* p) {
    uint32_t a;
    asm("{ .reg .u64 t; cvta.to.shared.u64 t, %1; cvt.u32.u64 %0, t; }" : "=r"(a) : "l"(p));
    return a;
}
__device__ __forceinline__ void ldsm4(uint32_t& r0, uint32_t& r1, uint32_t& r2,
                                      uint32_t& r3, uint32_t addr) {
    asm volatile("ldmatrix.sync.aligned.m8n8.x4.shared.b16 {%0,%1,%2,%3}, [%4];"
                 : "=r"(r0), "=r"(r1), "=r"(r2), "=r"(r3) : "r"(addr));
}
__device__ __forceinline__ void mma16816(float* c, const uint32_t* a, const uint32_t* b) {
    asm volatile("mma.sync.aligned.m16n8k16.row.col.f32.f16.f16.f32 "
                 "{%0,%1,%2,%3}, {%4,%5,%6,%7}, {%8,%9}, {%0,%1,%2,%3};"
                 : "+f"(c[0]), "+f"(c[1]), "+f"(c[2]), "+f"(c[3])
                 : "r"(a[0]), "r"(a[1]), "r"(a[2]), "r"(a[3]), "r"(b[0]), "r"(b[1]));
}
__device__ __forceinline__ void cp_async16(uint32_t dst, const void* src, int src_bytes) {
    asm volatile("cp.async.cg.shared.global [%0], [%1], 16, %2;"
                 :: "r"(dst), "l"(src), "r"(src_bytes) : "memory");
}
__device__ __forceinline__ void cp_commit() {
    asm volatile("cp.async.commit_group;" ::: "memory");
}

// ============================================================================
// fused prep kernel: blocks [0,256) wprepA | [256,640) wprepB | [640,800) wprepC
//                    | [800,13300) conv_node
// ============================================================================
__global__ void prep_all(const float* __restrict__ We1, const float* __restrict__ We2,
                         const float* __restrict__ Wn1, const float* __restrict__ Wn2,
                         const float* __restrict__ x)
{
    int b = blockIdx.x, t = threadIdx.x;
    if (b < 256) {                       // We1 -> region 0: [512 n][128 k]
        int idx = b * 256 + t;
        int local = idx & 32767, region = idx >> 15;
        int n = local >> 7, k = local & 127;
        g_Wh[idx] = __float2half_rn(We1[(size_t)(region * 128 + k) * 256 + n]);
    } else if (b < 640) {                // We2 + Wn1
        int idx = (b - 256) * 256 + t;
        if (idx < 32768) {
            int n = idx >> 8, k = idx & 255;
            g_Wh[65536 + idx] = __float2half_rn(We2[(size_t)k * 128 + n]);
        } else {
            int j = idx - 32768, n = j >> 8, k = j & 255;
            g_Wh[98304 + j] = __float2half_rn(Wn1[(size_t)k * 256 + n]);
        }
    } else if (b < 800) {                // Wn2 + We1 edge rows
        int idx = (b - 640) * 256 + t;
        if (idx < 32768) {
            int n = idx >> 8, k = idx & 255;
            g_Wh[163840 + idx] = __float2half_rn(Wn2[(size_t)k * 128 + n]);
        } else {
            int j = idx - 32768, n = j >> 5, k = j & 31;
            g_We[j] = __float2half_rn(We1[(size_t)(256 + k) * 256 + n]);
        }
    } else {                             // conv_node: 4 rows per block
        int row = (b - 800) * 4 + (t >> 6);
        int c = (t & 63) * 2;
        float2 v = *reinterpret_cast<const float2*>(&x[(size_t)row * 128 + c]);
        *reinterpret_cast<__half2*>(&g_NA[(size_t)row * 256 + c]) = __floats2half2_rn(v.x, v.y);
    }
}

// ============================================================================
// 1-term fp16 HMMA GEMM, cp.async double-buffered (r14-proven, 444.5us).
//   MODE 0: P store -> by 0,1: Ps fp16 (oB); by 2,3: Pr fp32 (outF)
//   MODE 1: v=acc*scale+bias; LN*mask -> fp16 g_NA cols 128..255
// ============================================================================
template<int K, int MODE>
__global__ void __launch_bounds__(256, 2) mma_gemm(
    const __half* __restrict__ A, const __half* __restrict__ B,
    const float* __restrict__ bias, float scale,
    const float* __restrict__ gamma, const float* __restrict__ beta,
    const float* __restrict__ mask,
    float* __restrict__ outF,
    __half* __restrict__ oB, int oCol)
{
    extern __shared__ __align__(16) char smem[];
    float* Csm = reinterpret_cast<float*>(smem);             // [128][132] (post-loop)

    const uint32_t sb = smem_u32(smem);
    const int t = threadIdx.x, lane = t & 31, warp = t >> 5;
    const int wm = warp & 3, wn = warp >> 2;
    const int n0 = blockIdx.x * 128, by = blockIdx.y;
    constexpr int NCH = K / 32;
    constexpr uint32_t BUFB = 20480;

    float acc[2][8][4];
    #pragma unroll
    for (int mt = 0; mt < 2; mt++)
        #pragma unroll
        for (int nt = 0; nt < 8; nt++)
            #pragma unroll
            for (int q = 0; q < 4; q++) acc[mt][nt][q] = 0.f;

    const int r0s = t >> 2, g0 = t & 3;

    auto stage = [&](int c, int b) {
        uint32_t base = sb + (uint32_t)b * BUFB;
        #pragma unroll
        for (int s = 0; s < 2; s++) {
            int row = r0s + s * 64;
            int grow = n0 + row;
            int ga = grow < NN ? grow : NN - 1;
            int ok = grow < NN ? 16 : 0;
            uint32_t so = (uint32_t)(row * 40 + g0 * 8) * 2;
            cp_async16(base + so,         &A[(size_t)ga * 256 + c * 32 + g0 * 8], ok);
            cp_async16(base + 10240 + so,
                       &B[(size_t)(by * 128 + row) * K + c * 32 + g0 * 8], 16);
        }
        cp_commit();
    };

    stage(0, 0);
    for (int c = 0; c < NCH; c++) {
        const int b = c & 1;
        if (c + 1 < NCH) {
            stage(c + 1, (c + 1) & 1);
            asm volatile("cp.async.wait_group 1;" ::: "memory");
        } else {
            asm volatile("cp.async.wait_group 0;" ::: "memory");
        }
        __syncthreads();

        const uint32_t base = sb + (uint32_t)b * BUFB;
        #pragma unroll
        for (int kt = 0; kt < 32; kt += 16) {
            uint32_t ah[2][4];
            {
                int ar = lane & 15, as_ = (lane >> 4) * 8;
                #pragma unroll
                for (int mt = 0; mt < 2; mt++) {
                    uint32_t off = (uint32_t)((wm * 32 + mt * 16 + ar) * 40 + kt + as_) * 2;
                    ldsm4(ah[mt][0], ah[mt][1], ah[mt][2], ah[mt][3], base + off);
                }
            }
            #pragma unroll
            for (int p = 0; p < 4; p++) {
                int sel = lane >> 3, i = lane & 7;
                uint32_t boff = (uint32_t)((wn * 64 + p * 16 + ((sel >> 1) << 3) + i) * 40
                                           + kt + ((sel & 1) << 3)) * 2;
                uint32_t bh[4];
                ldsm4(bh[0], bh[1], bh[2], bh[3], base + 10240 + boff);
                #pragma unroll
                for (int mt = 0; mt < 2; mt++)
                    #pragma unroll
                    for (int q = 0; q < 2; q++)
                        mma16816(acc[mt][2 * p + q], ah[mt], &bh[2 * q]);
            }
        }
        __syncthreads();
    }

    {
        int g = lane >> 2, cc = (lane & 3) * 2;
        #pragma unroll
        for (int mt = 0; mt < 2; mt++)
            #pragma unroll
            for (int nt = 0; nt < 8; nt++) {
                int r0 = wm * 32 + mt * 16 + g;
                int col = wn * 64 + nt * 8 + cc;
                *reinterpret_cast<float2*>(&Csm[r0 * 132 + col]) =
                    make_float2(acc[mt][nt][0], acc[mt][nt][1]);
                *reinterpret_cast<float2*>(&Csm[(r0 + 8) * 132 + col]) =
                    make_float2(acc[mt][nt][2], acc[mt][nt][3]);
            }
    }
    __syncthreads();

    const int r = t >> 1, hh = t & 1, ch0 = hh * 64;
    const int row = n0 + r;
    const float* crow = &Csm[r * 132 + ch0];

    if (MODE == 0) {
        if (row < NN) {
            if (by < 2) {
                __half* o = &oB[(size_t)row * 256 + by * 128 + ch0];
                #pragma unroll
                for (int j = 0; j < 64; j += 2)
                    *reinterpret_cast<__half2*>(&o[j]) =
                        __floats2half2_rn(crow[j], crow[j + 1]);
            } else {
                float* o = &outF[(size_t)row * 256 + (by - 2) * 128 + ch0];
                #pragma unroll
                for (int j = 0; j < 64; j += 4)
                    *reinterpret_cast<float4*>(&o[j]) =
                        *reinterpret_cast<const float4*>(&crow[j]);
            }
        }
        return;
    }
    // MODE 1: LN epilogue
    {
        float s = 0.f, s2 = 0.f;
        #pragma unroll
        for (int j = 0; j < 64; j += 4) {
            float4 c4 = *reinterpret_cast<const float4*>(&crow[j]);
            float v0 = c4.x * scale + bias[ch0 + j];
            float v1 = c4.y * scale + bias[ch0 + j + 1];
            float v2 = c4.z * scale + bias[ch0 + j + 2];
            float v3 = c4.w * scale + bias[ch0 + j + 3];
            s += v0 + v1 + v2 + v3;
            s2 += v0 * v0 + v1 * v1 + v2 * v2 + v3 * v3;
        }
        s  += __shfl_xor_sync(0xffffffffu, s, 1);
        s2 += __shfl_xor_sync(0xffffffffu, s2, 1);
        float m    = s * (1.0f / 128.0f);
        float var  = s2 * (1.0f / 128.0f) - m * m;
        float rstd = rsqrtf(var + 1e-5f);
        if (row < NN) {
            float mk = mask[row];
            #pragma unroll
            for (int j = 0; j < 64; j += 2) {
                int c = ch0 + j;
                float v0 = crow[j]     * scale + bias[c];
                float v1 = crow[j + 1] * scale + bias[c + 1];
                float w0 = ((v0 - m) * rstd * gamma[c]     + beta[c])     * mk;
                float w1 = ((v1 - m) * rstd * gamma[c + 1] + beta[c + 1]) * mk;
                *reinterpret_cast<__half2*>(&oB[(size_t)row * 256 + oCol + c]) =
                    __floats2half2_rn(w0, w1);
            }
        }
    }
}

// ============================================================================
// Fused gemm4+gemm5:
//   U[128,256] = swish(NA @ Wn1 + bn1)  -> smem (A-staging layout, 8 chunks)
//   out = LN(node_inp + U @ Wn2 + bn2; g_node, b_node) * mask
// Smem: stage 2x20480 @0 | usm 8x10240 @40960 | Csm overlays @40960 post-loop.
// ============================================================================
__global__ void __launch_bounds__(256, 1) gemm45(
    const __half* __restrict__ A,      // g_NA
    const __half* __restrict__ B1,     // Wn1 region [256 n][256 k]
    const __half* __restrict__ B2,     // Wn2 region [128 n][256 k]
    const float* __restrict__ bn1, const float* __restrict__ bn2,
    const float* __restrict__ gamma, const float* __restrict__ beta,
    const float* __restrict__ mask, const float* __restrict__ resid,
    float* __restrict__ outF)
{
    extern __shared__ __align__(16) char smem[];
    const uint32_t sb = smem_u32(smem);
    const uint32_t USM = 40960;
    float* Csm = reinterpret_cast<float*>(smem + USM);       // [128][132] post-loop

    const int t = threadIdx.x, lane = t & 31, warp = t >> 5;
    const int wm = warp & 3, wn = warp >> 2;
    const int n0 = blockIdx.x * 128;
    constexpr uint32_t BUFB = 20480;

    const int r0s = t >> 2, g0 = t & 3;
    const int g = lane >> 2, cc = (lane & 3) * 2;

    // ---------- phase 1: gemm4 (two N-tiles of Wn1) ----------
    auto stage1 = [&](int c, int b, int nt2) {
        uint32_t base = sb + (uint32_t)b * BUFB;
        #pragma unroll
        for (int s = 0; s < 2; s++) {
            int row = r0s + s * 64;
            int grow = n0 + row;
            int ga = grow < NN ? grow : NN - 1;
            int ok = grow < NN ? 16 : 0;
            uint32_t so = (uint32_t)(row * 40 + g0 * 8) * 2;
            cp_async16(base + so, &A[(size_t)ga * 256 + c * 32 + g0 * 8], ok);
            cp_async16(base + 10240 + so,
                       &B1[(size_t)(nt2 * 128 + row) * 256 + c * 32 + g0 * 8], 16);
        }
        cp_commit();
    };

    for (int nt2 = 0; nt2 < 2; nt2++) {
        float acc[2][8][4];
        #pragma unroll
        for (int mt = 0; mt < 2; mt++)
            #pragma unroll
            for (int nt = 0; nt < 8; nt++)
                #pragma unroll
                for (int q = 0; q < 4; q++) acc[mt][nt][q] = 0.f;

        stage1(0, 0, nt2);
        for (int c = 0; c < 8; c++) {
            const int b = c & 1;
            if (c + 1 < 8) {
                stage1(c + 1, (c + 1) & 1, nt2);
                asm volatile("cp.async.wait_group 1;" ::: "memory");
            } else {
                asm volatile("cp.async.wait_group 0;" ::: "memory");
            }
            __syncthreads();

            const uint32_t base = sb + (uint32_t)b * BUFB;
            #pragma unroll
            for (int kt = 0; kt < 32; kt += 16) {
                uint32_t ah[2][4];
                {
                    int ar = lane & 15, as_ = (lane >> 4) * 8;
                    #pragma unroll
                    for (int mt = 0; mt < 2; mt++) {
                        uint32_t off = (uint32_t)((wm * 32 + mt * 16 + ar) * 40 + kt + as_) * 2;
                        ldsm4(ah[mt][0], ah[mt][1], ah[mt][2], ah[mt][3], base + off);
                    }
                }
                #pragma unroll
                for (int p = 0; p < 4; p++) {
                    int sel = lane >> 3, i = lane & 7;
                    uint32_t boff = (uint32_t)((wn * 64 + p * 16 + ((sel >> 1) << 3) + i) * 40
                                               + kt + ((sel & 1) << 3)) * 2;
                    uint32_t bh[4];
                    ldsm4(bh[0], bh[1], bh[2], bh[3], base + 10240 + boff);
                    #pragma unroll
                    for (int mt = 0; mt < 2; mt++)
                        #pragma unroll
                        for (int q = 0; q < 2; q++)
                            mma16816(acc[mt][2 * p + q], ah[mt], &bh[2 * q]);
                }
            }
            __syncthreads();
        }

        // epilogue: swish fragments -> usm in A-staging layout (fp16)
        #pragma unroll
        for (int mt = 0; mt < 2; mt++)
            #pragma unroll
            for (int nt = 0; nt < 8; nt++) {
                int r0 = wm * 32 + mt * 16 + g;
                int ch = nt2 * 128 + wn * 64 + nt * 8 + cc;
                float b0 = bn1[ch], b1v = bn1[ch + 1];
                int chunk = ch >> 5, kk = ch & 31;
                __half* up = reinterpret_cast<__half*>(smem + USM + chunk * 10240);
                *reinterpret_cast<__half2*>(&up[r0 * 40 + kk]) =
                    __floats2half2_rn(swishf(acc[mt][nt][0] + b0),
                                      swishf(acc[mt][nt][1] + b1v));
                *reinterpret_cast<__half2*>(&up[(r0 + 8) * 40 + kk]) =
                    __floats2half2_rn(swishf(acc[mt][nt][2] + b0),
                                      swishf(acc[mt][nt][3] + b1v));
            }
        __syncthreads();
    }

    // ---------- phase 2: gemm5 (A = usm, B = Wn2 staged) ----------
    auto stage2 = [&](int c, int b) {
        uint32_t base = sb + (uint32_t)b * BUFB + 10240;
        #pragma unroll
        for (int s = 0; s < 2; s++) {
            int row = r0s + s * 64;
            uint32_t so = (uint32_t)(row * 40 + g0 * 8) * 2;
            cp_async16(base + so, &B2[(size_t)row * 256 + c * 32 + g0 * 8], 16);
        }
        cp_commit();
    };

    float acc[2][8][4];
    #pragma unroll
    for (int mt = 0; mt < 2; mt++)
        #pragma unroll
        for (int nt = 0; nt < 8; nt++)
            #pragma unroll
            for (int q = 0; q < 4; q++) acc[mt][nt][q] = 0.f;

    stage2(0, 0);
    for (int c = 0; c < 8; c++) {
        const int b = c & 1;
        if (c + 1 < 8) {
            stage2(c + 1, (c + 1) & 1);
            asm volatile("cp.async.wait_group 1;" ::: "memory");
        } else {
            asm volatile("cp.async.wait_group 0;" ::: "memory");
        }
        __syncthreads();

        const uint32_t baseB = sb + (uint32_t)b * BUFB + 10240;
        const uint32_t baseA = sb + USM + (uint32_t)c * 10240;
        #pragma unroll
        for (int kt = 0; kt < 32; kt += 16) {
            uint32_t ah[2][4];
            {
                int ar = lane & 15, as_ = (lane >> 4) * 8;
                #pragma unroll
                for (int mt = 0; mt < 2; mt++) {
                    uint32_t off = (uint32_t)((wm * 32 + mt * 16 + ar) * 40 + kt + as_) * 2;
                    ldsm4(ah[mt][0], ah[mt][1], ah[mt][2], ah[mt][3], baseA + off);
                }
            }
            #pragma unroll
            for (int p = 0; p < 4; p++) {
                int sel = lane >> 3, i = lane & 7;
                uint32_t boff = (uint32_t)((wn * 64 + p * 16 + ((sel >> 1) << 3) + i) * 40
                                           + kt + ((sel & 1) << 3)) * 2;
                uint32_t bh[4];
                ldsm4(bh[0], bh[1], bh[2], bh[3], baseB + boff);
                #pragma unroll
                for (int mt = 0; mt < 2; mt++)
                    #pragma unroll
                    for (int q = 0; q < 2; q++)
                        mma16816(acc[mt][2 * p + q], ah[mt], &bh[2 * q]);
            }
        }
        __syncthreads();
    }

    // fragments -> Csm (overlays usm; mainloop done)
    #pragma unroll
    for (int mt = 0; mt < 2; mt++)
        #pragma unroll
        for (int nt = 0; nt < 8; nt++) {
            int r0 = wm * 32 + mt * 16 + g;
            int col = wn * 64 + nt * 8 + cc;
            *reinterpret_cast<float2*>(&Csm[r0 * 132 + col]) =
                make_float2(acc[mt][nt][0], acc[mt][nt][1]);
            *reinterpret_cast<float2*>(&Csm[(r0 + 8) * 132 + col]) =
                make_float2(acc[mt][nt][2], acc[mt][nt][3]);
        }
    __syncthreads();

    // LN epilogue (resid + LN*mask -> fp32 out)
    const int r = t >> 1, hh = t & 1, ch0 = hh * 64;
    const int row = n0 + r;
    const float* crow = &Csm[r * 132 + ch0];

    float s = 0.f, s2 = 0.f;
    #pragma unroll
    for (int j = 0; j < 64; j += 4) {
        float4 c4 = *reinterpret_cast<const float4*>(&crow[j]);
        float v0 = c4.x + bn2[ch0 + j];
        float v1 = c4.y + bn2[ch0 + j + 1];
        float v2 = c4.z + bn2[ch0 + j + 2];
        float v3 = c4.w + bn2[ch0 + j + 3];
        if (row < NN) {
            float4 r4 = *reinterpret_cast<const float4*>(&resid[(size_t)row * 128 + ch0 + j]);
            v0 += r4.x; v1 += r4.y; v2 += r4.z; v3 += r4.w;
        }
        s += v0 + v1 + v2 + v3;
        s2 += v0 * v0 + v1 * v1 + v2 * v2 + v3 * v3;
    }
    s  += __shfl_xor_sync(0xffffffffu, s, 1);
    s2 += __shfl_xor_sync(0xffffffffu, s2, 1);
    float m    = s * (1.0f / 128.0f);
    float var  = s2 * (1.0f / 128.0f) - m * m;
    float rstd = rsqrtf(var + 1e-5f);
    if (row < NN) {
        float mk = mask[row];
        #pragma unroll
        for (int j = 0; j < 64; j += 2) {
            int c = ch0 + j;
            float2 r2 = *reinterpret_cast<const float2*>(&resid[(size_t)row * 128 + c]);
            float v0 = crow[j]     + bn2[c]     + r2.x;
            float v1 = crow[j + 1] + bn2[c + 1] + r2.y;
            float w0 = ((v0 - m) * rstd * gamma[c]     + beta[c])     * mk;
            float w1 = ((v1 - m) * rstd * gamma[c + 1] + beta[c + 1]) * mk;
            *reinterpret_cast<float2*>(&outF[(size_t)row * 128 + c]) = make_float2(w0, w1);
        }
    }
}

// ============================================================================
// Edge kernel (r12-14 proven; unchanged)
// ============================================================================
__global__ void __launch_bounds__(256, 2) edge_kernel(
    const float* __restrict__ edge_feat, const int* __restrict__ senders,
    const __half* __restrict__ gWe, const float* __restrict__ be1)
{
    extern __shared__ __align__(16) char esm[];
    __half* sW = reinterpret_cast<__half*>(esm);             // 20480 B
    __half* sE = reinterpret_cast<__half*>(esm + 20480);     // 10240 B
    __half* EP = reinterpret_cast<__half*>(esm + 30720);     // 66560 B
    int* snd   = reinterpret_cast<int*>(esm + 97280);        // 512 B

    const int t = threadIdx.x, lane = t & 31, warp = t >> 5;
    const int n0 = blockIdx.x * NPB;
    const int e0 = n0 * DEG;
    const uint32_t sWa = smem_u32(sW), sEa = smem_u32(sE);

    {
        const uint4* src = reinterpret_cast<const uint4*>(gWe);
        #pragma unroll
        for (int s = 0; s < 4; s++) {
            int i = t + s * 256;
            int n = i >> 2, kq = i & 3;
            *reinterpret_cast<uint4*>(sW + n * 40 + kq * 8) = src[i];
        }
    }
    #pragma unroll
    for (int s = 0; s < 4; s++) {
        int j4 = t + s * 256;
        int row = j4 >> 3, k4 = (j4 & 7) * 4;
        float4 v = *reinterpret_cast<const float4*>(&edge_feat[(size_t)e0 * EDIM + j4 * 4]);
        *reinterpret_cast<__half2*>(sE + row * 40 + k4)     = __floats2half2_rn(v.x, v.y);
        *reinterpret_cast<__half2*>(sE + row * 40 + k4 + 2) = __floats2half2_rn(v.z, v.w);
    }
    if (t < 128) snd[t] = senders[e0 + t];
    __syncthreads();

    {
        uint32_t af[2][4];
        int ar = lane & 15, as_ = (lane >> 4) * 8;
        #pragma unroll
        for (int kt = 0; kt < 2; kt++) {
            uint32_t off = (uint32_t)((warp * 16 + ar) * 40 + kt * 16 + as_) * 2;
            ldsm4(af[kt][0], af[kt][1], af[kt][2], af[kt][3], sEa + off);
        }
        int sel = lane >> 3, ii = lane & 7;
        int g = lane >> 2, cq = (lane & 3) * 2;
        int ebase = warp * 16 + g;
        #pragma unroll
        for (int p = 0; p < 16; p++) {
            uint32_t bh0[4], bh1[4];
            uint32_t brow = (uint32_t)(p * 16 + ((sel >> 1) << 3) + ii) * 40 + ((sel & 1) << 3);
            ldsm4(bh0[0], bh0[1], bh0[2], bh0[3], sWa + brow * 2);
            ldsm4(bh1[0], bh1[1], bh1[2], bh1[3], sWa + (brow + 16) * 2);
            #pragma unroll
            for (int q = 0; q < 2; q++) {
                float c4[4] = {0.f, 0.f, 0.f, 0.f};
                mma16816(c4, af[0], &bh0[2 * q]);
                mma16816(c4, af[1], &bh1[2 * q]);
                int ch = p * 16 + q * 8 + cq;
                *reinterpret_cast<__half2*>(EP + ebase * 260 + ch) =
                    __floats2half2_rn(c4[0], c4[1]);
                *reinterpret_cast<__half2*>(EP + (ebase + 8) * 260 + ch) =
                    __floats2half2_rn(c4[2], c4[3]);
            }
        }
    }
    __syncthreads();

    const float b1 = be1[t];
    for (int ni = 0; ni < NPB; ni++) {
        const int n = n0 + ni;
        const float pr = g_Pr[(size_t)n * 256 + t] + b1;

        float fv[DEG];
        #pragma unroll
        for (int e = 0; e < DEG; e++)
            fv[e] = __half2float(g_Psh[(size_t)snd[ni * DEG + e] * 256 + t]);

        float sacc = 0.f;
        #pragma unroll
        for (int e = 0; e < DEG; e++) {
            float ep = __half2float(EP[(ni * 16 + e) * 260 + t]);
            sacc += swishf(pr + fv[e] + ep);
        }
        g_S[(size_t)n * 256 + t] = __float2half_rn(sacc);
    }
}

// ============================================================================
extern "C" void kernel_launch(void* const* d_in, const int* in_sizes, int n_in,
                              void* d_out, int out_size)
{
    const float* node_inp  = (const float*)d_in[0];
    const float* edge_feat = (const float*)d_in[1];
    const float* node_mask = (const float*)d_in[2];
    const float* We1       = (const float*)d_in[3];
    const float* be1       = (const float*)d_in[4];
    const float* We2       = (const float*)d_in[5];
    const float* be2       = (const float*)d_in[6];
    const float* g_msg     = (const float*)d_in[7];
    const float* b_msg     = (const float*)d_in[8];
    const float* Wn1       = (const float*)d_in[9];
    const float* bn1       = (const float*)d_in[10];
    const float* Wn2       = (const float*)d_in[11];
    const float* bn2       = (const float*)d_in[12];
    const float* g_node    = (const float*)d_in[13];
    const float* b_node    = (const float*)d_in[14];
    const int*   senders   = (const int*)d_in[15];
    float* out = (float*)d_out;

    float* Prp;
    __half *Pshp, *NAp, *Sp, *Wep, *Whp;
    cudaGetSymbolAddress((void**)&Prp,  g_Pr);
    cudaGetSymbolAddress((void**)&Pshp, g_Psh);
    cudaGetSymbolAddress((void**)&NAp,  g_NA);
    cudaGetSymbolAddress((void**)&Sp,   g_S);
    cudaGetSymbolAddress((void**)&Wep,  g_We);
    cudaGetSymbolAddress((void**)&Whp,  g_Wh);

    const int SMEMT  = 67584;
    const int SMEME  = 97792;
    const int SMEM45 = 122880;
    cudaFuncSetAttribute(mma_gemm<128,0>, cudaFuncAttributeMaxDynamicSharedMemorySize, SMEMT);
    cudaFuncSetAttribute(mma_gemm<256,1>, cudaFuncAttributeMaxDynamicSharedMemorySize, SMEMT);
    cudaFuncSetAttribute(gemm45,          cudaFuncAttributeMaxDynamicSharedMemorySize, SMEM45);
    cudaFuncSetAttribute(edge_kernel,     cudaFuncAttributeMaxDynamicSharedMemorySize, SMEME);

    // 1) all prep in one launch
    prep_all<<<800 + NN / 4, 256>>>(We1, We2, Wn1, Wn2, node_inp);

    // 2) P: by 0,1 -> Ps fp16; by 2,3 -> Pr fp32
    mma_gemm<128,0><<<dim3(GX, 4), 256, SMEMT>>>(
        NAp, Whp, nullptr, 1.0f, nullptr, nullptr, nullptr, Prp, Pshp, 0);

    // 3) edge kernel
    edge_kernel<<<NN / NPB, 256, SMEME>>>(edge_feat, senders, Wep, be1);

    // 4) agg = LN(S @ We2 /16 + be2)*mask -> g_NA cols 128..255
    mma_gemm<256,1><<<dim3(GX, 1), 256, SMEMT>>>(
        Sp, Whp + 65536, be2, 1.0f / 16.0f, g_msg, b_msg, node_mask,
        nullptr, NAp, 128);

    // 5) fused: U = swish(NA@Wn1+bn1); out = LN(node_inp + U@Wn2 + bn2)*mask
    gemm45<<<dim3(GX, 1), 256, SMEM45>>>(
        NAp, Whp + 98304, Whp + 163840,
        bn1, bn2, g_node, b_node, node_mask, node_inp, out);
}

// round 17
// speedup vs baseline: 2.8121x; 1.0138x over previous
#include <cuda_runtime.h>
#include <cuda_fp16.h>
#include <cstdint>

#define NN   50000
#define NP   50048     // 391*128 padded rows
#define DEG  16
#define DIM  128
#define EDIM 32
#define HDIM 256
#define NPB  8
#define GX   391

typedef unsigned long long u64;

// ---- scratch (device globals; no allocation allowed) ----
__device__ __half g_Psh[(size_t)NN * 256];       // sender projections, fp16 (L2-resident gathers)
__device__ float  g_Pr[(size_t)NN * 256];        // receiver projections, fp32 (sequential)
__device__ __half g_NA[(size_t)NP * 256];        // cols 0-127 node_inp, 128-255 AGG (fp16)
__device__ __half g_S[(size_t)NP * 256];         // edge-sum S (fp16)
__device__ __half g_Wh[196608];                  // GEMM weights, [n][K] per region
__device__ __half g_We[8192];                    // edge-proj weights [256 ch][32 k] fp16

// single-MUFU swish: v*sigmoid(v) = 0.5*v*(1+tanh(0.5*v))
__device__ __forceinline__ float swishf(float v) {
    float th;
    asm("tanh.approx.f32 %0, %1;" : "=f"(th) : "f"(0.5f * v));
    return 0.5f * v * (1.0f + th);
}
__device__ __forceinline__ uint32_t smem_u32(const void* p) {
    uint32_t a;
    asm("{ .reg .u64 t; cvta.to.shared.u64 t, %1; cvt.u32.u64 %0, t; }" : "=r"(a) : "l"(p));
    return a;
}
__device__ __forceinline__ void ldsm4(uint32_t& r0, uint32_t& r1, uint32_t& r2,
                                      uint32_t& r3, uint32_t addr) {
    asm volatile("ldmatrix.sync.aligned.m8n8.x4.shared.b16 {%0,%1,%2,%3}, [%4];"
                 : "=r"(r0), "=r"(r1), "=r"(r2), "=r"(r3) : "r"(addr));
}
__device__ __forceinline__ void mma16816(float* c, const uint32_t* a, const uint32_t* b) {
    asm volatile("mma.sync.aligned.m16n8k16.row.col.f32.f16.f16.f32 "
                 "{%0,%1,%2,%3}, {%4,%5,%6,%7}, {%8,%9}, {%0,%1,%2,%3};"
                 : "+f"(c[0]), "+f"(c[1]), "+f"(c[2]), "+f"(c[3])
                 : "r"(a[0]), "r"(a[1]), "r"(a[2]), "r"(a[3]), "r"(b[0]), "r"(b[1]));
}
__device__ __forceinline__ void cp_async16(uint32_t dst, const void* src, int src_bytes) {
    asm volatile("cp.async.cg.shared.global [%0], [%1], 16, %2;"
                 :: "r"(dst), "l"(src), "r"(src_bytes) : "memory");
}
__device__ __forceinline__ void cp_commit() {
    asm volatile("cp.async.commit_group;" ::: "memory");
}

// ============================================================================
// fused prep kernel
// ============================================================================
__global__ void prep_all(const float* __restrict__ We1, const float* __restrict__ We2,
                         const float* __restrict__ Wn1, const float* __restrict__ Wn2,
                         const float* __restrict__ x)
{
    int b = blockIdx.x, t = threadIdx.x;
    if (b < 256) {
        int idx = b * 256 + t;
        int local = idx & 32767, region = idx >> 15;
        int n = local >> 7, k = local & 127;
        g_Wh[idx] = __float2half_rn(We1[(size_t)(region * 128 + k) * 256 + n]);
    } else if (b < 640) {
        int idx = (b - 256) * 256 + t;
        if (idx < 32768) {
            int n = idx >> 8, k = idx & 255;
            g_Wh[65536 + idx] = __float2half_rn(We2[(size_t)k * 128 + n]);
        } else {
            int j = idx - 32768, n = j >> 8, k = j & 255;
            g_Wh[98304 + j] = __float2half_rn(Wn1[(size_t)k * 256 + n]);
        }
    } else if (b < 800) {
        int idx = (b - 640) * 256 + t;
        if (idx < 32768) {
            int n = idx >> 8, k = idx & 255;
            g_Wh[163840 + idx] = __float2half_rn(Wn2[(size_t)k * 128 + n]);
        } else {
            int j = idx - 32768, n = j >> 5, k = j & 31;
            g_We[j] = __float2half_rn(We1[(size_t)(256 + k) * 256 + n]);
        }
    } else {
        int row = (b - 800) * 4 + (t >> 6);
        int c = (t & 63) * 2;
        float2 v = *reinterpret_cast<const float2*>(&x[(size_t)row * 128 + c]);
        *reinterpret_cast<__half2*>(&g_NA[(size_t)row * 256 + c]) = __floats2half2_rn(v.x, v.y);
    }
}

// ============================================================================
// 1-term fp16 HMMA GEMM, BK=64 double-buffered (2 chunks per buffer).
//   Buffer layout: [A0 10240 | A1 10240 | B0 10240 | B1 10240] = 40960 B/buf.
//   MODE 0: P store -> by 0,1: Ps fp16 (oB); by 2,3: Pr fp32 (outF)
//   MODE 1: v=acc*scale+bias; LN*mask -> fp16 g_NA cols 128..255
// ============================================================================
template<int K, int MODE>
__global__ void __launch_bounds__(256, 2) mma_gemm(
    const __half* __restrict__ A, const __half* __restrict__ B,
    const float* __restrict__ bias, float scale,
    const float* __restrict__ gamma, const float* __restrict__ beta,
    const float* __restrict__ mask,
    float* __restrict__ outF,
    __half* __restrict__ oB, int oCol)
{
    extern __shared__ __align__(16) char smem[];
    float* Csm = reinterpret_cast<float*>(smem);             // [128][132] (post-loop)

    const uint32_t sb = smem_u32(smem);
    const int t = threadIdx.x, lane = t & 31, warp = t >> 5;
    const int wm = warp & 3, wn = warp >> 2;
    const int n0 = blockIdx.x * 128, by = blockIdx.y;
    constexpr int NP2 = K / 64;                  // chunk-pairs
    constexpr uint32_t BUFB = 40960;

    float acc[2][8][4];
    #pragma unroll
    for (int mt = 0; mt < 2; mt++)
        #pragma unroll
        for (int nt = 0; nt < 8; nt++)
            #pragma unroll
            for (int q = 0; q < 4; q++) acc[mt][nt][q] = 0.f;

    const int r0s = t >> 2, g0 = t & 3;

    auto stage = [&](int cp, int b) {
        uint32_t base = sb + (uint32_t)b * BUFB;
        #pragma unroll
        for (int sub = 0; sub < 2; sub++) {
            int c = cp * 2 + sub;
            #pragma unroll
            for (int s = 0; s < 2; s++) {
                int row = r0s + s * 64;
                int grow = n0 + row;
                int ga = grow < NN ? grow : NN - 1;
                int ok = grow < NN ? 16 : 0;
                uint32_t so = (uint32_t)(row * 40 + g0 * 8) * 2 + sub * 10240u;
                cp_async16(base + so,          &A[(size_t)ga * 256 + c * 32 + g0 * 8], ok);
                cp_async16(base + 20480 + so,
                           &B[(size_t)(by * 128 + row) * K + c * 32 + g0 * 8], 16);
            }
        }
        cp_commit();
    };

    stage(0, 0);
    for (int cp = 0; cp < NP2; cp++) {
        const int b = cp & 1;
        if (cp + 1 < NP2) {
            stage(cp + 1, (cp + 1) & 1);
            asm volatile("cp.async.wait_group 1;" ::: "memory");
        } else {
            asm volatile("cp.async.wait_group 0;" ::: "memory");
        }
        __syncthreads();

        const uint32_t base = sb + (uint32_t)b * BUFB;
        #pragma unroll
        for (int sub = 0; sub < 2; sub++) {
            const uint32_t baseA = base + sub * 10240u;
            const uint32_t baseB = base + 20480 + sub * 10240u;
            #pragma unroll
            for (int kt = 0; kt < 32; kt += 16) {
                uint32_t ah[2][4];
                {
                    int ar = lane & 15, as_ = (lane >> 4) * 8;
                    #pragma unroll
                    for (int mt = 0; mt < 2; mt++) {
                        uint32_t off = (uint32_t)((wm * 32 + mt * 16 + ar) * 40 + kt + as_) * 2;
                        ldsm4(ah[mt][0], ah[mt][1], ah[mt][2], ah[mt][3], baseA + off);
                    }
                }
                #pragma unroll
                for (int p = 0; p < 4; p++) {
                    int sel = lane >> 3, i = lane & 7;
                    uint32_t boff = (uint32_t)((wn * 64 + p * 16 + ((sel >> 1) << 3) + i) * 40
                                               + kt + ((sel & 1) << 3)) * 2;
                    uint32_t bh[4];
                    ldsm4(bh[0], bh[1], bh[2], bh[3], baseB + boff);
                    #pragma unroll
                    for (int mt = 0; mt < 2; mt++)
                        #pragma unroll
                        for (int q = 0; q < 2; q++)
                            mma16816(acc[mt][2 * p + q], ah[mt], &bh[2 * q]);
                }
            }
        }
        __syncthreads();
    }

    {
        int g = lane >> 2, cc = (lane & 3) * 2;
        #pragma unroll
        for (int mt = 0; mt < 2; mt++)
            #pragma unroll
            for (int nt = 0; nt < 8; nt++) {
                int r0 = wm * 32 + mt * 16 + g;
                int col = wn * 64 + nt * 8 + cc;
                *reinterpret_cast<float2*>(&Csm[r0 * 132 + col]) =
                    make_float2(acc[mt][nt][0], acc[mt][nt][1]);
                *reinterpret_cast<float2*>(&Csm[(r0 + 8) * 132 + col]) =
                    make_float2(acc[mt][nt][2], acc[mt][nt][3]);
            }
    }
    __syncthreads();

    const int r = t >> 1, hh = t & 1, ch0 = hh * 64;
    const int row = n0 + r;
    const float* crow = &Csm[r * 132 + ch0];

    if (MODE == 0) {
        if (row < NN) {
            if (by < 2) {
                __half* o = &oB[(size_t)row * 256 + by * 128 + ch0];
                #pragma unroll
                for (int j = 0; j < 64; j += 2)
                    *reinterpret_cast<__half2*>(&o[j]) =
                        __floats2half2_rn(crow[j], crow[j + 1]);
            } else {
                float* o = &outF[(size_t)row * 256 + (by - 2) * 128 + ch0];
                #pragma unroll
                for (int j = 0; j < 64; j += 4)
                    *reinterpret_cast<float4*>(&o[j]) =
                        *reinterpret_cast<const float4*>(&crow[j]);
            }
        }
        return;
    }
    // MODE 1: LN epilogue
    {
        float s = 0.f, s2 = 0.f;
        #pragma unroll
        for (int j = 0; j < 64; j += 4) {
            float4 c4 = *reinterpret_cast<const float4*>(&crow[j]);
            float v0 = c4.x * scale + bias[ch0 + j];
            float v1 = c4.y * scale + bias[ch0 + j + 1];
            float v2 = c4.z * scale + bias[ch0 + j + 2];
            float v3 = c4.w * scale + bias[ch0 + j + 3];
            s += v0 + v1 + v2 + v3;
            s2 += v0 * v0 + v1 * v1 + v2 * v2 + v3 * v3;
        }
        s  += __shfl_xor_sync(0xffffffffu, s, 1);
        s2 += __shfl_xor_sync(0xffffffffu, s2, 1);
        float m    = s * (1.0f / 128.0f);
        float var  = s2 * (1.0f / 128.0f) - m * m;
        float rstd = rsqrtf(var + 1e-5f);
        if (row < NN) {
            float mk = mask[row];
            #pragma unroll
            for (int j = 0; j < 64; j += 2) {
                int c = ch0 + j;
                float v0 = crow[j]     * scale + bias[c];
                float v1 = crow[j + 1] * scale + bias[c + 1];
                float w0 = ((v0 - m) * rstd * gamma[c]     + beta[c])     * mk;
                float w1 = ((v1 - m) * rstd * gamma[c + 1] + beta[c + 1]) * mk;
                *reinterpret_cast<__half2*>(&oB[(size_t)row * 256 + oCol + c]) =
                    __floats2half2_rn(w0, w1);
            }
        }
    }
}

// ============================================================================
// Fused gemm4+gemm5 (BK=64 staging):
//   U[128,256] = swish(NA @ Wn1 + bn1)  -> usm (A-staging layout, 8 chunks)
//   out = LN(node_inp + U @ Wn2 + bn2; g_node, b_node) * mask
// Smem: stage 2x40960 @0 | usm 8x10240 @81920 | Csm overlays @0 post-loop.
// ============================================================================
__global__ void __launch_bounds__(256, 1) gemm45(
    const __half* __restrict__ A,      // g_NA
    const __half* __restrict__ B1,     // Wn1 region [256 n][256 k]
    const __half* __restrict__ B2,     // Wn2 region [128 n][256 k]
    const float* __restrict__ bn1, const float* __restrict__ bn2,
    const float* __restrict__ gamma, const float* __restrict__ beta,
    const float* __restrict__ mask, const float* __restrict__ resid,
    float* __restrict__ outF)
{
    extern __shared__ __align__(16) char smem[];
    const uint32_t sb = smem_u32(smem);
    const uint32_t USM = 81920;
    float* Csm = reinterpret_cast<float*>(smem);             // overlays stage, post-loop

    const int t = threadIdx.x, lane = t & 31, warp = t >> 5;
    const int wm = warp & 3, wn = warp >> 2;
    const int n0 = blockIdx.x * 128;
    constexpr uint32_t BUFB = 40960;

    const int r0s = t >> 2, g0 = t & 3;
    const int g = lane >> 2, cc = (lane & 3) * 2;

    // ---------- phase 1: gemm4 (two N-tiles of Wn1) ----------
    auto stage1 = [&](int cp, int b, int nt2) {
        uint32_t base = sb + (uint32_t)b * BUFB;
        #pragma unroll
        for (int sub = 0; sub < 2; sub++) {
            int c = cp * 2 + sub;
            #pragma unroll
            for (int s = 0; s < 2; s++) {
                int row = r0s + s * 64;
                int grow = n0 + row;
                int ga = grow < NN ? grow : NN - 1;
                int ok = grow < NN ? 16 : 0;
                uint32_t so = (uint32_t)(row * 40 + g0 * 8) * 2 + sub * 10240u;
                cp_async16(base + so, &A[(size_t)ga * 256 + c * 32 + g0 * 8], ok);
                cp_async16(base + 20480 + so,
                           &B1[(size_t)(nt2 * 128 + row) * 256 + c * 32 + g0 * 8], 16);
            }
        }
        cp_commit();
    };

    for (int nt2 = 0; nt2 < 2; nt2++) {
        float acc[2][8][4];
        #pragma unroll
        for (int mt = 0; mt < 2; mt++)
            #pragma unroll
            for (int nt = 0; nt < 8; nt++)
                #pragma unroll
                for (int q = 0; q < 4; q++) acc[mt][nt][q] = 0.f;

        stage1(0, 0, nt2);
        for (int cp = 0; cp < 4; cp++) {
            const int b = cp & 1;
            if (cp + 1 < 4) {
                stage1(cp + 1, (cp + 1) & 1, nt2);
                asm volatile("cp.async.wait_group 1;" ::: "memory");
            } else {
                asm volatile("cp.async.wait_group 0;" ::: "memory");
            }
            __syncthreads();

            const uint32_t base = sb + (uint32_t)b * BUFB;
            #pragma unroll
            for (int sub = 0; sub < 2; sub++) {
                const uint32_t baseA = base + sub * 10240u;
                const uint32_t baseB = base + 20480 + sub * 10240u;
                #pragma unroll
                for (int kt = 0; kt < 32; kt += 16) {
                    uint32_t ah[2][4];
                    {
                        int ar = lane & 15, as_ = (lane >> 4) * 8;
                        #pragma unroll
                        for (int mt = 0; mt < 2; mt++) {
                            uint32_t off = (uint32_t)((wm * 32 + mt * 16 + ar) * 40 + kt + as_) * 2;
                            ldsm4(ah[mt][0], ah[mt][1], ah[mt][2], ah[mt][3], baseA + off);
                        }
                    }
                    #pragma unroll
                    for (int p = 0; p < 4; p++) {
                        int sel = lane >> 3, i = lane & 7;
                        uint32_t boff = (uint32_t)((wn * 64 + p * 16 + ((sel >> 1) << 3) + i) * 40
                                                   + kt + ((sel & 1) << 3)) * 2;
                        uint32_t bh[4];
                        ldsm4(bh[0], bh[1], bh[2], bh[3], baseB + boff);
                        #pragma unroll
                        for (int mt = 0; mt < 2; mt++)
                            #pragma unroll
                            for (int q = 0; q < 2; q++)
                                mma16816(acc[mt][2 * p + q], ah[mt], &bh[2 * q]);
                    }
                }
            }
            __syncthreads();
        }

        // epilogue: swish fragments -> usm in A-staging layout (fp16)
        #pragma unroll
        for (int mt = 0; mt < 2; mt++)
            #pragma unroll
            for (int nt = 0; nt < 8; nt++) {
                int r0 = wm * 32 + mt * 16 + g;
                int ch = nt2 * 128 + wn * 64 + nt * 8 + cc;
                float b0 = bn1[ch], b1v = bn1[ch + 1];
                int chunk = ch >> 5, kk = ch & 31;
                __half* up = reinterpret_cast<__half*>(smem + USM + chunk * 10240);
                *reinterpret_cast<__half2*>(&up[r0 * 40 + kk]) =
                    __floats2half2_rn(swishf(acc[mt][nt][0] + b0),
                                      swishf(acc[mt][nt][1] + b1v));
                *reinterpret_cast<__half2*>(&up[(r0 + 8) * 40 + kk]) =
                    __floats2half2_rn(swishf(acc[mt][nt][2] + b0),
                                      swishf(acc[mt][nt][3] + b1v));
            }
        __syncthreads();
    }

    // ---------- phase 2: gemm5 (A = usm, B = Wn2 staged) ----------
    auto stage2 = [&](int cp, int b) {
        uint32_t base = sb + (uint32_t)b * BUFB;
        #pragma unroll
        for (int sub = 0; sub < 2; sub++) {
            int c = cp * 2 + sub;
            #pragma unroll
            for (int s = 0; s < 2; s++) {
                int row = r0s + s * 64;
                uint32_t so = (uint32_t)(row * 40 + g0 * 8) * 2 + sub * 10240u;
                cp_async16(base + so, &B2[(size_t)row * 256 + c * 32 + g0 * 8], 16);
            }
        }
        cp_commit();
    };

    float acc[2][8][4];
    #pragma unroll
    for (int mt = 0; mt < 2; mt++)
        #pragma unroll
        for (int nt = 0; nt < 8; nt++)
            #pragma unroll
            for (int q = 0; q < 4; q++) acc[mt][nt][q] = 0.f;

    stage2(0, 0);
    for (int cp = 0; cp < 4; cp++) {
        const int b = cp & 1;
        if (cp + 1 < 4) {
            stage2(cp + 1, (cp + 1) & 1);
            asm volatile("cp.async.wait_group 1;" ::: "memory");
        } else {
            asm volatile("cp.async.wait_group 0;" ::: "memory");
        }
        __syncthreads();

        #pragma unroll
        for (int sub = 0; sub < 2; sub++) {
            int c = cp * 2 + sub;
            const uint32_t baseB = sb + (uint32_t)b * BUFB + sub * 10240u;
            const uint32_t baseA = sb + USM + (uint32_t)c * 10240;
            #pragma unroll
            for (int kt = 0; kt < 32; kt += 16) {
                uint32_t ah[2][4];
                {
                    int ar = lane & 15, as_ = (lane >> 4) * 8;
                    #pragma unroll
                    for (int mt = 0; mt < 2; mt++) {
                        uint32_t off = (uint32_t)((wm * 32 + mt * 16 + ar) * 40 + kt + as_) * 2;
                        ldsm4(ah[mt][0], ah[mt][1], ah[mt][2], ah[mt][3], baseA + off);
                    }
                }
                #pragma unroll
                for (int p = 0; p < 4; p++) {
                    int sel = lane >> 3, i = lane & 7;
                    uint32_t boff = (uint32_t)((wn * 64 + p * 16 + ((sel >> 1) << 3) + i) * 40
                                               + kt + ((sel & 1) << 3)) * 2;
                    uint32_t bh[4];
                    ldsm4(bh[0], bh[1], bh[2], bh[3], baseB + boff);
                    #pragma unroll
                    for (int mt = 0; mt < 2; mt++)
                        #pragma unroll
                        for (int q = 0; q < 2; q++)
                            mma16816(acc[mt][2 * p + q], ah[mt], &bh[2 * q]);
                }
            }
        }
        __syncthreads();
    }

    // fragments -> Csm (overlays stage area; mainloop done)
    #pragma unroll
    for (int mt = 0; mt < 2; mt++)
        #pragma unroll
        for (int nt = 0; nt < 8; nt++) {
            int r0 = wm * 32 + mt * 16 + g;
            int col = wn * 64 + nt * 8 + cc;
            *reinterpret_cast<float2*>(&Csm[r0 * 132 + col]) =
                make_float2(acc[mt][nt][0], acc[mt][nt][1]);
            *reinterpret_cast<float2*>(&Csm[(r0 + 8) * 132 + col]) =
                make_float2(acc[mt][nt][2], acc[mt][nt][3]);
        }
    __syncthreads();

    // LN epilogue (resid + LN*mask -> fp32 out)
    const int r = t >> 1, hh = t & 1, ch0 = hh * 64;
    const int row = n0 + r;
    const float* crow = &Csm[r * 132 + ch0];

    float s = 0.f, s2 = 0.f;
    #pragma unroll
    for (int j = 0; j < 64; j += 4) {
        float4 c4 = *reinterpret_cast<const float4*>(&crow[j]);
        float v0 = c4.x + bn2[ch0 + j];
        float v1 = c4.y + bn2[ch0 + j + 1];
        float v2 = c4.z + bn2[ch0 + j + 2];
        float v3 = c4.w + bn2[ch0 + j + 3];
        if (row < NN) {
            float4 r4 = *reinterpret_cast<const float4*>(&resid[(size_t)row * 128 + ch0 + j]);
            v0 += r4.x; v1 += r4.y; v2 += r4.z; v3 += r4.w;
        }
        s += v0 + v1 + v2 + v3;
        s2 += v0 * v0 + v1 * v1 + v2 * v2 + v3 * v3;
    }
    s  += __shfl_xor_sync(0xffffffffu, s, 1);
    s2 += __shfl_xor_sync(0xffffffffu, s2, 1);
    float m    = s * (1.0f / 128.0f);
    float var  = s2 * (1.0f / 128.0f) - m * m;
    float rstd = rsqrtf(var + 1e-5f);
    if (row < NN) {
        float mk = mask[row];
        #pragma unroll
        for (int j = 0; j < 64; j += 2) {
            int c = ch0 + j;
            float2 r2 = *reinterpret_cast<const float2*>(&resid[(size_t)row * 128 + c]);
            float v0 = crow[j]     + bn2[c]     + r2.x;
            float v1 = crow[j + 1] + bn2[c + 1] + r2.y;
            float w0 = ((v0 - m) * rstd * gamma[c]     + beta[c])     * mk;
            float w1 = ((v1 - m) * rstd * gamma[c + 1] + beta[c + 1]) * mk;
            *reinterpret_cast<float2*>(&outF[(size_t)row * 128 + c]) = make_float2(w0, w1);
        }
    }
}

// ============================================================================
// Edge kernel (r12-16 proven; unchanged)
// ============================================================================
__global__ void __launch_bounds__(256, 2) edge_kernel(
    const float* __restrict__ edge_feat, const int* __restrict__ senders,
    const __half* __restrict__ gWe, const float* __restrict__ be1)
{
    extern __shared__ __align__(16) char esm[];
    __half* sW = reinterpret_cast<__half*>(esm);             // 20480 B
    __half* sE = reinterpret_cast<__half*>(esm + 20480);     // 10240 B
    __half* EP = reinterpret_cast<__half*>(esm + 30720);     // 66560 B
    int* snd   = reinterpret_cast<int*>(esm + 97280);        // 512 B

    const int t = threadIdx.x, lane = t & 31, warp = t >> 5;
    const int n0 = blockIdx.x * NPB;
    const int e0 = n0 * DEG;
    const uint32_t sWa = smem_u32(sW), sEa = smem_u32(sE);

    {
        const uint4* src = reinterpret_cast<const uint4*>(gWe);
        #pragma unroll
        for (int s = 0; s < 4; s++) {
            int i = t + s * 256;
            int n = i >> 2, kq = i & 3;
            *reinterpret_cast<uint4*>(sW + n * 40 + kq * 8) = src[i];
        }
    }
    #pragma unroll
    for (int s = 0; s < 4; s++) {
        int j4 = t + s * 256;
        int row = j4 >> 3, k4 = (j4 & 7) * 4;
        float4 v = *reinterpret_cast<const float4*>(&edge_feat[(size_t)e0 * EDIM + j4 * 4]);
        *reinterpret_cast<__half2*>(sE + row * 40 + k4)     = __floats2half2_rn(v.x, v.y);
        *reinterpret_cast<__half2*>(sE + row * 40 + k4 + 2) = __floats2half2_rn(v.z, v.w);
    }
    if (t < 128) snd[t] = senders[e0 + t];
    __syncthreads();

    {
        uint32_t af[2][4];
        int ar = lane & 15, as_ = (lane >> 4) * 8;
        #pragma unroll
        for (int kt = 0; kt < 2; kt++) {
            uint32_t off = (uint32_t)((warp * 16 + ar) * 40 + kt * 16 + as_) * 2;
            ldsm4(af[kt][0], af[kt][1], af[kt][2], af[kt][3], sEa + off);
        }
        int sel = lane >> 3, ii = lane & 7;
        int g = lane >> 2, cq = (lane & 3) * 2;
        int ebase = warp * 16 + g;
        #pragma unroll
        for (int p = 0; p < 16; p++) {
            uint32_t bh0[4], bh1[4];
            uint32_t brow = (uint32_t)(p * 16 + ((sel >> 1) << 3) + ii) * 40 + ((sel & 1) << 3);
            ldsm4(bh0[0], bh0[1], bh0[2], bh0[3], sWa + brow * 2);
            ldsm4(bh1[0], bh1[1], bh1[2], bh1[3], sWa + (brow + 16) * 2);
            #pragma unroll
            for (int q = 0; q < 2; q++) {
                float c4[4] = {0.f, 0.f, 0.f, 0.f};
                mma16816(c4, af[0], &bh0[2 * q]);
                mma16816(c4, af[1], &bh1[2 * q]);
                int ch = p * 16 + q * 8 + cq;
                *reinterpret_cast<__half2*>(EP + ebase * 260 + ch) =
                    __floats2half2_rn(c4[0], c4[1]);
                *reinterpret_cast<__half2*>(EP + (ebase + 8) * 260 + ch) =
                    __floats2half2_rn(c4[2], c4[3]);
            }
        }
    }
    __syncthreads();

    const float b1 = be1[t];
    for (int ni = 0; ni < NPB; ni++) {
        const int n = n0 + ni;
        const float pr = g_Pr[(size_t)n * 256 + t] + b1;

        float fv[DEG];
        #pragma unroll
        for (int e = 0; e < DEG; e++)
            fv[e] = __half2float(g_Psh[(size_t)snd[ni * DEG + e] * 256 + t]);

        float sacc = 0.f;
        #pragma unroll
        for (int e = 0; e < DEG; e++) {
            float ep = __half2float(EP[(ni * 16 + e) * 260 + t]);
            sacc += swishf(pr + fv[e] + ep);
        }
        g_S[(size_t)n * 256 + t] = __float2half_rn(sacc);
    }
}

// ============================================================================
extern "C" void kernel_launch(void* const* d_in, const int* in_sizes, int n_in,
                              void* d_out, int out_size)
{
    const float* node_inp  = (const float*)d_in[0];
    const float* edge_feat = (const float*)d_in[1];
    const float* node_mask = (const float*)d_in[2];
    const float* We1       = (const float*)d_in[3];
    const float* be1       = (const float*)d_in[4];
    const float* We2       = (const float*)d_in[5];
    const float* be2       = (const float*)d_in[6];
    const float* g_msg     = (const float*)d_in[7];
    const float* b_msg     = (const float*)d_in[8];
    const float* Wn1       = (const float*)d_in[9];
    const float* bn1       = (const float*)d_in[10];
    const float* Wn2       = (const float*)d_in[11];
    const float* bn2       = (const float*)d_in[12];
    const float* g_node    = (const float*)d_in[13];
    const float* b_node    = (const float*)d_in[14];
    const int*   senders   = (const int*)d_in[15];
    float* out = (float*)d_out;

    float* Prp;
    __half *Pshp, *NAp, *Sp, *Wep, *Whp;
    cudaGetSymbolAddress((void**)&Prp,  g_Pr);
    cudaGetSymbolAddress((void**)&Pshp, g_Psh);
    cudaGetSymbolAddress((void**)&NAp,  g_NA);
    cudaGetSymbolAddress((void**)&Sp,   g_S);
    cudaGetSymbolAddress((void**)&Wep,  g_We);
    cudaGetSymbolAddress((void**)&Whp,  g_Wh);

    const int SMEMT  = 81920;
    const int SMEME  = 97792;
    const int SMEM45 = 163840;
    cudaFuncSetAttribute(mma_gemm<128,0>, cudaFuncAttributeMaxDynamicSharedMemorySize, SMEMT);
    cudaFuncSetAttribute(mma_gemm<256,1>, cudaFuncAttributeMaxDynamicSharedMemorySize, SMEMT);
    cudaFuncSetAttribute(gemm45,          cudaFuncAttributeMaxDynamicSharedMemorySize, SMEM45);
    cudaFuncSetAttribute(edge_kernel,     cudaFuncAttributeMaxDynamicSharedMemorySize, SMEME);

    // 1) all prep in one launch
    prep_all<<<800 + NN / 4, 256>>>(We1, We2, Wn1, Wn2, node_inp);

    // 2) P: by 0,1 -> Ps fp16; by 2,3 -> Pr fp32
    mma_gemm<128,0><<<dim3(GX, 4), 256, SMEMT>>>(
        NAp, Whp, nullptr, 1.0f, nullptr, nullptr, nullptr, Prp, Pshp, 0);

    // 3) edge kernel
    edge_kernel<<<NN / NPB, 256, SMEME>>>(edge_feat, senders, Wep, be1);

    // 4) agg = LN(S @ We2 /16 + be2)*mask -> g_NA cols 128..255
    mma_gemm<256,1><<<dim3(GX, 1), 256, SMEMT>>>(
        Sp, Whp + 65536, be2, 1.0f / 16.0f, g_msg, b_msg, node_mask,
        nullptr, NAp, 128);

    // 5) fused: U = swish(NA@Wn1+bn1); out = LN(node_inp + U@Wn2 + bn2)*mask
    gemm45<<<dim3(GX, 1), 256, SMEM45>>>(
        NAp, Whp + 98304, Whp + 163840,
        bn1, bn2, g_node, b_node, node_mask, node_inp, out);
}